// round 12
// baseline (speedup 1.0000x reference)
#include <cuda_runtime.h>
#include <cuda_bf16.h>
#include <cstdint>

#define NPIX 65536
#define IMG_H 256
#define IMG_W 256
#define NB 8

// ---- device scratch ----
__device__ __nv_bfloat16 g_hi[NB * NPIX * 128];   // NHWC [b][y][x][ci], hi plane
__device__ __nv_bfloat16 g_lo[NB * NPIX * 128];   // lo plane
__device__ uint32_t g_Bfrag[3 * 24 * 2 * 32 * 16];  // conv weight mma frags
__device__ uint32_t g_QKVfrag[3 * 2 * 2 * 4 * 32 * 16]; // [kind q/k/v][br][half][kc][lane][ntj]
__device__ uint32_t g_RMfrag[16 * 2 * 4 * 32 * 16]; // [(br*8+b)][half][kc][lane][ntj]
__device__ float g_mat[2 * NB * 64 * 64];
__device__ float g_ksum[2 * NB * 64];
__device__ float g_vsum[2 * NB * 64];
__device__ float g_rv[2 * NB * 64];
__device__ float g_ksumE[2 * NB * 64];

// ---- mma.sync bf16 helper (m16n8k16, f32 accum) ----
__device__ __forceinline__ void mma_bf16(float* d,
                                         uint32_t a0, uint32_t a1, uint32_t a2, uint32_t a3,
                                         uint32_t b0, uint32_t b1) {
    asm volatile(
        "mma.sync.aligned.m16n8k16.row.col.f32.bf16.bf16.f32 "
        "{%0,%1,%2,%3}, {%4,%5,%6,%7}, {%8,%9}, {%0,%1,%2,%3};"
        : "+f"(d[0]), "+f"(d[1]), "+f"(d[2]), "+f"(d[3])
        : "r"(a0), "r"(a1), "r"(a2), "r"(a3), "r"(b0), "r"(b1));
}

__device__ __forceinline__ void ldsm_x4(uint32_t& r0, uint32_t& r1, uint32_t& r2, uint32_t& r3,
                                        uint32_t addr) {
    asm volatile("ldmatrix.sync.aligned.m8n8.x4.shared.b16 {%0,%1,%2,%3}, [%4];"
                 : "=r"(r0), "=r"(r1), "=r"(r2), "=r"(r3) : "r"(addr));
}
__device__ __forceinline__ void ldsm_x4_trans(uint32_t& r0, uint32_t& r1, uint32_t& r2, uint32_t& r3,
                                              uint32_t addr) {
    asm volatile("ldmatrix.sync.aligned.m8n8.x4.trans.shared.b16 {%0,%1,%2,%3}, [%4];"
                 : "=r"(r0), "=r"(r1), "=r"(r2), "=r"(r3) : "r"(addr));
}

__device__ __forceinline__ uint32_t smem_u32(const void* p) {
    uint32_t a;
    asm("{ .reg .u64 t; cvta.to.shared.u64 t, %1; cvt.u32.u64 %0, t; }" : "=r"(a) : "l"(p));
    return a;
}

__device__ __forceinline__ void splitbf(float a, float b, uint32_t& h, uint32_t& l) {
    __nv_bfloat16 ha = __float2bfloat16(a), hb = __float2bfloat16(b);
    __nv_bfloat162 hh; hh.x = ha; hh.y = hb;
    h = *(uint32_t*)&hh;
    __nv_bfloat162 ll = __floats2bfloat162_rn(a - __bfloat162float(ha),
                                              b - __bfloat162float(hb));
    l = *(uint32_t*)&ll;
}
__device__ __forceinline__ uint32_t packbf_hi_lo(float a, float b, int half) {
    if (half == 0) {
        __nv_bfloat162 hh; hh.x = __float2bfloat16(a); hh.y = __float2bfloat16(b);
        return *(uint32_t*)&hh;
    }
    __nv_bfloat16 ha = __float2bfloat16(a), hb = __float2bfloat16(b);
    __nv_bfloat162 ll = __floats2bfloat162_rn(a - __bfloat162float(ha),
                                              b - __bfloat162float(hb));
    return *(uint32_t*)&ll;
}

// -------------------- prep (single kernel) --------------------
__global__ void __launch_bounds__(256) prep_kernel(
    const float* __restrict__ q1w, const float* __restrict__ k1w, const float* __restrict__ v1w,
    const float* __restrict__ q2w, const float* __restrict__ k2w, const float* __restrict__ v2w,
    const float* __restrict__ cw)
{
    int nb = blockIdx.x, tid = threadIdx.x;
    if (nb < 256) {
        int idx = nb * 256 + tid;
        g_mat[idx] = 0.f;
        if (idx < 2 * NB * 64) { g_ksum[idx] = 0.f; g_vsum[idx] = 0.f; }
        return;
    }
    if (nb < 544) {
        int i = (nb - 256) * 256 + tid;  // 0..73727
        int ky = i / 24576;
        int rem = i % 24576;
        int kc = rem / 1024;
        int rem2 = rem % 1024;
        int half = rem2 / 512;
        int rem3 = rem2 % 512;
        int lane = rem3 / 16;
        int r4 = rem3 % 16;
        int nt = r4 >> 1, j = r4 & 1;
        int kx = kc >> 3, cc8 = kc & 7;
        int n = nt * 8 + (lane >> 2);
        int ci0 = cc8 * 16 + (lane & 3) * 2 + j * 8;
        float w0 = cw[((n * 128 + ci0) * 3 + ky) * 3 + kx];
        float w1 = cw[((n * 128 + ci0 + 1) * 3 + ky) * 3 + kx];
        g_Bfrag[i] = packbf_hi_lo(w0, w1, half);
        return;
    }
    {
        int t = nb - 544;                // 0..95
        int kind = t / 32;               // 0=q, 1=k, 2=v
        int i = (t % 32) * 256 + tid;    // 0..8191
        int br = i >> 12;
        int r = i & 4095;
        int half = r >> 11;
        int kc = (r >> 9) & 3;
        int lane = (r >> 4) & 31;
        int ntj = r & 15;
        int nt = ntj >> 1, j = ntj & 1;
        int o = nt * 8 + (lane >> 2);
        int c0 = kc * 16 + (lane & 3) * 2 + j * 8;
        const float* w;
        if (kind == 0) w = br ? q2w : q1w;
        else if (kind == 1) w = br ? k2w : k1w;
        else w = br ? v2w : v1w;
        float w0 = w[o * 64 + c0];
        float w1 = w[o * 64 + c0 + 1];
        g_QKVfrag[kind * 8192 + i] = packbf_hi_lo(w0, w1, half);
    }
}

// -------------------- pass 1: ldmatrix K,V proj + ldmatrix stats --------------------
// grid (512, 8, 2), 256 thr = 8 warps, 2 CTAs/SM. Tile: 128 px.
// smem bytes: sXh [0,17408) sXl [17408,34816) |
//   Kn hi [34816,53248) Kn lo [53248,71680) | V hi [71680,90112) V lo [90112,108544)
//   (K/V planes: [px 128][och 64], stride 144B, bf16)
#define P1_SMEM 108544

__global__ void __launch_bounds__(256, 2) pass1_kernel(
    const float* __restrict__ x1, const float* __restrict__ x2,
    const float* __restrict__ kb1, const float* __restrict__ vb1,
    const float* __restrict__ kb2, const float* __restrict__ vb2)
{
    extern __shared__ __align__(16) char dsm1c[];
    __shared__ float sKsum[64], sVsum[64];
    const uint32_t sbase = smem_u32(dsm1c);

    const int tid = threadIdx.x;
    const int lane = tid & 31, wt = tid >> 5;
    const int g = lane >> 2, tg = lane & 3;
    const int b = blockIdx.y, br = blockIdx.z;
    const int p0 = blockIdx.x * 128;
    const float* xb = (br ? x2 : x1) + (size_t)b * 64 * NPIX;
    const float* kb = br ? kb2 : kb1;
    const float* vb = br ? vb2 : vb1;

    if (tid < 64) { sKsum[tid] = 0.f; sVsum[tid] = 0.f; }

    // stage X as pre-split bf16 planes [c][px], stride 272B
    for (int i = tid; i < 2048; i += 256) {
        int c = i >> 5, chunk = i & 31;
        float4 xv = *(const float4*)&xb[(size_t)c * NPIX + p0 + chunk * 4];
        uint32_t h0, l0, h1, l1;
        splitbf(xv.x, xv.y, h0, l0);
        splitbf(xv.z, xv.w, h1, l1);
        *(uint2*)(dsm1c + c * 272 + chunk * 8) = make_uint2(h0, h1);
        *(uint2*)(dsm1c + 17408 + c * 272 + chunk * 8) = make_uint2(l0, l1);
    }
    __syncthreads();

    // ldmatrix.trans lane address (A[m=px][k=c] from [c][px] storage)
    const uint32_t aH = sbase + ((((lane >> 4) & 1) * 8 + (lane & 7)) * 272)
                              + ((wt * 16 + ((lane >> 3) & 1) * 8) * 2);
    const uint32_t aL = aH + 17408;

    char* parkK = dsm1c + 34816;
    char* parkV = dsm1c + 71680;

    // ---- projections: kv=0 -> K (normalized at park), kv=1 -> V ----
#pragma unroll 1
    for (int kv = 0; kv < 2; kv++) {
        const uint32_t* wf = g_QKVfrag + (kv + 1) * 8192 + br * 4096;
        const float* bias = kv ? vb : kb;
        char* park = kv ? parkV : parkK;

        float acc[8][4];
#pragma unroll
        for (int nt = 0; nt < 8; nt++)
#pragma unroll
            for (int k = 0; k < 4; k++) acc[nt][k] = 0.f;

#pragma unroll
        for (int kc = 0; kc < 4; kc++) {
            const uint4* WH = (const uint4*)&wf[(0 * 4 + kc) * 512 + lane * 16];
            const uint4* WL = (const uint4*)&wf[(1 * 4 + kc) * 512 + lane * 16];
            uint4 bh[4], bl[4];
#pragma unroll
            for (int q = 0; q < 4; q++) { bh[q] = __ldg(&WH[q]); bl[q] = __ldg(&WL[q]); }
            uint32_t ah0, ah1, ah2, ah3, al0, al1, al2, al3;
            ldsm_x4_trans(ah0, ah1, ah2, ah3, aH + kc * 4352);
            ldsm_x4_trans(al0, al1, al2, al3, aL + kc * 4352);
#pragma unroll
            for (int nt = 0; nt < 8; nt++) {
                uint32_t b0h = (nt & 1) ? bh[nt >> 1].z : bh[nt >> 1].x;
                uint32_t b1h = (nt & 1) ? bh[nt >> 1].w : bh[nt >> 1].y;
                uint32_t b0l = (nt & 1) ? bl[nt >> 1].z : bl[nt >> 1].x;
                uint32_t b1l = (nt & 1) ? bl[nt >> 1].w : bl[nt >> 1].y;
                mma_bf16(acc[nt], ah0, ah1, ah2, ah3, b0h, b1h);
                mma_bf16(acc[nt], ah0, ah1, ah2, ah3, b0l, b1l);
                mma_bf16(acc[nt], al0, al1, al2, al3, b0h, b1h);
            }
        }

        // add bias
#pragma unroll
        for (int nt = 0; nt < 8; nt++) {
            float b0 = __ldg(&bias[nt * 8 + tg * 2 + 0]);
            float b1 = __ldg(&bias[nt * 8 + tg * 2 + 1]);
            acc[nt][0] += b0; acc[nt][1] += b1;
            acc[nt][2] += b0; acc[nt][3] += b1;
        }

        float invv[2] = {1.f, 1.f};
        if (kv == 0) {
#pragma unroll
            for (int h = 0; h < 2; h++) {
                float s = 0.f;
#pragma unroll
                for (int nt = 0; nt < 8; nt++) {
                    float a = acc[nt][h * 2], c = acc[nt][h * 2 + 1];
                    s = fmaf(a, a, s); s = fmaf(c, c, s);
                }
                s += __shfl_xor_sync(0xffffffffu, s, 1);
                s += __shfl_xor_sync(0xffffffffu, s, 2);
                invv[h] = rsqrtf(s);
            }
        }

        // park as pre-split bf16 [px][och] stride 144B; collect channel sums
        float tsum[16];
#pragma unroll
        for (int nt = 0; nt < 8; nt++) {
            int oc2 = (nt * 8 + tg * 2) * 2;   // byte offset of och pair
#pragma unroll
            for (int h = 0; h < 2; h++) {
                float v0 = acc[nt][h * 2 + 0] * invv[h];
                float v1 = acc[nt][h * 2 + 1] * invv[h];
                if (h == 0) { tsum[nt * 2] = v0; tsum[nt * 2 + 1] = v1; }
                else        { tsum[nt * 2] += v0; tsum[nt * 2 + 1] += v1; }
                uint32_t ph, pl;
                splitbf(v0, v1, ph, pl);
                int px = wt * 16 + g + h * 8;
                *(uint32_t*)(park + px * 144 + oc2) = ph;
                *(uint32_t*)(park + 18432 + px * 144 + oc2) = pl;
            }
        }
        // reduce over g lanes, accumulate into smem channel sums
#pragma unroll
        for (int i = 0; i < 16; i++) {
            tsum[i] += __shfl_xor_sync(0xffffffffu, tsum[i], 4);
            tsum[i] += __shfl_xor_sync(0xffffffffu, tsum[i], 8);
            tsum[i] += __shfl_xor_sync(0xffffffffu, tsum[i], 16);
        }
        if (g == 0) {
            float* sdst = kv ? sVsum : sKsum;
#pragma unroll
            for (int nt = 0; nt < 8; nt++) {
                atomicAdd(&sdst[nt * 8 + tg * 2 + 0], tsum[nt * 2 + 0]);
                atomicAdd(&sdst[nt * 8 + tg * 2 + 1], tsum[nt * 2 + 1]);
            }
        }
    }
    __syncthreads();

    // ---- stats GEMM via trans ldmatrix: matrix += Kn * V^T ----
    const int mt4 = wt >> 1;
    const int nh = wt & 1;
    float acc2[4][4];
#pragma unroll
    for (int nt = 0; nt < 4; nt++)
#pragma unroll
        for (int k = 0; k < 4; k++) acc2[nt][k] = 0.f;

    const uint32_t kBase = sbase + 34816;
    const uint32_t vBase = sbase + 71680;
    const uint32_t rowOff = ((((lane >> 4) & 1) * 8) + (lane & 7)) * 144;
    const uint32_t aCol = (mt4 * 16 + ((lane >> 3) & 1) * 8) * 2;
    const uint32_t bCol = (nh * 32 + ((lane >> 3) & 1) * 8) * 2;

#pragma unroll
    for (int kc = 0; kc < 8; kc++) {
        uint32_t rb = rowOff + kc * 2304;
        uint32_t ah0, ah1, ah2, ah3, al0, al1, al2, al3;
        ldsm_x4_trans(ah0, ah1, ah2, ah3, kBase + rb + aCol);
        ldsm_x4_trans(al0, al1, al2, al3, kBase + 18432 + rb + aCol);
        uint32_t h00, h01, h02, h03, h10, h11, h12, h13;
        uint32_t l00, l01, l02, l03, l10, l11, l12, l13;
        ldsm_x4_trans(h00, h01, h02, h03, vBase + rb + bCol);
        ldsm_x4_trans(h10, h11, h12, h13, vBase + rb + bCol + 32);
        ldsm_x4_trans(l00, l01, l02, l03, vBase + 18432 + rb + bCol);
        ldsm_x4_trans(l10, l11, l12, l13, vBase + 18432 + rb + bCol + 32);

        // nt 0: (h00,h02); nt 1: (h01,h03); nt 2: (h10,h12); nt 3: (h11,h13)
        mma_bf16(acc2[0], ah0, ah1, ah2, ah3, h00, h02);
        mma_bf16(acc2[0], ah0, ah1, ah2, ah3, l00, l02);
        mma_bf16(acc2[0], al0, al1, al2, al3, h00, h02);
        mma_bf16(acc2[1], ah0, ah1, ah2, ah3, h01, h03);
        mma_bf16(acc2[1], ah0, ah1, ah2, ah3, l01, l03);
        mma_bf16(acc2[1], al0, al1, al2, al3, h01, h03);
        mma_bf16(acc2[2], ah0, ah1, ah2, ah3, h10, h12);
        mma_bf16(acc2[2], ah0, ah1, ah2, ah3, l10, l12);
        mma_bf16(acc2[2], al0, al1, al2, al3, h10, h12);
        mma_bf16(acc2[3], ah0, ah1, ah2, ah3, h11, h13);
        mma_bf16(acc2[3], ah0, ah1, ah2, ah3, l11, l13);
        mma_bf16(acc2[3], al0, al1, al2, al3, h11, h13);
    }

    float* mat = g_mat + ((size_t)br * NB + b) * 4096;
#pragma unroll
    for (int nt = 0; nt < 4; nt++) {
#pragma unroll
        for (int k = 0; k < 4; k++) {
            int m = mt4 * 16 + g + ((k >= 2) ? 8 : 0);
            int n = nh * 32 + nt * 8 + tg * 2 + (k & 1);
            atomicAdd(&mat[m * 64 + n], acc2[nt][k]);
        }
    }
    if (tid < 64) {
        atomicAdd(&g_ksum[((size_t)br * NB + b) * 64 + tid], sKsum[tid]);
        atomicAdd(&g_vsum[((size_t)br * NB + b) * 64 + tid], sVsum[tid]);
    }
}

// -------------------- mid: RM frags, rv, ksumE --------------------
__global__ void __launch_bounds__(256) mid_kernel(const float* __restrict__ rw1,
                                                  const float* __restrict__ rw2)
{
    __shared__ float sMat[4096];
    __shared__ float sRw[4096];
    const int tid = threadIdx.x;
    const int b = blockIdx.x, br = blockIdx.y;
    const float* rw = br ? rw2 : rw1;
    const float* mat = g_mat + ((size_t)br * NB + b) * 4096;
#pragma unroll
    for (int r = 0; r < 16; r++) {
        int i = tid + r * 256;
        sMat[i] = mat[i];
        sRw[i] = rw[i];
    }
    __syncthreads();
    const int ty = tid >> 4, tx = tid & 15;
    float acc[4][4];
#pragma unroll
    for (int i = 0; i < 4; i++)
#pragma unroll
        for (int j = 0; j < 4; j++) acc[i][j] = 0.f;
#pragma unroll 4
    for (int c = 0; c < 64; c++) {
        float a[4], w[4];
#pragma unroll
        for (int i = 0; i < 4; i++) a[i] = sMat[(ty * 4 + i) * 64 + c];
#pragma unroll
        for (int j = 0; j < 4; j++) w[j] = sRw[(tx * 4 + j) * 64 + c];
#pragma unroll
        for (int i = 0; i < 4; i++)
#pragma unroll
            for (int j = 0; j < 4; j++) acc[i][j] += a[i] * w[j];
    }
    if (tid < 64) {
        const float* vsump = g_vsum + ((size_t)br * NB + b) * 64;
        float s = 0.f;
        for (int c = 0; c < 64; c++) s += sRw[tid * 64 + c] * vsump[c];
        g_rv[((size_t)br * NB + b) * 64 + tid] = s;
        g_ksumE[((size_t)br * NB + b) * 64 + tid] =
            g_ksum[((size_t)br * NB + b) * 64 + tid] + 1e-6f;
    }
    __syncthreads();
#pragma unroll
    for (int i = 0; i < 4; i++)
#pragma unroll
        for (int j = 0; j < 4; j++)
            sMat[(tx * 4 + j) * 64 + (ty * 4 + i)] = acc[i][j];
    __syncthreads();
    uint32_t* dst = g_RMfrag + (size_t)(br * 8 + b) * 4096;
    for (int t = tid; t < 4096; t += 256) {
        int half = t >> 11;
        int lane = (t >> 4) & 31;
        int ntj = t & 15;
        int nt = ntj >> 1, j = ntj & 1;
        int kc = (t >> 9) & 3;
        int o = nt * 8 + (lane >> 2);
        int m0 = kc * 16 + (lane & 3) * 2 + j * 8;
        float w0 = sMat[o * 64 + m0];
        float w1 = sMat[o * 64 + m0 + 1];
        dst[t] = packbf_hi_lo(w0, w1, half);
    }
}

// -------------------- pass 2: ldmatrix Q proj + register-resident RM*Qn -----------
#define P2_SMEM 36864

__global__ void __launch_bounds__(256, 2) pass2_kernel(
    const float* __restrict__ x1, const float* __restrict__ x2,
    const float* __restrict__ qb1, const float* __restrict__ rb1,
    const float* __restrict__ qb2, const float* __restrict__ rb2)
{
    extern __shared__ __align__(16) char dsmc2[];
    const uint32_t sbase = smem_u32(dsmc2);

    const int tid = threadIdx.x;
    const int lane = tid & 31, wt = tid >> 5;
    const int g = lane >> 2, tg = lane & 3;
    const int b = blockIdx.y, br = blockIdx.z;
    const int p0 = blockIdx.x * 128;
    const float* xb = (br ? x2 : x1) + (size_t)b * 64 * NPIX;
    const float* qb = br ? qb2 : qb1;
    const float* rb = br ? rb2 : rb1;
    const float* ksE = g_ksumE + ((size_t)br * NB + b) * 64;
    const float* rvp = g_rv + ((size_t)br * NB + b) * 64;

    for (int i = tid; i < 2048; i += 256) {
        int c = i >> 5, chunk = i & 31;
        float4 xv = *(const float4*)&xb[(size_t)c * NPIX + p0 + chunk * 4];
        uint32_t h0, l0, h1, l1;
        splitbf(xv.x, xv.y, h0, l0);
        splitbf(xv.z, xv.w, h1, l1);
        *(uint2*)(dsmc2 + c * 272 + chunk * 8) = make_uint2(h0, h1);
        *(uint2*)(dsmc2 + 17408 + c * 272 + chunk * 8) = make_uint2(l0, l1);
    }
    __syncthreads();

    const uint32_t aHa = sbase + ((((lane >> 4) & 1) * 8 + (lane & 7)) * 272)
                               + ((wt * 16 + ((lane >> 3) & 1) * 8) * 2);
    const uint32_t aLa = aHa + 17408;

    // ---- phase A: Q = Wq*x + qb ----
    float acc[8][4];
#pragma unroll
    for (int nt = 0; nt < 8; nt++)
#pragma unroll
        for (int k = 0; k < 4; k++) acc[nt][k] = 0.f;

#pragma unroll
    for (int kc = 0; kc < 4; kc++) {
        const uint4* WH = (const uint4*)&g_QKVfrag[((br * 2 + 0) * 4 + kc) * 512 + lane * 16];
        const uint4* WL = (const uint4*)&g_QKVfrag[((br * 2 + 1) * 4 + kc) * 512 + lane * 16];
        uint4 bh[4], bl[4];
#pragma unroll
        for (int q = 0; q < 4; q++) { bh[q] = __ldg(&WH[q]); bl[q] = __ldg(&WL[q]); }
        uint32_t ah0, ah1, ah2, ah3, al0, al1, al2, al3;
        ldsm_x4_trans(ah0, ah1, ah2, ah3, aHa + kc * 4352);
        ldsm_x4_trans(al0, al1, al2, al3, aLa + kc * 4352);
#pragma unroll
        for (int nt = 0; nt < 8; nt++) {
            uint32_t b0h = (nt & 1) ? bh[nt >> 1].z : bh[nt >> 1].x;
            uint32_t b1h = (nt & 1) ? bh[nt >> 1].w : bh[nt >> 1].y;
            uint32_t b0l = (nt & 1) ? bl[nt >> 1].z : bl[nt >> 1].x;
            uint32_t b1l = (nt & 1) ? bl[nt >> 1].w : bl[nt >> 1].y;
            mma_bf16(acc[nt], ah0, ah1, ah2, ah3, b0h, b1h);
            mma_bf16(acc[nt], ah0, ah1, ah2, ah3, b0l, b1l);
            mma_bf16(acc[nt], al0, al1, al2, al3, b0h, b1h);
        }
    }
    __syncthreads();   // X dead; smem free for staging

    // add qb
    float kse[16];
#pragma unroll
    for (int nt = 0; nt < 8; nt++) {
        float q0 = __ldg(&qb[nt * 8 + tg * 2 + 0]);
        float q1 = __ldg(&qb[nt * 8 + tg * 2 + 1]);
        kse[nt * 2 + 0] = __ldg(&ksE[nt * 8 + tg * 2 + 0]);
        kse[nt * 2 + 1] = __ldg(&ksE[nt * 8 + tg * 2 + 1]);
        acc[nt][0] += q0; acc[nt][1] += q1;
        acc[nt][2] += q0; acc[nt][3] += q1;
    }

    // per-px inv + den via quad shfl
    float invv[2], denn[2];
#pragma unroll
    for (int h = 0; h < 2; h++) {
        float s = 0.f, d = 0.f;
#pragma unroll
        for (int nt = 0; nt < 8; nt++) {
            float a = acc[nt][h * 2], c = acc[nt][h * 2 + 1];
            s = fmaf(a, a, s); s = fmaf(c, c, s);
            d = fmaf(a, kse[nt * 2], d); d = fmaf(c, kse[nt * 2 + 1], d);
        }
        s += __shfl_xor_sync(0xffffffffu, s, 1);
        s += __shfl_xor_sync(0xffffffffu, s, 2);
        d += __shfl_xor_sync(0xffffffffu, d, 1);
        d += __shfl_xor_sync(0xffffffffu, d, 2);
        float inv = rsqrtf(s);
        invv[h] = inv;
        denn[h] = 1.f / (65536.f + inv * d);
    }

    // ---- phase B from registers: out = RM * (Q * inv) ----
    float acc2[8][4];
#pragma unroll
    for (int nt = 0; nt < 8; nt++)
#pragma unroll
        for (int k = 0; k < 4; k++) acc2[nt][k] = 0.f;

    const uint32_t* rmbase = g_RMfrag + (size_t)(br * 8 + b) * 4096;
#pragma unroll
    for (int kc = 0; kc < 4; kc++) {
        const uint4* RH = (const uint4*)&rmbase[(0 * 4 + kc) * 512 + lane * 16];
        const uint4* RL = (const uint4*)&rmbase[(1 * 4 + kc) * 512 + lane * 16];
        uint4 bh[4], bl[4];
#pragma unroll
        for (int q = 0; q < 4; q++) { bh[q] = __ldg(&RH[q]); bl[q] = __ldg(&RL[q]); }
        float i0 = invv[0], i1 = invv[1];
        uint32_t ah0, ah1, ah2, ah3, al0, al1, al2, al3;
        splitbf(acc[2 * kc][0] * i0, acc[2 * kc][1] * i0, ah0, al0);
        splitbf(acc[2 * kc][2] * i1, acc[2 * kc][3] * i1, ah1, al1);
        splitbf(acc[2 * kc + 1][0] * i0, acc[2 * kc + 1][1] * i0, ah2, al2);
        splitbf(acc[2 * kc + 1][2] * i1, acc[2 * kc + 1][3] * i1, ah3, al3);
#pragma unroll
        for (int nt = 0; nt < 8; nt++) {
            uint32_t b0h = (nt & 1) ? bh[nt >> 1].z : bh[nt >> 1].x;
            uint32_t b1h = (nt & 1) ? bh[nt >> 1].w : bh[nt >> 1].y;
            uint32_t b0l = (nt & 1) ? bl[nt >> 1].z : bl[nt >> 1].x;
            uint32_t b1l = (nt & 1) ? bl[nt >> 1].w : bl[nt >> 1].y;
            mma_bf16(acc2[nt], ah0, ah1, ah2, ah3, b0h, b1h);
            mma_bf16(acc2[nt], ah0, ah1, ah2, ah3, b0l, b1l);
            mma_bf16(acc2[nt], al0, al1, al2, al3, b0h, b1h);
        }
    }

    // epilogue -> bf16 hi/lo planes [px][72 bf16 stride] in smem, packed STS.32
#pragma unroll
    for (int nt = 0; nt < 8; nt++) {
        int o = nt * 8 + tg * 2;
        float rv0 = __ldg(&rvp[o]), rv1 = __ldg(&rvp[o + 1]);
        float rb0 = __ldg(&rb[o]),  rb1 = __ldg(&rb[o + 1]);
#pragma unroll
        for (int h = 0; h < 2; h++) {
            int r = wt * 16 + g + h * 8;
            float den = denn[h];
            float v0 = den * (rv0 + acc2[nt][h * 2 + 0]) + rb0;
            float v1 = den * (rv1 + acc2[nt][h * 2 + 1]) + rb1;
            uint32_t ph, pl;
            splitbf(v0, v1, ph, pl);
            *(uint32_t*)(dsmc2 + r * 144 + o * 2) = ph;
            *(uint32_t*)(dsmc2 + 18432 + r * 144 + o * 2) = pl;
        }
    }
    __syncthreads();

    for (int u = tid; u < 2048; u += 256) {
        int plane = u >> 10;
        int rest = u & 1023;
        int px = rest >> 3, q = rest & 7;
        uint4 val = *(const uint4*)(dsmc2 + plane * 18432 + px * 144 + q * 16);
        __nv_bfloat16* dst = plane ? g_lo : g_hi;
        *(uint4*)&dst[((size_t)(b * NPIX + p0 + px)) * 128 + br * 64 + q * 8] = val;
    }
}

// -------------------- conv: ldmatrix bf16-split implicit GEMM --------------------
#define STRIP_STRIDE 272
#define STRIP_BYTES (130 * STRIP_STRIDE)
#define CONV_SMEM (2 * STRIP_BYTES)

__global__ void __launch_bounds__(256, 2) conv_kernel(const float* __restrict__ cbias,
                                                      float* __restrict__ out)
{
    extern __shared__ __align__(16) char dsmc[];
    char* sHi = dsmc;
    char* sLo = dsmc + STRIP_BYTES;
    float* sOut = (float*)dsmc;
    const uint32_t sHiB = smem_u32(dsmc);

    const int tid = threadIdx.x;
    const int lane = tid & 31, wt = tid >> 5;
    const int x0 = blockIdx.x * 128, y = blockIdx.y, b = blockIdx.z;

    float acc[8][4];
#pragma unroll
    for (int nt = 0; nt < 8; nt++)
#pragma unroll
        for (int j = 0; j < 4; j++) acc[nt][j] = 0.f;

    const int g = lane >> 2, tg = lane & 3;
    const uint32_t aBase = (uint32_t)((wt * 16 + ((lane >> 3) & 1) * 8 + (lane & 7)) * STRIP_STRIDE
                                      + ((lane >> 4) & 1) * 16);

    for (int ky = 0; ky < 3; ky++) {
        int yy = y + ky - 1;
        bool yok = (yy >= 0 && yy < IMG_H);
        __syncthreads();
        if (yok) {
            size_t rowbase = ((size_t)b * NPIX + (size_t)yy * IMG_W) * 128;
            for (int i = tid; i < 130 * 16; i += 256) {
                int row = i >> 4, ch = i & 15;
                int px = x0 + row - 1;
                uint4 vh = make_uint4(0u, 0u, 0u, 0u);
                uint4 vl = make_uint4(0u, 0u, 0u, 0u);
                if (px >= 0 && px < IMG_W) {
                    size_t gi = rowbase + (size_t)px * 128 + ch * 8;
                    vh = *(const uint4*)&g_hi[gi];
                    vl = *(const uint4*)&g_lo[gi];
                }
                *(uint4*)(sHi + row * STRIP_STRIDE + ch * 16) = vh;
                *(uint4*)(sLo + row * STRIP_STRIDE + ch * 16) = vl;
            }
        }
        __syncthreads();
        if (!yok) continue;

#pragma unroll 1
        for (int kc = 0; kc < 24; kc++) {
            int kx = kc >> 3, cc8 = kc & 7;
            uint32_t ad = sHiB + aBase + kx * STRIP_STRIDE + cc8 * 32;
            uint32_t ah0, ah1, ah2, ah3, al0, al1, al2, al3;
            ldsm_x4(ah0, ah1, ah2, ah3, ad);
            ldsm_x4(al0, al1, al2, al3, ad + STRIP_BYTES);

            const uint4* bfH = (const uint4*)(g_Bfrag + (((ky * 24 + kc) * 2 + 0) * 32 + lane) * 16);
            const uint4* bfL = (const uint4*)(g_Bfrag + (((ky * 24 + kc) * 2 + 1) * 32 + lane) * 16);
            uint4 bh[4], bl[4];
#pragma unroll
            for (int q = 0; q < 4; q++) { bh[q] = __ldg(&bfH[q]); bl[q] = __ldg(&bfL[q]); }

#pragma unroll
            for (int nt = 0; nt < 8; nt++) {
                uint32_t bh0 = (nt & 1) ? bh[nt >> 1].z : bh[nt >> 1].x;
                uint32_t bh1 = (nt & 1) ? bh[nt >> 1].w : bh[nt >> 1].y;
                uint32_t bl0 = (nt & 1) ? bl[nt >> 1].z : bl[nt >> 1].x;
                uint32_t bl1 = (nt & 1) ? bl[nt >> 1].w : bl[nt >> 1].y;
                mma_bf16(acc[nt], ah0, ah1, ah2, ah3, bh0, bh1);
                mma_bf16(acc[nt], ah0, ah1, ah2, ah3, bl0, bl1);
                mma_bf16(acc[nt], al0, al1, al2, al3, bh0, bh1);
            }
        }
    }

    __syncthreads();
#pragma unroll
    for (int nt = 0; nt < 8; nt++)
#pragma unroll
        for (int h = 0; h < 2; h++)
#pragma unroll
            for (int j = 0; j < 2; j++) {
                int o = nt * 8 + tg * 2 + j;
                int px = wt * 16 + g + h * 8;
                sOut[o * 132 + px] = acc[nt][h * 2 + j];
            }
    __syncthreads();
    for (int i = tid; i < 64 * 32; i += 256) {
        int o = i >> 5, ch = i & 31;
        float4 v = *(const float4*)&sOut[o * 132 + ch * 4];
        float bias = __ldg(&cbias[o]);
        v.x += bias; v.y += bias; v.z += bias; v.w += bias;
        *(float4*)&out[((size_t)(b * 64 + o)) * NPIX + (size_t)y * IMG_W + x0 + ch * 4] = v;
    }
}

// -------------------- launch --------------------
extern "C" void kernel_launch(void* const* d_in, const int* in_sizes, int n_in,
                              void* d_out, int out_size)
{
    (void)in_sizes; (void)n_in; (void)out_size;
    const float* t1  = (const float*)d_in[0];
    const float* t2  = (const float*)d_in[1];
    const float* q1w = (const float*)d_in[2];  const float* q1b = (const float*)d_in[3];
    const float* k1w = (const float*)d_in[4];  const float* k1b = (const float*)d_in[5];
    const float* v1w = (const float*)d_in[6];  const float* v1b = (const float*)d_in[7];
    const float* r1w = (const float*)d_in[8];  const float* r1b = (const float*)d_in[9];
    const float* q2w = (const float*)d_in[10]; const float* q2b = (const float*)d_in[11];
    const float* k2w = (const float*)d_in[12]; const float* k2b = (const float*)d_in[13];
    const float* v2w = (const float*)d_in[14]; const float* v2b = (const float*)d_in[15];
    const float* r2w = (const float*)d_in[16]; const float* r2b = (const float*)d_in[17];
    const float* cw  = (const float*)d_in[18]; const float* cb  = (const float*)d_in[19];

    cudaFuncSetAttribute(pass1_kernel, cudaFuncAttributeMaxDynamicSharedMemorySize, P1_SMEM);
    cudaFuncSetAttribute(pass2_kernel, cudaFuncAttributeMaxDynamicSharedMemorySize, P2_SMEM);
    cudaFuncSetAttribute(conv_kernel, cudaFuncAttributeMaxDynamicSharedMemorySize, CONV_SMEM);

    prep_kernel<<<640, 256>>>(q1w, k1w, v1w, q2w, k2w, v2w, cw);      // launch 0
    dim3 g1(512, 8, 2);
    pass1_kernel<<<g1, 256, P1_SMEM>>>(t1, t2, k1b, v1b, k2b, v2b);   // launch 1
    dim3 gm(8, 2);
    mid_kernel<<<gm, 256>>>(r1w, r2w);                                // launch 2
    pass2_kernel<<<g1, 256, P2_SMEM>>>(t1, t2, q1b, r1b, q2b, r2b);   // launch 3
    dim3 gc(2, 256, 8);
    conv_kernel<<<gc, 256, CONV_SMEM>>>(cb, (float*)d_out);           // launch 4
}

// round 13
// speedup vs baseline: 1.0233x; 1.0233x over previous
#include <cuda_runtime.h>
#include <cuda_bf16.h>
#include <cstdint>

#define NPIX 65536
#define IMG_H 256
#define IMG_W 256
#define NB 8

// ---- device scratch ----
__device__ __nv_bfloat16 g_hi[NB * NPIX * 128];   // NHWC [b][y][x][ci], hi plane
__device__ __nv_bfloat16 g_lo[NB * NPIX * 128];   // lo plane
__device__ uint32_t g_Bfrag[3 * 24 * 2 * 32 * 16];  // conv weight mma frags
__device__ uint32_t g_QKVfrag[3 * 2 * 2 * 4 * 32 * 16]; // [kind q/k/v][br][half][kc][lane][ntj]
__device__ uint32_t g_RMfrag[16 * 2 * 4 * 32 * 16]; // [(br*8+b)][half][kc][lane][ntj]
__device__ float g_mat[2 * NB * 64 * 64];
__device__ float g_ksum[2 * NB * 64];
__device__ float g_vsum[2 * NB * 64];
__device__ float g_rv[2 * NB * 64];
__device__ float g_ksumE[2 * NB * 64];

// ---- mma.sync bf16 helper (m16n8k16, f32 accum) ----
__device__ __forceinline__ void mma_bf16(float* d,
                                         uint32_t a0, uint32_t a1, uint32_t a2, uint32_t a3,
                                         uint32_t b0, uint32_t b1) {
    asm volatile(
        "mma.sync.aligned.m16n8k16.row.col.f32.bf16.bf16.f32 "
        "{%0,%1,%2,%3}, {%4,%5,%6,%7}, {%8,%9}, {%0,%1,%2,%3};"
        : "+f"(d[0]), "+f"(d[1]), "+f"(d[2]), "+f"(d[3])
        : "r"(a0), "r"(a1), "r"(a2), "r"(a3), "r"(b0), "r"(b1));
}

__device__ __forceinline__ void ldsm_x4(uint32_t& r0, uint32_t& r1, uint32_t& r2, uint32_t& r3,
                                        uint32_t addr) {
    asm volatile("ldmatrix.sync.aligned.m8n8.x4.shared.b16 {%0,%1,%2,%3}, [%4];"
                 : "=r"(r0), "=r"(r1), "=r"(r2), "=r"(r3) : "r"(addr));
}
__device__ __forceinline__ void ldsm_x4_trans(uint32_t& r0, uint32_t& r1, uint32_t& r2, uint32_t& r3,
                                              uint32_t addr) {
    asm volatile("ldmatrix.sync.aligned.m8n8.x4.trans.shared.b16 {%0,%1,%2,%3}, [%4];"
                 : "=r"(r0), "=r"(r1), "=r"(r2), "=r"(r3) : "r"(addr));
}

__device__ __forceinline__ uint32_t smem_u32(const void* p) {
    uint32_t a;
    asm("{ .reg .u64 t; cvta.to.shared.u64 t, %1; cvt.u32.u64 %0, t; }" : "=r"(a) : "l"(p));
    return a;
}

__device__ __forceinline__ void splitbf(float a, float b, uint32_t& h, uint32_t& l) {
    __nv_bfloat16 ha = __float2bfloat16(a), hb = __float2bfloat16(b);
    __nv_bfloat162 hh; hh.x = ha; hh.y = hb;
    h = *(uint32_t*)&hh;
    __nv_bfloat162 ll = __floats2bfloat162_rn(a - __bfloat162float(ha),
                                              b - __bfloat162float(hb));
    l = *(uint32_t*)&ll;
}
__device__ __forceinline__ uint32_t packbf_hi_lo(float a, float b, int half) {
    if (half == 0) {
        __nv_bfloat162 hh; hh.x = __float2bfloat16(a); hh.y = __float2bfloat16(b);
        return *(uint32_t*)&hh;
    }
    __nv_bfloat16 ha = __float2bfloat16(a), hb = __float2bfloat16(b);
    __nv_bfloat162 ll = __floats2bfloat162_rn(a - __bfloat162float(ha),
                                              b - __bfloat162float(hb));
    return *(uint32_t*)&ll;
}

// -------------------- prep (single kernel) --------------------
__global__ void __launch_bounds__(256) prep_kernel(
    const float* __restrict__ q1w, const float* __restrict__ k1w, const float* __restrict__ v1w,
    const float* __restrict__ q2w, const float* __restrict__ k2w, const float* __restrict__ v2w,
    const float* __restrict__ cw)
{
    int nb = blockIdx.x, tid = threadIdx.x;
    if (nb < 256) {
        int idx = nb * 256 + tid;
        g_mat[idx] = 0.f;
        if (idx < 2 * NB * 64) { g_ksum[idx] = 0.f; g_vsum[idx] = 0.f; }
        return;
    }
    if (nb < 544) {
        int i = (nb - 256) * 256 + tid;  // 0..73727
        int ky = i / 24576;
        int rem = i % 24576;
        int kc = rem / 1024;
        int rem2 = rem % 1024;
        int half = rem2 / 512;
        int rem3 = rem2 % 512;
        int lane = rem3 / 16;
        int r4 = rem3 % 16;
        int nt = r4 >> 1, j = r4 & 1;
        int kx = kc >> 3, cc8 = kc & 7;
        int n = nt * 8 + (lane >> 2);
        int ci0 = cc8 * 16 + (lane & 3) * 2 + j * 8;
        float w0 = cw[((n * 128 + ci0) * 3 + ky) * 3 + kx];
        float w1 = cw[((n * 128 + ci0 + 1) * 3 + ky) * 3 + kx];
        g_Bfrag[i] = packbf_hi_lo(w0, w1, half);
        return;
    }
    {
        int t = nb - 544;                // 0..95
        int kind = t / 32;               // 0=q, 1=k, 2=v
        int i = (t % 32) * 256 + tid;    // 0..8191
        int br = i >> 12;
        int r = i & 4095;
        int half = r >> 11;
        int kc = (r >> 9) & 3;
        int lane = (r >> 4) & 31;
        int ntj = r & 15;
        int nt = ntj >> 1, j = ntj & 1;
        int o = nt * 8 + (lane >> 2);
        int c0 = kc * 16 + (lane & 3) * 2 + j * 8;
        const float* w;
        if (kind == 0) w = br ? q2w : q1w;
        else if (kind == 1) w = br ? k2w : k1w;
        else w = br ? v2w : v1w;
        float w0 = w[o * 64 + c0];
        float w1 = w[o * 64 + c0 + 1];
        g_QKVfrag[kind * 8192 + i] = packbf_hi_lo(w0, w1, half);
    }
}

// -------------------- pass 1: ldmatrix K,V proj + mma stats (round-11 version) ----
// grid (512, 8, 2), 256 thr = 8 warps, 2 CTAs/SM. Tile: 128 px.
// smem bytes: sXh [0,17408) | sXl [17408,34816) | Kp fp32 [34816,68608) | Vp [68608,102400)
#define P1_SMEM 102400

__global__ void __launch_bounds__(256, 2) pass1_kernel(
    const float* __restrict__ x1, const float* __restrict__ x2,
    const float* __restrict__ kb1, const float* __restrict__ vb1,
    const float* __restrict__ kb2, const float* __restrict__ vb2)
{
    extern __shared__ __align__(16) char dsm1c[];
    float* Kp = (float*)(dsm1c + 34816);
    float* Vp = (float*)(dsm1c + 68608);
    const uint32_t sbase = smem_u32(dsm1c);

    const int tid = threadIdx.x;
    const int lane = tid & 31, wt = tid >> 5;
    const int g = lane >> 2, tg = lane & 3;
    const int b = blockIdx.y, br = blockIdx.z;
    const int p0 = blockIdx.x * 128;
    const float* xb = (br ? x2 : x1) + (size_t)b * 64 * NPIX;
    const float* kb = br ? kb2 : kb1;
    const float* vb = br ? vb2 : vb1;

    // stage X as pre-split bf16 planes [c][px], stride 272B
    for (int i = tid; i < 2048; i += 256) {
        int c = i >> 5, chunk = i & 31;
        float4 xv = *(const float4*)&xb[(size_t)c * NPIX + p0 + chunk * 4];
        uint32_t h0, l0, h1, l1;
        splitbf(xv.x, xv.y, h0, l0);
        splitbf(xv.z, xv.w, h1, l1);
        *(uint2*)(dsm1c + c * 272 + chunk * 8) = make_uint2(h0, h1);
        *(uint2*)(dsm1c + 17408 + c * 272 + chunk * 8) = make_uint2(l0, l1);
    }
    __syncthreads();

    const uint32_t aH = sbase + ((((lane >> 4) & 1) * 8 + (lane & 7)) * 272)
                              + ((wt * 16 + ((lane >> 3) & 1) * 8) * 2);
    const uint32_t aL = aH + 17408;

    // ---- projections: kv=0 -> K (normalized at park), kv=1 -> V ----
#pragma unroll 1
    for (int kv = 0; kv < 2; kv++) {
        const uint32_t* wf = g_QKVfrag + (kv + 1) * 8192 + br * 4096;
        const float* bias = kv ? vb : kb;
        float* park = kv ? Vp : Kp;

        float acc[8][4];
#pragma unroll
        for (int nt = 0; nt < 8; nt++)
#pragma unroll
            for (int k = 0; k < 4; k++) acc[nt][k] = 0.f;

#pragma unroll
        for (int kc = 0; kc < 4; kc++) {
            const uint4* WH = (const uint4*)&wf[(0 * 4 + kc) * 512 + lane * 16];
            const uint4* WL = (const uint4*)&wf[(1 * 4 + kc) * 512 + lane * 16];
            uint4 bh[4], bl[4];
#pragma unroll
            for (int q = 0; q < 4; q++) { bh[q] = __ldg(&WH[q]); bl[q] = __ldg(&WL[q]); }
            uint32_t ah0, ah1, ah2, ah3, al0, al1, al2, al3;
            ldsm_x4_trans(ah0, ah1, ah2, ah3, aH + kc * 4352);
            ldsm_x4_trans(al0, al1, al2, al3, aL + kc * 4352);
#pragma unroll
            for (int nt = 0; nt < 8; nt++) {
                uint32_t b0h = (nt & 1) ? bh[nt >> 1].z : bh[nt >> 1].x;
                uint32_t b1h = (nt & 1) ? bh[nt >> 1].w : bh[nt >> 1].y;
                uint32_t b0l = (nt & 1) ? bl[nt >> 1].z : bl[nt >> 1].x;
                uint32_t b1l = (nt & 1) ? bl[nt >> 1].w : bl[nt >> 1].y;
                mma_bf16(acc[nt], ah0, ah1, ah2, ah3, b0h, b1h);
                mma_bf16(acc[nt], ah0, ah1, ah2, ah3, b0l, b1l);
                mma_bf16(acc[nt], al0, al1, al2, al3, b0h, b1h);
            }
        }

        // add bias
#pragma unroll
        for (int nt = 0; nt < 8; nt++) {
            float b0 = __ldg(&bias[nt * 8 + tg * 2 + 0]);
            float b1 = __ldg(&bias[nt * 8 + tg * 2 + 1]);
            acc[nt][0] += b0; acc[nt][1] += b1;
            acc[nt][2] += b0; acc[nt][3] += b1;
        }

        if (kv == 0) {
#pragma unroll
            for (int h = 0; h < 2; h++) {
                float s = 0.f;
#pragma unroll
                for (int nt = 0; nt < 8; nt++) {
                    float a = acc[nt][h * 2], c = acc[nt][h * 2 + 1];
                    s = fmaf(a, a, s); s = fmaf(c, c, s);
                }
                s += __shfl_xor_sync(0xffffffffu, s, 1);
                s += __shfl_xor_sync(0xffffffffu, s, 2);
                float inv = rsqrtf(s);
                int px = wt * 16 + g + h * 8;
#pragma unroll
                for (int nt = 0; nt < 8; nt++)
#pragma unroll
                    for (int j = 0; j < 2; j++)
                        park[(nt * 8 + tg * 2 + j) * 132 + px] = acc[nt][h * 2 + j] * inv;
            }
        } else {
#pragma unroll
            for (int h = 0; h < 2; h++) {
                int px = wt * 16 + g + h * 8;
#pragma unroll
                for (int nt = 0; nt < 8; nt++)
#pragma unroll
                    for (int j = 0; j < 2; j++)
                        park[(nt * 8 + tg * 2 + j) * 132 + px] = acc[nt][h * 2 + j];
            }
        }
    }
    __syncthreads();

    // ---- stats GEMM: matrix += Kn * V^T  (M=64 kch, N=64 vch, K=128 px) ----
    const int mt4 = wt >> 1;
    const int nh = wt & 1;
    float acc2[4][4];
#pragma unroll
    for (int nt = 0; nt < 4; nt++)
#pragma unroll
        for (int k = 0; k < 4; k++) acc2[nt][k] = 0.f;
    float ksg = 0.f, ksg8 = 0.f;
    float vs[4] = {0.f, 0.f, 0.f, 0.f};

#pragma unroll 2
    for (int kc = 0; kc < 8; kc++) {
        int px0 = kc * 16 + tg * 2;
        int m0 = mt4 * 16 + g;
        float2 k0 = *(const float2*)&Kp[m0 * 132 + px0];
        float2 k8 = *(const float2*)&Kp[m0 * 132 + px0 + 8];
        float2 k10 = *(const float2*)&Kp[(m0 + 8) * 132 + px0];
        float2 k18 = *(const float2*)&Kp[(m0 + 8) * 132 + px0 + 8];
        uint32_t a0h, a0l, a1h, a1l, a2h, a2l, a3h, a3l;
        splitbf(k0.x, k0.y, a0h, a0l);
        splitbf(k10.x, k10.y, a1h, a1l);
        splitbf(k8.x, k8.y, a2h, a2l);
        splitbf(k18.x, k18.y, a3h, a3l);
        if (nh == 0) {
            ksg += k0.x + k0.y + k8.x + k8.y;
            ksg8 += k10.x + k10.y + k18.x + k18.y;
        }
#pragma unroll
        for (int nt = 0; nt < 4; nt++) {
            int n = (nh * 4 + nt) * 8 + g;
            float2 b0 = *(const float2*)&Vp[n * 132 + px0];
            float2 b8 = *(const float2*)&Vp[n * 132 + px0 + 8];
            if (mt4 == 0) vs[nt] += b0.x + b0.y + b8.x + b8.y;
            uint32_t bh0, bl0, bh1, bl1;
            splitbf(b0.x, b0.y, bh0, bl0);
            splitbf(b8.x, b8.y, bh1, bl1);
            mma_bf16(acc2[nt], a0h, a1h, a2h, a3h, bh0, bh1);
            mma_bf16(acc2[nt], a0h, a1h, a2h, a3h, bl0, bl1);
            mma_bf16(acc2[nt], a0l, a1l, a2l, a3l, bh0, bh1);
        }
    }

    float* mat = g_mat + ((size_t)br * NB + b) * 4096;
#pragma unroll
    for (int nt = 0; nt < 4; nt++) {
#pragma unroll
        for (int k = 0; k < 4; k++) {
            int m = mt4 * 16 + g + ((k >= 2) ? 8 : 0);
            int n = (nh * 4 + nt) * 8 + tg * 2 + (k & 1);
            atomicAdd(&mat[m * 64 + n], acc2[nt][k]);
        }
    }
    if (nh == 0) {
        ksg += __shfl_xor_sync(0xffffffffu, ksg, 1);
        ksg += __shfl_xor_sync(0xffffffffu, ksg, 2);
        ksg8 += __shfl_xor_sync(0xffffffffu, ksg8, 1);
        ksg8 += __shfl_xor_sync(0xffffffffu, ksg8, 2);
        if (tg == 0) {
            float* kp = g_ksum + ((size_t)br * NB + b) * 64;
            atomicAdd(&kp[mt4 * 16 + g], ksg);
            atomicAdd(&kp[mt4 * 16 + g + 8], ksg8);
        }
    }
    if (mt4 == 0) {
#pragma unroll
        for (int nt = 0; nt < 4; nt++) {
            float v = vs[nt];
            v += __shfl_xor_sync(0xffffffffu, v, 1);
            v += __shfl_xor_sync(0xffffffffu, v, 2);
            if (tg == 0)
                atomicAdd(&g_vsum[((size_t)br * NB + b) * 64 + (nh * 4 + nt) * 8 + g], v);
        }
    }
}

// -------------------- mid: RM frags, rv, ksumE --------------------
__global__ void __launch_bounds__(256) mid_kernel(const float* __restrict__ rw1,
                                                  const float* __restrict__ rw2)
{
    __shared__ float sMat[4096];
    __shared__ float sRw[4096];
    const int tid = threadIdx.x;
    const int b = blockIdx.x, br = blockIdx.y;
    const float* rw = br ? rw2 : rw1;
    const float* mat = g_mat + ((size_t)br * NB + b) * 4096;
#pragma unroll
    for (int r = 0; r < 16; r++) {
        int i = tid + r * 256;
        sMat[i] = mat[i];
        sRw[i] = rw[i];
    }
    __syncthreads();
    const int ty = tid >> 4, tx = tid & 15;
    float acc[4][4];
#pragma unroll
    for (int i = 0; i < 4; i++)
#pragma unroll
        for (int j = 0; j < 4; j++) acc[i][j] = 0.f;
#pragma unroll 4
    for (int c = 0; c < 64; c++) {
        float a[4], w[4];
#pragma unroll
        for (int i = 0; i < 4; i++) a[i] = sMat[(ty * 4 + i) * 64 + c];
#pragma unroll
        for (int j = 0; j < 4; j++) w[j] = sRw[(tx * 4 + j) * 64 + c];
#pragma unroll
        for (int i = 0; i < 4; i++)
#pragma unroll
            for (int j = 0; j < 4; j++) acc[i][j] += a[i] * w[j];
    }
    if (tid < 64) {
        const float* vsump = g_vsum + ((size_t)br * NB + b) * 64;
        float s = 0.f;
        for (int c = 0; c < 64; c++) s += sRw[tid * 64 + c] * vsump[c];
        g_rv[((size_t)br * NB + b) * 64 + tid] = s;
        g_ksumE[((size_t)br * NB + b) * 64 + tid] =
            g_ksum[((size_t)br * NB + b) * 64 + tid] + 1e-6f;
    }
    __syncthreads();
#pragma unroll
    for (int i = 0; i < 4; i++)
#pragma unroll
        for (int j = 0; j < 4; j++)
            sMat[(tx * 4 + j) * 64 + (ty * 4 + i)] = acc[i][j];
    __syncthreads();
    uint32_t* dst = g_RMfrag + (size_t)(br * 8 + b) * 4096;
    for (int t = tid; t < 4096; t += 256) {
        int half = t >> 11;
        int lane = (t >> 4) & 31;
        int ntj = t & 15;
        int nt = ntj >> 1, j = ntj & 1;
        int kc = (t >> 9) & 3;
        int o = nt * 8 + (lane >> 2);
        int m0 = kc * 16 + (lane & 3) * 2 + j * 8;
        float w0 = sMat[o * 64 + m0];
        float w1 = sMat[o * 64 + m0 + 1];
        dst[t] = packbf_hi_lo(w0, w1, half);
    }
}

// -------------------- pass 2: ldmatrix Q proj + register-resident RM*Qn -----------
#define P2_SMEM 36864

__global__ void __launch_bounds__(256, 2) pass2_kernel(
    const float* __restrict__ x1, const float* __restrict__ x2,
    const float* __restrict__ qb1, const float* __restrict__ rb1,
    const float* __restrict__ qb2, const float* __restrict__ rb2)
{
    extern __shared__ __align__(16) char dsmc2[];
    const uint32_t sbase = smem_u32(dsmc2);

    const int tid = threadIdx.x;
    const int lane = tid & 31, wt = tid >> 5;
    const int g = lane >> 2, tg = lane & 3;
    const int b = blockIdx.y, br = blockIdx.z;
    const int p0 = blockIdx.x * 128;
    const float* xb = (br ? x2 : x1) + (size_t)b * 64 * NPIX;
    const float* qb = br ? qb2 : qb1;
    const float* rb = br ? rb2 : rb1;
    const float* ksE = g_ksumE + ((size_t)br * NB + b) * 64;
    const float* rvp = g_rv + ((size_t)br * NB + b) * 64;

    for (int i = tid; i < 2048; i += 256) {
        int c = i >> 5, chunk = i & 31;
        float4 xv = *(const float4*)&xb[(size_t)c * NPIX + p0 + chunk * 4];
        uint32_t h0, l0, h1, l1;
        splitbf(xv.x, xv.y, h0, l0);
        splitbf(xv.z, xv.w, h1, l1);
        *(uint2*)(dsmc2 + c * 272 + chunk * 8) = make_uint2(h0, h1);
        *(uint2*)(dsmc2 + 17408 + c * 272 + chunk * 8) = make_uint2(l0, l1);
    }
    __syncthreads();

    const uint32_t aHa = sbase + ((((lane >> 4) & 1) * 8 + (lane & 7)) * 272)
                               + ((wt * 16 + ((lane >> 3) & 1) * 8) * 2);
    const uint32_t aLa = aHa + 17408;

    // ---- phase A: Q = Wq*x + qb ----
    float acc[8][4];
#pragma unroll
    for (int nt = 0; nt < 8; nt++)
#pragma unroll
        for (int k = 0; k < 4; k++) acc[nt][k] = 0.f;

#pragma unroll
    for (int kc = 0; kc < 4; kc++) {
        const uint4* WH = (const uint4*)&g_QKVfrag[((br * 2 + 0) * 4 + kc) * 512 + lane * 16];
        const uint4* WL = (const uint4*)&g_QKVfrag[((br * 2 + 1) * 4 + kc) * 512 + lane * 16];
        uint4 bh[4], bl[4];
#pragma unroll
        for (int q = 0; q < 4; q++) { bh[q] = __ldg(&WH[q]); bl[q] = __ldg(&WL[q]); }
        uint32_t ah0, ah1, ah2, ah3, al0, al1, al2, al3;
        ldsm_x4_trans(ah0, ah1, ah2, ah3, aHa + kc * 4352);
        ldsm_x4_trans(al0, al1, al2, al3, aLa + kc * 4352);
#pragma unroll
        for (int nt = 0; nt < 8; nt++) {
            uint32_t b0h = (nt & 1) ? bh[nt >> 1].z : bh[nt >> 1].x;
            uint32_t b1h = (nt & 1) ? bh[nt >> 1].w : bh[nt >> 1].y;
            uint32_t b0l = (nt & 1) ? bl[nt >> 1].z : bl[nt >> 1].x;
            uint32_t b1l = (nt & 1) ? bl[nt >> 1].w : bl[nt >> 1].y;
            mma_bf16(acc[nt], ah0, ah1, ah2, ah3, b0h, b1h);
            mma_bf16(acc[nt], ah0, ah1, ah2, ah3, b0l, b1l);
            mma_bf16(acc[nt], al0, al1, al2, al3, b0h, b1h);
        }
    }
    __syncthreads();   // X dead; smem free for staging

    // add qb
    float kse[16];
#pragma unroll
    for (int nt = 0; nt < 8; nt++) {
        float q0 = __ldg(&qb[nt * 8 + tg * 2 + 0]);
        float q1 = __ldg(&qb[nt * 8 + tg * 2 + 1]);
        kse[nt * 2 + 0] = __ldg(&ksE[nt * 8 + tg * 2 + 0]);
        kse[nt * 2 + 1] = __ldg(&ksE[nt * 8 + tg * 2 + 1]);
        acc[nt][0] += q0; acc[nt][1] += q1;
        acc[nt][2] += q0; acc[nt][3] += q1;
    }

    // per-px inv + den via quad shfl
    float invv[2], denn[2];
#pragma unroll
    for (int h = 0; h < 2; h++) {
        float s = 0.f, d = 0.f;
#pragma unroll
        for (int nt = 0; nt < 8; nt++) {
            float a = acc[nt][h * 2], c = acc[nt][h * 2 + 1];
            s = fmaf(a, a, s); s = fmaf(c, c, s);
            d = fmaf(a, kse[nt * 2], d); d = fmaf(c, kse[nt * 2 + 1], d);
        }
        s += __shfl_xor_sync(0xffffffffu, s, 1);
        s += __shfl_xor_sync(0xffffffffu, s, 2);
        d += __shfl_xor_sync(0xffffffffu, d, 1);
        d += __shfl_xor_sync(0xffffffffu, d, 2);
        float inv = rsqrtf(s);
        invv[h] = inv;
        denn[h] = 1.f / (65536.f + inv * d);
    }

    // ---- phase B from registers: out = RM * (Q * inv) ----
    float acc2[8][4];
#pragma unroll
    for (int nt = 0; nt < 8; nt++)
#pragma unroll
        for (int k = 0; k < 4; k++) acc2[nt][k] = 0.f;

    const uint32_t* rmbase = g_RMfrag + (size_t)(br * 8 + b) * 4096;
#pragma unroll
    for (int kc = 0; kc < 4; kc++) {
        const uint4* RH = (const uint4*)&rmbase[(0 * 4 + kc) * 512 + lane * 16];
        const uint4* RL = (const uint4*)&rmbase[(1 * 4 + kc) * 512 + lane * 16];
        uint4 bh[4], bl[4];
#pragma unroll
        for (int q = 0; q < 4; q++) { bh[q] = __ldg(&RH[q]); bl[q] = __ldg(&RL[q]); }
        float i0 = invv[0], i1 = invv[1];
        uint32_t ah0, ah1, ah2, ah3, al0, al1, al2, al3;
        splitbf(acc[2 * kc][0] * i0, acc[2 * kc][1] * i0, ah0, al0);
        splitbf(acc[2 * kc][2] * i1, acc[2 * kc][3] * i1, ah1, al1);
        splitbf(acc[2 * kc + 1][0] * i0, acc[2 * kc + 1][1] * i0, ah2, al2);
        splitbf(acc[2 * kc + 1][2] * i1, acc[2 * kc + 1][3] * i1, ah3, al3);
#pragma unroll
        for (int nt = 0; nt < 8; nt++) {
            uint32_t b0h = (nt & 1) ? bh[nt >> 1].z : bh[nt >> 1].x;
            uint32_t b1h = (nt & 1) ? bh[nt >> 1].w : bh[nt >> 1].y;
            uint32_t b0l = (nt & 1) ? bl[nt >> 1].z : bl[nt >> 1].x;
            uint32_t b1l = (nt & 1) ? bl[nt >> 1].w : bl[nt >> 1].y;
            mma_bf16(acc2[nt], ah0, ah1, ah2, ah3, b0h, b1h);
            mma_bf16(acc2[nt], ah0, ah1, ah2, ah3, b0l, b1l);
            mma_bf16(acc2[nt], al0, al1, al2, al3, b0h, b1h);
        }
    }

    // epilogue -> bf16 hi/lo planes [px][72 bf16 stride] in smem, packed STS.32
#pragma unroll
    for (int nt = 0; nt < 8; nt++) {
        int o = nt * 8 + tg * 2;
        float rv0 = __ldg(&rvp[o]), rv1 = __ldg(&rvp[o + 1]);
        float rb0 = __ldg(&rb[o]),  rb1 = __ldg(&rb[o + 1]);
#pragma unroll
        for (int h = 0; h < 2; h++) {
            int r = wt * 16 + g + h * 8;
            float den = denn[h];
            float v0 = den * (rv0 + acc2[nt][h * 2 + 0]) + rb0;
            float v1 = den * (rv1 + acc2[nt][h * 2 + 1]) + rb1;
            uint32_t ph, pl;
            splitbf(v0, v1, ph, pl);
            *(uint32_t*)(dsmc2 + r * 144 + o * 2) = ph;
            *(uint32_t*)(dsmc2 + 18432 + r * 144 + o * 2) = pl;
        }
    }
    __syncthreads();

    for (int u = tid; u < 2048; u += 256) {
        int plane = u >> 10;
        int rest = u & 1023;
        int px = rest >> 3, q = rest & 7;
        uint4 val = *(const uint4*)(dsmc2 + plane * 18432 + px * 144 + q * 16);
        __nv_bfloat16* dst = plane ? g_lo : g_hi;
        *(uint4*)&dst[((size_t)(b * NPIX + p0 + px)) * 128 + br * 64 + q * 8] = val;
    }
}

// -------------------- conv: ldmatrix bf16-split implicit GEMM (kc-loop unrolled) --
#define STRIP_STRIDE 272
#define STRIP_BYTES (130 * STRIP_STRIDE)
#define CONV_SMEM (2 * STRIP_BYTES)

__global__ void __launch_bounds__(256, 2) conv_kernel(const float* __restrict__ cbias,
                                                      float* __restrict__ out)
{
    extern __shared__ __align__(16) char dsmc[];
    char* sHi = dsmc;
    char* sLo = dsmc + STRIP_BYTES;
    float* sOut = (float*)dsmc;
    const uint32_t sHiB = smem_u32(dsmc);

    const int tid = threadIdx.x;
    const int lane = tid & 31, wt = tid >> 5;
    const int x0 = blockIdx.x * 128, y = blockIdx.y, b = blockIdx.z;

    float acc[8][4];
#pragma unroll
    for (int nt = 0; nt < 8; nt++)
#pragma unroll
        for (int j = 0; j < 4; j++) acc[nt][j] = 0.f;

    const int g = lane >> 2, tg = lane & 3;
    const uint32_t aBase = (uint32_t)((wt * 16 + ((lane >> 3) & 1) * 8 + (lane & 7)) * STRIP_STRIDE
                                      + ((lane >> 4) & 1) * 16);

    for (int ky = 0; ky < 3; ky++) {
        int yy = y + ky - 1;
        bool yok = (yy >= 0 && yy < IMG_H);
        __syncthreads();
        if (yok) {
            size_t rowbase = ((size_t)b * NPIX + (size_t)yy * IMG_W) * 128;
            for (int i = tid; i < 130 * 16; i += 256) {
                int row = i >> 4, ch = i & 15;
                int px = x0 + row - 1;
                uint4 vh = make_uint4(0u, 0u, 0u, 0u);
                uint4 vl = make_uint4(0u, 0u, 0u, 0u);
                if (px >= 0 && px < IMG_W) {
                    size_t gi = rowbase + (size_t)px * 128 + ch * 8;
                    vh = *(const uint4*)&g_hi[gi];
                    vl = *(const uint4*)&g_lo[gi];
                }
                *(uint4*)(sHi + row * STRIP_STRIDE + ch * 16) = vh;
                *(uint4*)(sLo + row * STRIP_STRIDE + ch * 16) = vl;
            }
        }
        __syncthreads();
        if (!yok) continue;

        // unrolled mainloop: lets ptxas overlap iter i+1's LDG/LDSM with iter i's mma
#pragma unroll 4
        for (int kc = 0; kc < 24; kc++) {
            int kx = kc >> 3, cc8 = kc & 7;
            // loads first (independent), mma after
            const uint4* bfH = (const uint4*)(g_Bfrag + (((ky * 24 + kc) * 2 + 0) * 32 + lane) * 16);
            const uint4* bfL = (const uint4*)(g_Bfrag + (((ky * 24 + kc) * 2 + 1) * 32 + lane) * 16);
            uint4 bh[4], bl[4];
#pragma unroll
            for (int q = 0; q < 4; q++) { bh[q] = __ldg(&bfH[q]); bl[q] = __ldg(&bfL[q]); }
            uint32_t ad = sHiB + aBase + kx * STRIP_STRIDE + cc8 * 32;
            uint32_t ah0, ah1, ah2, ah3, al0, al1, al2, al3;
            ldsm_x4(ah0, ah1, ah2, ah3, ad);
            ldsm_x4(al0, al1, al2, al3, ad + STRIP_BYTES);

#pragma unroll
            for (int nt = 0; nt < 8; nt++) {
                uint32_t bh0 = (nt & 1) ? bh[nt >> 1].z : bh[nt >> 1].x;
                uint32_t bh1 = (nt & 1) ? bh[nt >> 1].w : bh[nt >> 1].y;
                uint32_t bl0 = (nt & 1) ? bl[nt >> 1].z : bl[nt >> 1].x;
                uint32_t bl1 = (nt & 1) ? bl[nt >> 1].w : bl[nt >> 1].y;
                mma_bf16(acc[nt], ah0, ah1, ah2, ah3, bh0, bh1);
                mma_bf16(acc[nt], ah0, ah1, ah2, ah3, bl0, bl1);
                mma_bf16(acc[nt], al0, al1, al2, al3, bh0, bh1);
            }
        }
    }

    __syncthreads();
#pragma unroll
    for (int nt = 0; nt < 8; nt++)
#pragma unroll
        for (int h = 0; h < 2; h++)
#pragma unroll
            for (int j = 0; j < 2; j++) {
                int o = nt * 8 + tg * 2 + j;
                int px = wt * 16 + g + h * 8;
                sOut[o * 132 + px] = acc[nt][h * 2 + j];
            }
    __syncthreads();
    for (int i = tid; i < 64 * 32; i += 256) {
        int o = i >> 5, ch = i & 31;
        float4 v = *(const float4*)&sOut[o * 132 + ch * 4];
        float bias = __ldg(&cbias[o]);
        v.x += bias; v.y += bias; v.z += bias; v.w += bias;
        *(float4*)&out[((size_t)(b * 64 + o)) * NPIX + (size_t)y * IMG_W + x0 + ch * 4] = v;
    }
}

// -------------------- launch --------------------
extern "C" void kernel_launch(void* const* d_in, const int* in_sizes, int n_in,
                              void* d_out, int out_size)
{
    (void)in_sizes; (void)n_in; (void)out_size;
    const float* t1  = (const float*)d_in[0];
    const float* t2  = (const float*)d_in[1];
    const float* q1w = (const float*)d_in[2];  const float* q1b = (const float*)d_in[3];
    const float* k1w = (const float*)d_in[4];  const float* k1b = (const float*)d_in[5];
    const float* v1w = (const float*)d_in[6];  const float* v1b = (const float*)d_in[7];
    const float* r1w = (const float*)d_in[8];  const float* r1b = (const float*)d_in[9];
    const float* q2w = (const float*)d_in[10]; const float* q2b = (const float*)d_in[11];
    const float* k2w = (const float*)d_in[12]; const float* k2b = (const float*)d_in[13];
    const float* v2w = (const float*)d_in[14]; const float* v2b = (const float*)d_in[15];
    const float* r2w = (const float*)d_in[16]; const float* r2b = (const float*)d_in[17];
    const float* cw  = (const float*)d_in[18]; const float* cb  = (const float*)d_in[19];

    cudaFuncSetAttribute(pass1_kernel, cudaFuncAttributeMaxDynamicSharedMemorySize, P1_SMEM);
    cudaFuncSetAttribute(pass2_kernel, cudaFuncAttributeMaxDynamicSharedMemorySize, P2_SMEM);
    cudaFuncSetAttribute(conv_kernel, cudaFuncAttributeMaxDynamicSharedMemorySize, CONV_SMEM);

    prep_kernel<<<640, 256>>>(q1w, k1w, v1w, q2w, k2w, v2w, cw);      // launch 0
    dim3 g1(512, 8, 2);
    pass1_kernel<<<g1, 256, P1_SMEM>>>(t1, t2, k1b, v1b, k2b, v2b);   // launch 1
    dim3 gm(8, 2);
    mid_kernel<<<gm, 256>>>(r1w, r2w);                                // launch 2
    pass2_kernel<<<g1, 256, P2_SMEM>>>(t1, t2, q1b, r1b, q2b, r2b);   // launch 3
    dim3 gc(2, 256, 8);
    conv_kernel<<<gc, 256, CONV_SMEM>>>(cb, (float*)d_out);           // launch 4
}

// round 14
// speedup vs baseline: 1.0250x; 1.0016x over previous
#include <cuda_runtime.h>
#include <cuda_bf16.h>
#include <cstdint>

#define NPIX 65536
#define IMG_H 256
#define IMG_W 256
#define NB 8

// ---- device scratch ----
__device__ __nv_bfloat16 g_hi[NB * NPIX * 128];   // NHWC [b][y][x][ci], hi plane
__device__ __nv_bfloat16 g_lo[NB * NPIX * 128];   // lo plane
__device__ uint32_t g_Bfrag[3 * 24 * 2 * 32 * 16];  // conv weight mma frags
__device__ uint32_t g_QKVfrag[3 * 2 * 2 * 4 * 32 * 16]; // [kind q/k/v][br][half][kc][lane][ntj]
__device__ uint32_t g_RMfrag[16 * 2 * 4 * 32 * 16]; // [(br*8+b)][half][kc][lane][ntj]
__device__ float g_mat[2 * NB * 64 * 64];
__device__ float g_ksum[2 * NB * 64];
__device__ float g_vsum[2 * NB * 64];
__device__ float g_rv[2 * NB * 64];
__device__ float g_ksumE[2 * NB * 64];

// ---- mma.sync bf16 helper (m16n8k16, f32 accum) ----
__device__ __forceinline__ void mma_bf16(float* d,
                                         uint32_t a0, uint32_t a1, uint32_t a2, uint32_t a3,
                                         uint32_t b0, uint32_t b1) {
    asm volatile(
        "mma.sync.aligned.m16n8k16.row.col.f32.bf16.bf16.f32 "
        "{%0,%1,%2,%3}, {%4,%5,%6,%7}, {%8,%9}, {%0,%1,%2,%3};"
        : "+f"(d[0]), "+f"(d[1]), "+f"(d[2]), "+f"(d[3])
        : "r"(a0), "r"(a1), "r"(a2), "r"(a3), "r"(b0), "r"(b1));
}

__device__ __forceinline__ void ldsm_x4(uint32_t& r0, uint32_t& r1, uint32_t& r2, uint32_t& r3,
                                        uint32_t addr) {
    asm volatile("ldmatrix.sync.aligned.m8n8.x4.shared.b16 {%0,%1,%2,%3}, [%4];"
                 : "=r"(r0), "=r"(r1), "=r"(r2), "=r"(r3) : "r"(addr));
}
__device__ __forceinline__ void ldsm_x4_trans(uint32_t& r0, uint32_t& r1, uint32_t& r2, uint32_t& r3,
                                              uint32_t addr) {
    asm volatile("ldmatrix.sync.aligned.m8n8.x4.trans.shared.b16 {%0,%1,%2,%3}, [%4];"
                 : "=r"(r0), "=r"(r1), "=r"(r2), "=r"(r3) : "r"(addr));
}

__device__ __forceinline__ uint32_t smem_u32(const void* p) {
    uint32_t a;
    asm("{ .reg .u64 t; cvta.to.shared.u64 t, %1; cvt.u32.u64 %0, t; }" : "=r"(a) : "l"(p));
    return a;
}

__device__ __forceinline__ void splitbf(float a, float b, uint32_t& h, uint32_t& l) {
    __nv_bfloat16 ha = __float2bfloat16(a), hb = __float2bfloat16(b);
    __nv_bfloat162 hh; hh.x = ha; hh.y = hb;
    h = *(uint32_t*)&hh;
    __nv_bfloat162 ll = __floats2bfloat162_rn(a - __bfloat162float(ha),
                                              b - __bfloat162float(hb));
    l = *(uint32_t*)&ll;
}
__device__ __forceinline__ uint32_t packbf_hi_lo(float a, float b, int half) {
    if (half == 0) {
        __nv_bfloat162 hh; hh.x = __float2bfloat16(a); hh.y = __float2bfloat16(b);
        return *(uint32_t*)&hh;
    }
    __nv_bfloat16 ha = __float2bfloat16(a), hb = __float2bfloat16(b);
    __nv_bfloat162 ll = __floats2bfloat162_rn(a - __bfloat162float(ha),
                                              b - __bfloat162float(hb));
    return *(uint32_t*)&ll;
}

// -------------------- prep, split into 3 launches (puts pass1 at capture idx 3) ----
__global__ void __launch_bounds__(256) prep_zero_kernel() {
    int idx = blockIdx.x * 256 + threadIdx.x;   // grid 256 -> 65536
    g_mat[idx] = 0.f;
    if (idx < 2 * NB * 64) { g_ksum[idx] = 0.f; g_vsum[idx] = 0.f; }
}

__global__ void __launch_bounds__(256) prep_conv_kernel(const float* __restrict__ cw) {
    int i = blockIdx.x * 256 + threadIdx.x;     // grid 288 -> 73728
    if (i >= 73728) return;
    int ky = i / 24576;
    int rem = i % 24576;
    int kc = rem / 1024;
    int rem2 = rem % 1024;
    int half = rem2 / 512;
    int rem3 = rem2 % 512;
    int lane = rem3 / 16;
    int r4 = rem3 % 16;
    int nt = r4 >> 1, j = r4 & 1;
    int kx = kc >> 3, cc8 = kc & 7;
    int n = nt * 8 + (lane >> 2);
    int ci0 = cc8 * 16 + (lane & 3) * 2 + j * 8;
    float w0 = cw[((n * 128 + ci0) * 3 + ky) * 3 + kx];
    float w1 = cw[((n * 128 + ci0 + 1) * 3 + ky) * 3 + kx];
    g_Bfrag[i] = packbf_hi_lo(w0, w1, half);
}

__global__ void __launch_bounds__(256) prep_qkv_kernel(
    const float* __restrict__ q1w, const float* __restrict__ k1w, const float* __restrict__ v1w,
    const float* __restrict__ q2w, const float* __restrict__ k2w, const float* __restrict__ v2w)
{
    int t = blockIdx.x;                          // grid 96
    int kind = t / 32;                           // 0=q, 1=k, 2=v
    int i = (t % 32) * 256 + threadIdx.x;        // 0..8191
    int br = i >> 12;
    int r = i & 4095;
    int half = r >> 11;
    int kc = (r >> 9) & 3;
    int lane = (r >> 4) & 31;
    int ntj = r & 15;
    int nt = ntj >> 1, j = ntj & 1;
    int o = nt * 8 + (lane >> 2);
    int c0 = kc * 16 + (lane & 3) * 2 + j * 8;
    const float* w;
    if (kind == 0) w = br ? q2w : q1w;
    else if (kind == 1) w = br ? k2w : k1w;
    else w = br ? v2w : v1w;
    float w0 = w[o * 64 + c0];
    float w1 = w[o * 64 + c0 + 1];
    g_QKVfrag[kind * 8192 + i] = packbf_hi_lo(w0, w1, half);
}

// -------------------- pass 1: ldmatrix K,V proj + mma stats --------------------
// grid (512, 8, 2), 256 thr = 8 warps, 2 CTAs/SM. Tile: 128 px.
// smem bytes: sXh [0,17408) | sXl [17408,34816) | Kp fp32 [34816,68608) | Vp [68608,102400)
#define P1_SMEM 102400

__global__ void __launch_bounds__(256, 2) pass1_kernel(
    const float* __restrict__ x1, const float* __restrict__ x2,
    const float* __restrict__ kb1, const float* __restrict__ vb1,
    const float* __restrict__ kb2, const float* __restrict__ vb2)
{
    extern __shared__ __align__(16) char dsm1c[];
    float* Kp = (float*)(dsm1c + 34816);
    float* Vp = (float*)(dsm1c + 68608);
    const uint32_t sbase = smem_u32(dsm1c);

    const int tid = threadIdx.x;
    const int lane = tid & 31, wt = tid >> 5;
    const int g = lane >> 2, tg = lane & 3;
    const int b = blockIdx.y, br = blockIdx.z;
    const int p0 = blockIdx.x * 128;
    const float* xb = (br ? x2 : x1) + (size_t)b * 64 * NPIX;
    const float* kb = br ? kb2 : kb1;
    const float* vb = br ? vb2 : vb1;

    // stage X as pre-split bf16 planes [c][px], stride 272B
    for (int i = tid; i < 2048; i += 256) {
        int c = i >> 5, chunk = i & 31;
        float4 xv = *(const float4*)&xb[(size_t)c * NPIX + p0 + chunk * 4];
        uint32_t h0, l0, h1, l1;
        splitbf(xv.x, xv.y, h0, l0);
        splitbf(xv.z, xv.w, h1, l1);
        *(uint2*)(dsm1c + c * 272 + chunk * 8) = make_uint2(h0, h1);
        *(uint2*)(dsm1c + 17408 + c * 272 + chunk * 8) = make_uint2(l0, l1);
    }
    __syncthreads();

    const uint32_t aH = sbase + ((((lane >> 4) & 1) * 8 + (lane & 7)) * 272)
                              + ((wt * 16 + ((lane >> 3) & 1) * 8) * 2);
    const uint32_t aL = aH + 17408;

    // ---- projections: kv=0 -> K (normalized at park), kv=1 -> V ----
#pragma unroll 1
    for (int kv = 0; kv < 2; kv++) {
        const uint32_t* wf = g_QKVfrag + (kv + 1) * 8192 + br * 4096;
        const float* bias = kv ? vb : kb;
        float* park = kv ? Vp : Kp;

        float acc[8][4];
#pragma unroll
        for (int nt = 0; nt < 8; nt++)
#pragma unroll
            for (int k = 0; k < 4; k++) acc[nt][k] = 0.f;

#pragma unroll
        for (int kc = 0; kc < 4; kc++) {
            const uint4* WH = (const uint4*)&wf[(0 * 4 + kc) * 512 + lane * 16];
            const uint4* WL = (const uint4*)&wf[(1 * 4 + kc) * 512 + lane * 16];
            uint4 bh[4], bl[4];
#pragma unroll
            for (int q = 0; q < 4; q++) { bh[q] = __ldg(&WH[q]); bl[q] = __ldg(&WL[q]); }
            uint32_t ah0, ah1, ah2, ah3, al0, al1, al2, al3;
            ldsm_x4_trans(ah0, ah1, ah2, ah3, aH + kc * 4352);
            ldsm_x4_trans(al0, al1, al2, al3, aL + kc * 4352);
#pragma unroll
            for (int nt = 0; nt < 8; nt++) {
                uint32_t b0h = (nt & 1) ? bh[nt >> 1].z : bh[nt >> 1].x;
                uint32_t b1h = (nt & 1) ? bh[nt >> 1].w : bh[nt >> 1].y;
                uint32_t b0l = (nt & 1) ? bl[nt >> 1].z : bl[nt >> 1].x;
                uint32_t b1l = (nt & 1) ? bl[nt >> 1].w : bl[nt >> 1].y;
                mma_bf16(acc[nt], ah0, ah1, ah2, ah3, b0h, b1h);
                mma_bf16(acc[nt], ah0, ah1, ah2, ah3, b0l, b1l);
                mma_bf16(acc[nt], al0, al1, al2, al3, b0h, b1h);
            }
        }

        // add bias
#pragma unroll
        for (int nt = 0; nt < 8; nt++) {
            float b0 = __ldg(&bias[nt * 8 + tg * 2 + 0]);
            float b1 = __ldg(&bias[nt * 8 + tg * 2 + 1]);
            acc[nt][0] += b0; acc[nt][1] += b1;
            acc[nt][2] += b0; acc[nt][3] += b1;
        }

        if (kv == 0) {
#pragma unroll
            for (int h = 0; h < 2; h++) {
                float s = 0.f;
#pragma unroll
                for (int nt = 0; nt < 8; nt++) {
                    float a = acc[nt][h * 2], c = acc[nt][h * 2 + 1];
                    s = fmaf(a, a, s); s = fmaf(c, c, s);
                }
                s += __shfl_xor_sync(0xffffffffu, s, 1);
                s += __shfl_xor_sync(0xffffffffu, s, 2);
                float inv = rsqrtf(s);
                int px = wt * 16 + g + h * 8;
#pragma unroll
                for (int nt = 0; nt < 8; nt++)
#pragma unroll
                    for (int j = 0; j < 2; j++)
                        park[(nt * 8 + tg * 2 + j) * 132 + px] = acc[nt][h * 2 + j] * inv;
            }
        } else {
#pragma unroll
            for (int h = 0; h < 2; h++) {
                int px = wt * 16 + g + h * 8;
#pragma unroll
                for (int nt = 0; nt < 8; nt++)
#pragma unroll
                    for (int j = 0; j < 2; j++)
                        park[(nt * 8 + tg * 2 + j) * 132 + px] = acc[nt][h * 2 + j];
            }
        }
    }
    __syncthreads();

    // ---- stats GEMM: matrix += Kn * V^T  (M=64 kch, N=64 vch, K=128 px) ----
    const int mt4 = wt >> 1;
    const int nh = wt & 1;
    float acc2[4][4];
#pragma unroll
    for (int nt = 0; nt < 4; nt++)
#pragma unroll
        for (int k = 0; k < 4; k++) acc2[nt][k] = 0.f;
    float ksg = 0.f, ksg8 = 0.f;
    float vs[4] = {0.f, 0.f, 0.f, 0.f};

#pragma unroll 4
    for (int kc = 0; kc < 8; kc++) {
        int px0 = kc * 16 + tg * 2;
        int m0 = mt4 * 16 + g;
        float2 k0 = *(const float2*)&Kp[m0 * 132 + px0];
        float2 k8 = *(const float2*)&Kp[m0 * 132 + px0 + 8];
        float2 k10 = *(const float2*)&Kp[(m0 + 8) * 132 + px0];
        float2 k18 = *(const float2*)&Kp[(m0 + 8) * 132 + px0 + 8];
        uint32_t a0h, a0l, a1h, a1l, a2h, a2l, a3h, a3l;
        splitbf(k0.x, k0.y, a0h, a0l);
        splitbf(k10.x, k10.y, a1h, a1l);
        splitbf(k8.x, k8.y, a2h, a2l);
        splitbf(k18.x, k18.y, a3h, a3l);
        if (nh == 0) {
            ksg += k0.x + k0.y + k8.x + k8.y;
            ksg8 += k10.x + k10.y + k18.x + k18.y;
        }
#pragma unroll
        for (int nt = 0; nt < 4; nt++) {
            int n = (nh * 4 + nt) * 8 + g;
            float2 b0 = *(const float2*)&Vp[n * 132 + px0];
            float2 b8 = *(const float2*)&Vp[n * 132 + px0 + 8];
            if (mt4 == 0) vs[nt] += b0.x + b0.y + b8.x + b8.y;
            uint32_t bh0, bl0, bh1, bl1;
            splitbf(b0.x, b0.y, bh0, bl0);
            splitbf(b8.x, b8.y, bh1, bl1);
            mma_bf16(acc2[nt], a0h, a1h, a2h, a3h, bh0, bh1);
            mma_bf16(acc2[nt], a0h, a1h, a2h, a3h, bl0, bl1);
            mma_bf16(acc2[nt], a0l, a1l, a2l, a3l, bh0, bh1);
        }
    }

    float* mat = g_mat + ((size_t)br * NB + b) * 4096;
#pragma unroll
    for (int nt = 0; nt < 4; nt++) {
#pragma unroll
        for (int k = 0; k < 4; k++) {
            int m = mt4 * 16 + g + ((k >= 2) ? 8 : 0);
            int n = (nh * 4 + nt) * 8 + tg * 2 + (k & 1);
            atomicAdd(&mat[m * 64 + n], acc2[nt][k]);
        }
    }
    if (nh == 0) {
        ksg += __shfl_xor_sync(0xffffffffu, ksg, 1);
        ksg += __shfl_xor_sync(0xffffffffu, ksg, 2);
        ksg8 += __shfl_xor_sync(0xffffffffu, ksg8, 1);
        ksg8 += __shfl_xor_sync(0xffffffffu, ksg8, 2);
        if (tg == 0) {
            float* kp = g_ksum + ((size_t)br * NB + b) * 64;
            atomicAdd(&kp[mt4 * 16 + g], ksg);
            atomicAdd(&kp[mt4 * 16 + g + 8], ksg8);
        }
    }
    if (mt4 == 0) {
#pragma unroll
        for (int nt = 0; nt < 4; nt++) {
            float v = vs[nt];
            v += __shfl_xor_sync(0xffffffffu, v, 1);
            v += __shfl_xor_sync(0xffffffffu, v, 2);
            if (tg == 0)
                atomicAdd(&g_vsum[((size_t)br * NB + b) * 64 + (nh * 4 + nt) * 8 + g], v);
        }
    }
}

// -------------------- mid: RM frags, rv, ksumE --------------------
__global__ void __launch_bounds__(256) mid_kernel(const float* __restrict__ rw1,
                                                  const float* __restrict__ rw2)
{
    __shared__ float sMat[4096];
    __shared__ float sRw[4096];
    const int tid = threadIdx.x;
    const int b = blockIdx.x, br = blockIdx.y;
    const float* rw = br ? rw2 : rw1;
    const float* mat = g_mat + ((size_t)br * NB + b) * 4096;
#pragma unroll
    for (int r = 0; r < 16; r++) {
        int i = tid + r * 256;
        sMat[i] = mat[i];
        sRw[i] = rw[i];
    }
    __syncthreads();
    const int ty = tid >> 4, tx = tid & 15;
    float acc[4][4];
#pragma unroll
    for (int i = 0; i < 4; i++)
#pragma unroll
        for (int j = 0; j < 4; j++) acc[i][j] = 0.f;
#pragma unroll 4
    for (int c = 0; c < 64; c++) {
        float a[4], w[4];
#pragma unroll
        for (int i = 0; i < 4; i++) a[i] = sMat[(ty * 4 + i) * 64 + c];
#pragma unroll
        for (int j = 0; j < 4; j++) w[j] = sRw[(tx * 4 + j) * 64 + c];
#pragma unroll
        for (int i = 0; i < 4; i++)
#pragma unroll
            for (int j = 0; j < 4; j++) acc[i][j] += a[i] * w[j];
    }
    if (tid < 64) {
        const float* vsump = g_vsum + ((size_t)br * NB + b) * 64;
        float s = 0.f;
        for (int c = 0; c < 64; c++) s += sRw[tid * 64 + c] * vsump[c];
        g_rv[((size_t)br * NB + b) * 64 + tid] = s;
        g_ksumE[((size_t)br * NB + b) * 64 + tid] =
            g_ksum[((size_t)br * NB + b) * 64 + tid] + 1e-6f;
    }
    __syncthreads();
#pragma unroll
    for (int i = 0; i < 4; i++)
#pragma unroll
        for (int j = 0; j < 4; j++)
            sMat[(tx * 4 + j) * 64 + (ty * 4 + i)] = acc[i][j];
    __syncthreads();
    uint32_t* dst = g_RMfrag + (size_t)(br * 8 + b) * 4096;
    for (int t = tid; t < 4096; t += 256) {
        int half = t >> 11;
        int lane = (t >> 4) & 31;
        int ntj = t & 15;
        int nt = ntj >> 1, j = ntj & 1;
        int kc = (t >> 9) & 3;
        int o = nt * 8 + (lane >> 2);
        int m0 = kc * 16 + (lane & 3) * 2 + j * 8;
        float w0 = sMat[o * 64 + m0];
        float w1 = sMat[o * 64 + m0 + 1];
        dst[t] = packbf_hi_lo(w0, w1, half);
    }
}

// -------------------- pass 2: ldmatrix Q proj + register-resident RM*Qn -----------
#define P2_SMEM 36864

__global__ void __launch_bounds__(256, 2) pass2_kernel(
    const float* __restrict__ x1, const float* __restrict__ x2,
    const float* __restrict__ qb1, const float* __restrict__ rb1,
    const float* __restrict__ qb2, const float* __restrict__ rb2)
{
    extern __shared__ __align__(16) char dsmc2[];
    const uint32_t sbase = smem_u32(dsmc2);

    const int tid = threadIdx.x;
    const int lane = tid & 31, wt = tid >> 5;
    const int g = lane >> 2, tg = lane & 3;
    const int b = blockIdx.y, br = blockIdx.z;
    const int p0 = blockIdx.x * 128;
    const float* xb = (br ? x2 : x1) + (size_t)b * 64 * NPIX;
    const float* qb = br ? qb2 : qb1;
    const float* rb = br ? rb2 : rb1;
    const float* ksE = g_ksumE + ((size_t)br * NB + b) * 64;
    const float* rvp = g_rv + ((size_t)br * NB + b) * 64;

    for (int i = tid; i < 2048; i += 256) {
        int c = i >> 5, chunk = i & 31;
        float4 xv = *(const float4*)&xb[(size_t)c * NPIX + p0 + chunk * 4];
        uint32_t h0, l0, h1, l1;
        splitbf(xv.x, xv.y, h0, l0);
        splitbf(xv.z, xv.w, h1, l1);
        *(uint2*)(dsmc2 + c * 272 + chunk * 8) = make_uint2(h0, h1);
        *(uint2*)(dsmc2 + 17408 + c * 272 + chunk * 8) = make_uint2(l0, l1);
    }
    __syncthreads();

    const uint32_t aHa = sbase + ((((lane >> 4) & 1) * 8 + (lane & 7)) * 272)
                               + ((wt * 16 + ((lane >> 3) & 1) * 8) * 2);
    const uint32_t aLa = aHa + 17408;

    // ---- phase A: Q = Wq*x + qb ----
    float acc[8][4];
#pragma unroll
    for (int nt = 0; nt < 8; nt++)
#pragma unroll
        for (int k = 0; k < 4; k++) acc[nt][k] = 0.f;

#pragma unroll
    for (int kc = 0; kc < 4; kc++) {
        const uint4* WH = (const uint4*)&g_QKVfrag[((br * 2 + 0) * 4 + kc) * 512 + lane * 16];
        const uint4* WL = (const uint4*)&g_QKVfrag[((br * 2 + 1) * 4 + kc) * 512 + lane * 16];
        uint4 bh[4], bl[4];
#pragma unroll
        for (int q = 0; q < 4; q++) { bh[q] = __ldg(&WH[q]); bl[q] = __ldg(&WL[q]); }
        uint32_t ah0, ah1, ah2, ah3, al0, al1, al2, al3;
        ldsm_x4_trans(ah0, ah1, ah2, ah3, aHa + kc * 4352);
        ldsm_x4_trans(al0, al1, al2, al3, aLa + kc * 4352);
#pragma unroll
        for (int nt = 0; nt < 8; nt++) {
            uint32_t b0h = (nt & 1) ? bh[nt >> 1].z : bh[nt >> 1].x;
            uint32_t b1h = (nt & 1) ? bh[nt >> 1].w : bh[nt >> 1].y;
            uint32_t b0l = (nt & 1) ? bl[nt >> 1].z : bl[nt >> 1].x;
            uint32_t b1l = (nt & 1) ? bl[nt >> 1].w : bl[nt >> 1].y;
            mma_bf16(acc[nt], ah0, ah1, ah2, ah3, b0h, b1h);
            mma_bf16(acc[nt], ah0, ah1, ah2, ah3, b0l, b1l);
            mma_bf16(acc[nt], al0, al1, al2, al3, b0h, b1h);
        }
    }
    __syncthreads();   // X dead; smem free for staging

    // add qb
    float kse[16];
#pragma unroll
    for (int nt = 0; nt < 8; nt++) {
        float q0 = __ldg(&qb[nt * 8 + tg * 2 + 0]);
        float q1 = __ldg(&qb[nt * 8 + tg * 2 + 1]);
        kse[nt * 2 + 0] = __ldg(&ksE[nt * 8 + tg * 2 + 0]);
        kse[nt * 2 + 1] = __ldg(&ksE[nt * 8 + tg * 2 + 1]);
        acc[nt][0] += q0; acc[nt][1] += q1;
        acc[nt][2] += q0; acc[nt][3] += q1;
    }

    // per-px inv + den via quad shfl
    float invv[2], denn[2];
#pragma unroll
    for (int h = 0; h < 2; h++) {
        float s = 0.f, d = 0.f;
#pragma unroll
        for (int nt = 0; nt < 8; nt++) {
            float a = acc[nt][h * 2], c = acc[nt][h * 2 + 1];
            s = fmaf(a, a, s); s = fmaf(c, c, s);
            d = fmaf(a, kse[nt * 2], d); d = fmaf(c, kse[nt * 2 + 1], d);
        }
        s += __shfl_xor_sync(0xffffffffu, s, 1);
        s += __shfl_xor_sync(0xffffffffu, s, 2);
        d += __shfl_xor_sync(0xffffffffu, d, 1);
        d += __shfl_xor_sync(0xffffffffu, d, 2);
        float inv = rsqrtf(s);
        invv[h] = inv;
        denn[h] = 1.f / (65536.f + inv * d);
    }

    // ---- phase B from registers: out = RM * (Q * inv) ----
    float acc2[8][4];
#pragma unroll
    for (int nt = 0; nt < 8; nt++)
#pragma unroll
        for (int k = 0; k < 4; k++) acc2[nt][k] = 0.f;

    const uint32_t* rmbase = g_RMfrag + (size_t)(br * 8 + b) * 4096;
#pragma unroll
    for (int kc = 0; kc < 4; kc++) {
        const uint4* RH = (const uint4*)&rmbase[(0 * 4 + kc) * 512 + lane * 16];
        const uint4* RL = (const uint4*)&rmbase[(1 * 4 + kc) * 512 + lane * 16];
        uint4 bh[4], bl[4];
#pragma unroll
        for (int q = 0; q < 4; q++) { bh[q] = __ldg(&RH[q]); bl[q] = __ldg(&RL[q]); }
        float i0 = invv[0], i1 = invv[1];
        uint32_t ah0, ah1, ah2, ah3, al0, al1, al2, al3;
        splitbf(acc[2 * kc][0] * i0, acc[2 * kc][1] * i0, ah0, al0);
        splitbf(acc[2 * kc][2] * i1, acc[2 * kc][3] * i1, ah1, al1);
        splitbf(acc[2 * kc + 1][0] * i0, acc[2 * kc + 1][1] * i0, ah2, al2);
        splitbf(acc[2 * kc + 1][2] * i1, acc[2 * kc + 1][3] * i1, ah3, al3);
#pragma unroll
        for (int nt = 0; nt < 8; nt++) {
            uint32_t b0h = (nt & 1) ? bh[nt >> 1].z : bh[nt >> 1].x;
            uint32_t b1h = (nt & 1) ? bh[nt >> 1].w : bh[nt >> 1].y;
            uint32_t b0l = (nt & 1) ? bl[nt >> 1].z : bl[nt >> 1].x;
            uint32_t b1l = (nt & 1) ? bl[nt >> 1].w : bl[nt >> 1].y;
            mma_bf16(acc2[nt], ah0, ah1, ah2, ah3, b0h, b1h);
            mma_bf16(acc2[nt], ah0, ah1, ah2, ah3, b0l, b1l);
            mma_bf16(acc2[nt], al0, al1, al2, al3, b0h, b1h);
        }
    }

    // epilogue -> bf16 hi/lo planes [px][72 bf16 stride] in smem, packed STS.32
#pragma unroll
    for (int nt = 0; nt < 8; nt++) {
        int o = nt * 8 + tg * 2;
        float rv0 = __ldg(&rvp[o]), rv1 = __ldg(&rvp[o + 1]);
        float rb0 = __ldg(&rb[o]),  rb1 = __ldg(&rb[o + 1]);
#pragma unroll
        for (int h = 0; h < 2; h++) {
            int r = wt * 16 + g + h * 8;
            float den = denn[h];
            float v0 = den * (rv0 + acc2[nt][h * 2 + 0]) + rb0;
            float v1 = den * (rv1 + acc2[nt][h * 2 + 1]) + rb1;
            uint32_t ph, pl;
            splitbf(v0, v1, ph, pl);
            *(uint32_t*)(dsmc2 + r * 144 + o * 2) = ph;
            *(uint32_t*)(dsmc2 + 18432 + r * 144 + o * 2) = pl;
        }
    }
    __syncthreads();

    for (int u = tid; u < 2048; u += 256) {
        int plane = u >> 10;
        int rest = u & 1023;
        int px = rest >> 3, q = rest & 7;
        uint4 val = *(const uint4*)(dsmc2 + plane * 18432 + px * 144 + q * 16);
        __nv_bfloat16* dst = plane ? g_lo : g_hi;
        *(uint4*)&dst[((size_t)(b * NPIX + p0 + px)) * 128 + br * 64 + q * 8] = val;
    }
}

// -------------------- conv: ldmatrix bf16-split implicit GEMM --------------------
#define STRIP_STRIDE 272
#define STRIP_BYTES (130 * STRIP_STRIDE)
#define CONV_SMEM (2 * STRIP_BYTES)

__global__ void __launch_bounds__(256, 2) conv_kernel(const float* __restrict__ cbias,
                                                      float* __restrict__ out)
{
    extern __shared__ __align__(16) char dsmc[];
    char* sHi = dsmc;
    char* sLo = dsmc + STRIP_BYTES;
    float* sOut = (float*)dsmc;
    const uint32_t sHiB = smem_u32(dsmc);

    const int tid = threadIdx.x;
    const int lane = tid & 31, wt = tid >> 5;
    const int x0 = blockIdx.x * 128, y = blockIdx.y, b = blockIdx.z;

    float acc[8][4];
#pragma unroll
    for (int nt = 0; nt < 8; nt++)
#pragma unroll
        for (int j = 0; j < 4; j++) acc[nt][j] = 0.f;

    const int g = lane >> 2, tg = lane & 3;
    const uint32_t aBase = (uint32_t)((wt * 16 + ((lane >> 3) & 1) * 8 + (lane & 7)) * STRIP_STRIDE
                                      + ((lane >> 4) & 1) * 16);

    for (int ky = 0; ky < 3; ky++) {
        int yy = y + ky - 1;
        bool yok = (yy >= 0 && yy < IMG_H);
        __syncthreads();
        if (yok) {
            size_t rowbase = ((size_t)b * NPIX + (size_t)yy * IMG_W) * 128;
            for (int i = tid; i < 130 * 16; i += 256) {
                int row = i >> 4, ch = i & 15;
                int px = x0 + row - 1;
                uint4 vh = make_uint4(0u, 0u, 0u, 0u);
                uint4 vl = make_uint4(0u, 0u, 0u, 0u);
                if (px >= 0 && px < IMG_W) {
                    size_t gi = rowbase + (size_t)px * 128 + ch * 8;
                    vh = *(const uint4*)&g_hi[gi];
                    vl = *(const uint4*)&g_lo[gi];
                }
                *(uint4*)(sHi + row * STRIP_STRIDE + ch * 16) = vh;
                *(uint4*)(sLo + row * STRIP_STRIDE + ch * 16) = vl;
            }
        }
        __syncthreads();
        if (!yok) continue;

#pragma unroll 1
        for (int kx = 0; kx < 3; kx++) {
#pragma unroll
            for (int cc8 = 0; cc8 < 8; cc8++) {
                int kc = kx * 8 + cc8;
                const uint4* bfH = (const uint4*)(g_Bfrag + (((ky * 24 + kc) * 2 + 0) * 32 + lane) * 16);
                const uint4* bfL = (const uint4*)(g_Bfrag + (((ky * 24 + kc) * 2 + 1) * 32 + lane) * 16);
                uint4 bh[4], bl[4];
#pragma unroll
                for (int q = 0; q < 4; q++) { bh[q] = __ldg(&bfH[q]); bl[q] = __ldg(&bfL[q]); }
                uint32_t ad = sHiB + aBase + kx * STRIP_STRIDE + cc8 * 32;
                uint32_t ah0, ah1, ah2, ah3, al0, al1, al2, al3;
                ldsm_x4(ah0, ah1, ah2, ah3, ad);
                ldsm_x4(al0, al1, al2, al3, ad + STRIP_BYTES);

#pragma unroll
                for (int nt = 0; nt < 8; nt++) {
                    uint32_t bh0 = (nt & 1) ? bh[nt >> 1].z : bh[nt >> 1].x;
                    uint32_t bh1 = (nt & 1) ? bh[nt >> 1].w : bh[nt >> 1].y;
                    uint32_t bl0 = (nt & 1) ? bl[nt >> 1].z : bl[nt >> 1].x;
                    uint32_t bl1 = (nt & 1) ? bl[nt >> 1].w : bl[nt >> 1].y;
                    mma_bf16(acc[nt], ah0, ah1, ah2, ah3, bh0, bh1);
                    mma_bf16(acc[nt], ah0, ah1, ah2, ah3, bl0, bl1);
                    mma_bf16(acc[nt], al0, al1, al2, al3, bh0, bh1);
                }
            }
        }
    }

    __syncthreads();
#pragma unroll
    for (int nt = 0; nt < 8; nt++)
#pragma unroll
        for (int h = 0; h < 2; h++)
#pragma unroll
            for (int j = 0; j < 2; j++) {
                int o = nt * 8 + tg * 2 + j;
                int px = wt * 16 + g + h * 8;
                sOut[o * 132 + px] = acc[nt][h * 2 + j];
            }
    __syncthreads();
    for (int i = tid; i < 64 * 32; i += 256) {
        int o = i >> 5, ch = i & 31;
        float4 v = *(const float4*)&sOut[o * 132 + ch * 4];
        float bias = __ldg(&cbias[o]);
        v.x += bias; v.y += bias; v.z += bias; v.w += bias;
        *(float4*)&out[((size_t)(b * 64 + o)) * NPIX + (size_t)y * IMG_W + x0 + ch * 4] = v;
    }
}

// -------------------- launch --------------------
extern "C" void kernel_launch(void* const* d_in, const int* in_sizes, int n_in,
                              void* d_out, int out_size)
{
    (void)in_sizes; (void)n_in; (void)out_size;
    const float* t1  = (const float*)d_in[0];
    const float* t2  = (const float*)d_in[1];
    const float* q1w = (const float*)d_in[2];  const float* q1b = (const float*)d_in[3];
    const float* k1w = (const float*)d_in[4];  const float* k1b = (const float*)d_in[5];
    const float* v1w = (const float*)d_in[6];  const float* v1b = (const float*)d_in[7];
    const float* r1w = (const float*)d_in[8];  const float* r1b = (const float*)d_in[9];
    const float* q2w = (const float*)d_in[10]; const float* q2b = (const float*)d_in[11];
    const float* k2w = (const float*)d_in[12]; const float* k2b = (const float*)d_in[13];
    const float* v2w = (const float*)d_in[14]; const float* v2b = (const float*)d_in[15];
    const float* r2w = (const float*)d_in[16]; const float* r2b = (const float*)d_in[17];
    const float* cw  = (const float*)d_in[18]; const float* cb  = (const float*)d_in[19];

    cudaFuncSetAttribute(pass1_kernel, cudaFuncAttributeMaxDynamicSharedMemorySize, P1_SMEM);
    cudaFuncSetAttribute(pass2_kernel, cudaFuncAttributeMaxDynamicSharedMemorySize, P2_SMEM);
    cudaFuncSetAttribute(conv_kernel, cudaFuncAttributeMaxDynamicSharedMemorySize, CONV_SMEM);

    prep_zero_kernel<<<256, 256>>>();                                 // launch 0
    prep_conv_kernel<<<288, 256>>>(cw);                               // launch 1
    prep_qkv_kernel<<<96, 256>>>(q1w, k1w, v1w, q2w, k2w, v2w);       // launch 2
    dim3 g1(512, 8, 2);
    pass1_kernel<<<g1, 256, P1_SMEM>>>(t1, t2, k1b, v1b, k2b, v2b);   // launch 3 (ncu)
    dim3 gm(8, 2);
    mid_kernel<<<gm, 256>>>(r1w, r2w);                                // launch 4
    pass2_kernel<<<g1, 256, P2_SMEM>>>(t1, t2, q1b, r1b, q2b, r2b);   // launch 5
    dim3 gc(2, 256, 8);
    conv_kernel<<<gc, 256, CONV_SMEM>>>(cb, (float*)d_out);           // launch 6
}

// round 15
// speedup vs baseline: 1.3635x; 1.3303x over previous
#include <cuda_runtime.h>
#include <cuda_bf16.h>
#include <cstdint>

#define NPIX 65536
#define IMG_H 256
#define IMG_W 256
#define NB 8

// ---- device scratch ----
__device__ __nv_bfloat16 g_hi[NB * NPIX * 128];   // NHWC [b][y][x][ci], hi plane
__device__ __nv_bfloat16 g_lo[NB * NPIX * 128];   // lo plane
__device__ uint32_t g_Bfrag[3 * 24 * 2 * 32 * 16];  // conv weight mma frags
__device__ uint32_t g_QKVfrag[3 * 2 * 2 * 4 * 32 * 16]; // [kind q/k/v][br][half][kc][lane][ntj]
__device__ uint32_t g_RMfrag[16 * 2 * 4 * 32 * 16]; // [(br*8+b)][half][kc][lane][ntj]
__device__ float g_mat[2 * NB * 64 * 64];
__device__ float g_ksum[2 * NB * 64];
__device__ float g_vsum[2 * NB * 64];
__device__ float g_rv[2 * NB * 64];
__device__ float g_ksumE[2 * NB * 64];

// ---- mma.sync bf16 helper (m16n8k16, f32 accum) ----
__device__ __forceinline__ void mma_bf16(float* d,
                                         uint32_t a0, uint32_t a1, uint32_t a2, uint32_t a3,
                                         uint32_t b0, uint32_t b1) {
    asm volatile(
        "mma.sync.aligned.m16n8k16.row.col.f32.bf16.bf16.f32 "
        "{%0,%1,%2,%3}, {%4,%5,%6,%7}, {%8,%9}, {%0,%1,%2,%3};"
        : "+f"(d[0]), "+f"(d[1]), "+f"(d[2]), "+f"(d[3])
        : "r"(a0), "r"(a1), "r"(a2), "r"(a3), "r"(b0), "r"(b1));
}

__device__ __forceinline__ void ldsm_x4(uint32_t& r0, uint32_t& r1, uint32_t& r2, uint32_t& r3,
                                        uint32_t addr) {
    asm volatile("ldmatrix.sync.aligned.m8n8.x4.shared.b16 {%0,%1,%2,%3}, [%4];"
                 : "=r"(r0), "=r"(r1), "=r"(r2), "=r"(r3) : "r"(addr));
}
__device__ __forceinline__ void ldsm_x4_trans(uint32_t& r0, uint32_t& r1, uint32_t& r2, uint32_t& r3,
                                              uint32_t addr) {
    asm volatile("ldmatrix.sync.aligned.m8n8.x4.trans.shared.b16 {%0,%1,%2,%3}, [%4];"
                 : "=r"(r0), "=r"(r1), "=r"(r2), "=r"(r3) : "r"(addr));
}

__device__ __forceinline__ uint32_t smem_u32(const void* p) {
    uint32_t a;
    asm("{ .reg .u64 t; cvta.to.shared.u64 t, %1; cvt.u32.u64 %0, t; }" : "=r"(a) : "l"(p));
    return a;
}

__device__ __forceinline__ void splitbf(float a, float b, uint32_t& h, uint32_t& l) {
    __nv_bfloat16 ha = __float2bfloat16(a), hb = __float2bfloat16(b);
    __nv_bfloat162 hh; hh.x = ha; hh.y = hb;
    h = *(uint32_t*)&hh;
    __nv_bfloat162 ll = __floats2bfloat162_rn(a - __bfloat162float(ha),
                                              b - __bfloat162float(hb));
    l = *(uint32_t*)&ll;
}
__device__ __forceinline__ uint32_t packbf_hi_lo(float a, float b, int half) {
    if (half == 0) {
        __nv_bfloat162 hh; hh.x = __float2bfloat16(a); hh.y = __float2bfloat16(b);
        return *(uint32_t*)&hh;
    }
    __nv_bfloat16 ha = __float2bfloat16(a), hb = __float2bfloat16(b);
    __nv_bfloat162 ll = __floats2bfloat162_rn(a - __bfloat162float(ha),
                                              b - __bfloat162float(hb));
    return *(uint32_t*)&ll;
}

// -------------------- prep, split into 3 launches (pass1 at capture idx 3) ----
__global__ void __launch_bounds__(256) prep_zero_kernel() {
    int idx = blockIdx.x * 256 + threadIdx.x;   // grid 256 -> 65536
    g_mat[idx] = 0.f;
    if (idx < 2 * NB * 64) { g_ksum[idx] = 0.f; g_vsum[idx] = 0.f; }
}

__global__ void __launch_bounds__(256) prep_conv_kernel(const float* __restrict__ cw) {
    int i = blockIdx.x * 256 + threadIdx.x;     // grid 288 -> 73728
    if (i >= 73728) return;
    int ky = i / 24576;
    int rem = i % 24576;
    int kc = rem / 1024;
    int rem2 = rem % 1024;
    int half = rem2 / 512;
    int rem3 = rem2 % 512;
    int lane = rem3 / 16;
    int r4 = rem3 % 16;
    int nt = r4 >> 1, j = r4 & 1;
    int kx = kc >> 3, cc8 = kc & 7;
    int n = nt * 8 + (lane >> 2);
    int ci0 = cc8 * 16 + (lane & 3) * 2 + j * 8;
    float w0 = cw[((n * 128 + ci0) * 3 + ky) * 3 + kx];
    float w1 = cw[((n * 128 + ci0 + 1) * 3 + ky) * 3 + kx];
    g_Bfrag[i] = packbf_hi_lo(w0, w1, half);
}

__global__ void __launch_bounds__(256) prep_qkv_kernel(
    const float* __restrict__ q1w, const float* __restrict__ k1w, const float* __restrict__ v1w,
    const float* __restrict__ q2w, const float* __restrict__ k2w, const float* __restrict__ v2w)
{
    int t = blockIdx.x;                          // grid 96
    int kind = t / 32;                           // 0=q, 1=k, 2=v
    int i = (t % 32) * 256 + threadIdx.x;        // 0..8191
    int br = i >> 12;
    int r = i & 4095;
    int half = r >> 11;
    int kc = (r >> 9) & 3;
    int lane = (r >> 4) & 31;
    int ntj = r & 15;
    int nt = ntj >> 1, j = ntj & 1;
    int o = nt * 8 + (lane >> 2);
    int c0 = kc * 16 + (lane & 3) * 2 + j * 8;
    const float* w;
    if (kind == 0) w = br ? q2w : q1w;
    else if (kind == 1) w = br ? k2w : k1w;
    else w = br ? v2w : v1w;
    float w0 = w[o * 64 + c0];
    float w1 = w[o * 64 + c0 + 1];
    g_QKVfrag[kind * 8192 + i] = packbf_hi_lo(w0, w1, half);
}

// -------------------- pass 1: ldmatrix K,V proj + mma stats --------------------
// grid (512, 8, 2), 256 thr = 8 warps, 2 CTAs/SM. Tile: 128 px.
#define P1_SMEM 102400

__global__ void __launch_bounds__(256, 2) pass1_kernel(
    const float* __restrict__ x1, const float* __restrict__ x2,
    const float* __restrict__ kb1, const float* __restrict__ vb1,
    const float* __restrict__ kb2, const float* __restrict__ vb2)
{
    extern __shared__ __align__(16) char dsm1c[];
    float* Kp = (float*)(dsm1c + 34816);
    float* Vp = (float*)(dsm1c + 68608);
    const uint32_t sbase = smem_u32(dsm1c);

    const int tid = threadIdx.x;
    const int lane = tid & 31, wt = tid >> 5;
    const int g = lane >> 2, tg = lane & 3;
    const int b = blockIdx.y, br = blockIdx.z;
    const int p0 = blockIdx.x * 128;
    const float* xb = (br ? x2 : x1) + (size_t)b * 64 * NPIX;
    const float* kb = br ? kb2 : kb1;
    const float* vb = br ? vb2 : vb1;

    for (int i = tid; i < 2048; i += 256) {
        int c = i >> 5, chunk = i & 31;
        float4 xv = *(const float4*)&xb[(size_t)c * NPIX + p0 + chunk * 4];
        uint32_t h0, l0, h1, l1;
        splitbf(xv.x, xv.y, h0, l0);
        splitbf(xv.z, xv.w, h1, l1);
        *(uint2*)(dsm1c + c * 272 + chunk * 8) = make_uint2(h0, h1);
        *(uint2*)(dsm1c + 17408 + c * 272 + chunk * 8) = make_uint2(l0, l1);
    }
    __syncthreads();

    const uint32_t aH = sbase + ((((lane >> 4) & 1) * 8 + (lane & 7)) * 272)
                              + ((wt * 16 + ((lane >> 3) & 1) * 8) * 2);
    const uint32_t aL = aH + 17408;

#pragma unroll 1
    for (int kv = 0; kv < 2; kv++) {
        const uint32_t* wf = g_QKVfrag + (kv + 1) * 8192 + br * 4096;
        const float* bias = kv ? vb : kb;
        float* park = kv ? Vp : Kp;

        float acc[8][4];
#pragma unroll
        for (int nt = 0; nt < 8; nt++)
#pragma unroll
            for (int k = 0; k < 4; k++) acc[nt][k] = 0.f;

#pragma unroll
        for (int kc = 0; kc < 4; kc++) {
            const uint4* WH = (const uint4*)&wf[(0 * 4 + kc) * 512 + lane * 16];
            const uint4* WL = (const uint4*)&wf[(1 * 4 + kc) * 512 + lane * 16];
            uint4 bh[4], bl[4];
#pragma unroll
            for (int q = 0; q < 4; q++) { bh[q] = __ldg(&WH[q]); bl[q] = __ldg(&WL[q]); }
            uint32_t ah0, ah1, ah2, ah3, al0, al1, al2, al3;
            ldsm_x4_trans(ah0, ah1, ah2, ah3, aH + kc * 4352);
            ldsm_x4_trans(al0, al1, al2, al3, aL + kc * 4352);
#pragma unroll
            for (int nt = 0; nt < 8; nt++) {
                uint32_t b0h = (nt & 1) ? bh[nt >> 1].z : bh[nt >> 1].x;
                uint32_t b1h = (nt & 1) ? bh[nt >> 1].w : bh[nt >> 1].y;
                uint32_t b0l = (nt & 1) ? bl[nt >> 1].z : bl[nt >> 1].x;
                uint32_t b1l = (nt & 1) ? bl[nt >> 1].w : bl[nt >> 1].y;
                mma_bf16(acc[nt], ah0, ah1, ah2, ah3, b0h, b1h);
                mma_bf16(acc[nt], ah0, ah1, ah2, ah3, b0l, b1l);
                mma_bf16(acc[nt], al0, al1, al2, al3, b0h, b1h);
            }
        }

#pragma unroll
        for (int nt = 0; nt < 8; nt++) {
            float b0 = __ldg(&bias[nt * 8 + tg * 2 + 0]);
            float b1 = __ldg(&bias[nt * 8 + tg * 2 + 1]);
            acc[nt][0] += b0; acc[nt][1] += b1;
            acc[nt][2] += b0; acc[nt][3] += b1;
        }

        if (kv == 0) {
#pragma unroll
            for (int h = 0; h < 2; h++) {
                float s = 0.f;
#pragma unroll
                for (int nt = 0; nt < 8; nt++) {
                    float a = acc[nt][h * 2], c = acc[nt][h * 2 + 1];
                    s = fmaf(a, a, s); s = fmaf(c, c, s);
                }
                s += __shfl_xor_sync(0xffffffffu, s, 1);
                s += __shfl_xor_sync(0xffffffffu, s, 2);
                float inv = rsqrtf(s);
                int px = wt * 16 + g + h * 8;
#pragma unroll
                for (int nt = 0; nt < 8; nt++)
#pragma unroll
                    for (int j = 0; j < 2; j++)
                        park[(nt * 8 + tg * 2 + j) * 132 + px] = acc[nt][h * 2 + j] * inv;
            }
        } else {
#pragma unroll
            for (int h = 0; h < 2; h++) {
                int px = wt * 16 + g + h * 8;
#pragma unroll
                for (int nt = 0; nt < 8; nt++)
#pragma unroll
                    for (int j = 0; j < 2; j++)
                        park[(nt * 8 + tg * 2 + j) * 132 + px] = acc[nt][h * 2 + j];
            }
        }
    }
    __syncthreads();

    const int mt4 = wt >> 1;
    const int nh = wt & 1;
    float acc2[4][4];
#pragma unroll
    for (int nt = 0; nt < 4; nt++)
#pragma unroll
        for (int k = 0; k < 4; k++) acc2[nt][k] = 0.f;
    float ksg = 0.f, ksg8 = 0.f;
    float vs[4] = {0.f, 0.f, 0.f, 0.f};

#pragma unroll 4
    for (int kc = 0; kc < 8; kc++) {
        int px0 = kc * 16 + tg * 2;
        int m0 = mt4 * 16 + g;
        float2 k0 = *(const float2*)&Kp[m0 * 132 + px0];
        float2 k8 = *(const float2*)&Kp[m0 * 132 + px0 + 8];
        float2 k10 = *(const float2*)&Kp[(m0 + 8) * 132 + px0];
        float2 k18 = *(const float2*)&Kp[(m0 + 8) * 132 + px0 + 8];
        uint32_t a0h, a0l, a1h, a1l, a2h, a2l, a3h, a3l;
        splitbf(k0.x, k0.y, a0h, a0l);
        splitbf(k10.x, k10.y, a1h, a1l);
        splitbf(k8.x, k8.y, a2h, a2l);
        splitbf(k18.x, k18.y, a3h, a3l);
        if (nh == 0) {
            ksg += k0.x + k0.y + k8.x + k8.y;
            ksg8 += k10.x + k10.y + k18.x + k18.y;
        }
#pragma unroll
        for (int nt = 0; nt < 4; nt++) {
            int n = (nh * 4 + nt) * 8 + g;
            float2 b0 = *(const float2*)&Vp[n * 132 + px0];
            float2 b8 = *(const float2*)&Vp[n * 132 + px0 + 8];
            if (mt4 == 0) vs[nt] += b0.x + b0.y + b8.x + b8.y;
            uint32_t bh0, bl0, bh1, bl1;
            splitbf(b0.x, b0.y, bh0, bl0);
            splitbf(b8.x, b8.y, bh1, bl1);
            mma_bf16(acc2[nt], a0h, a1h, a2h, a3h, bh0, bh1);
            mma_bf16(acc2[nt], a0h, a1h, a2h, a3h, bl0, bl1);
            mma_bf16(acc2[nt], a0l, a1l, a2l, a3l, bh0, bh1);
        }
    }

    float* mat = g_mat + ((size_t)br * NB + b) * 4096;
#pragma unroll
    for (int nt = 0; nt < 4; nt++) {
#pragma unroll
        for (int k = 0; k < 4; k++) {
            int m = mt4 * 16 + g + ((k >= 2) ? 8 : 0);
            int n = (nh * 4 + nt) * 8 + tg * 2 + (k & 1);
            atomicAdd(&mat[m * 64 + n], acc2[nt][k]);
        }
    }
    if (nh == 0) {
        ksg += __shfl_xor_sync(0xffffffffu, ksg, 1);
        ksg += __shfl_xor_sync(0xffffffffu, ksg, 2);
        ksg8 += __shfl_xor_sync(0xffffffffu, ksg8, 1);
        ksg8 += __shfl_xor_sync(0xffffffffu, ksg8, 2);
        if (tg == 0) {
            float* kp = g_ksum + ((size_t)br * NB + b) * 64;
            atomicAdd(&kp[mt4 * 16 + g], ksg);
            atomicAdd(&kp[mt4 * 16 + g + 8], ksg8);
        }
    }
    if (mt4 == 0) {
#pragma unroll
        for (int nt = 0; nt < 4; nt++) {
            float v = vs[nt];
            v += __shfl_xor_sync(0xffffffffu, v, 1);
            v += __shfl_xor_sync(0xffffffffu, v, 2);
            if (tg == 0)
                atomicAdd(&g_vsum[((size_t)br * NB + b) * 64 + (nh * 4 + nt) * 8 + g], v);
        }
    }
}

// -------------------- mid: RM frags, rv, ksumE --------------------
__global__ void __launch_bounds__(256) mid_kernel(const float* __restrict__ rw1,
                                                  const float* __restrict__ rw2)
{
    __shared__ float sMat[4096];
    __shared__ float sRw[4096];
    const int tid = threadIdx.x;
    const int b = blockIdx.x, br = blockIdx.y;
    const float* rw = br ? rw2 : rw1;
    const float* mat = g_mat + ((size_t)br * NB + b) * 4096;
#pragma unroll
    for (int r = 0; r < 16; r++) {
        int i = tid + r * 256;
        sMat[i] = mat[i];
        sRw[i] = rw[i];
    }
    __syncthreads();
    const int ty = tid >> 4, tx = tid & 15;
    float acc[4][4];
#pragma unroll
    for (int i = 0; i < 4; i++)
#pragma unroll
        for (int j = 0; j < 4; j++) acc[i][j] = 0.f;
#pragma unroll 4
    for (int c = 0; c < 64; c++) {
        float a[4], w[4];
#pragma unroll
        for (int i = 0; i < 4; i++) a[i] = sMat[(ty * 4 + i) * 64 + c];
#pragma unroll
        for (int j = 0; j < 4; j++) w[j] = sRw[(tx * 4 + j) * 64 + c];
#pragma unroll
        for (int i = 0; i < 4; i++)
#pragma unroll
            for (int j = 0; j < 4; j++) acc[i][j] += a[i] * w[j];
    }
    if (tid < 64) {
        const float* vsump = g_vsum + ((size_t)br * NB + b) * 64;
        float s = 0.f;
        for (int c = 0; c < 64; c++) s += sRw[tid * 64 + c] * vsump[c];
        g_rv[((size_t)br * NB + b) * 64 + tid] = s;
        g_ksumE[((size_t)br * NB + b) * 64 + tid] =
            g_ksum[((size_t)br * NB + b) * 64 + tid] + 1e-6f;
    }
    __syncthreads();
#pragma unroll
    for (int i = 0; i < 4; i++)
#pragma unroll
        for (int j = 0; j < 4; j++)
            sMat[(tx * 4 + j) * 64 + (ty * 4 + i)] = acc[i][j];
    __syncthreads();
    uint32_t* dst = g_RMfrag + (size_t)(br * 8 + b) * 4096;
    for (int t = tid; t < 4096; t += 256) {
        int half = t >> 11;
        int lane = (t >> 4) & 31;
        int ntj = t & 15;
        int nt = ntj >> 1, j = ntj & 1;
        int kc = (t >> 9) & 3;
        int o = nt * 8 + (lane >> 2);
        int m0 = kc * 16 + (lane & 3) * 2 + j * 8;
        float w0 = sMat[o * 64 + m0];
        float w1 = sMat[o * 64 + m0 + 1];
        dst[t] = packbf_hi_lo(w0, w1, half);
    }
}

// -------------------- pass 2: ldmatrix Q proj + register-resident RM*Qn -----------
#define P2_SMEM 36864

__global__ void __launch_bounds__(256, 2) pass2_kernel(
    const float* __restrict__ x1, const float* __restrict__ x2,
    const float* __restrict__ qb1, const float* __restrict__ rb1,
    const float* __restrict__ qb2, const float* __restrict__ rb2)
{
    extern __shared__ __align__(16) char dsmc2[];
    const uint32_t sbase = smem_u32(dsmc2);

    const int tid = threadIdx.x;
    const int lane = tid & 31, wt = tid >> 5;
    const int g = lane >> 2, tg = lane & 3;
    const int b = blockIdx.y, br = blockIdx.z;
    const int p0 = blockIdx.x * 128;
    const float* xb = (br ? x2 : x1) + (size_t)b * 64 * NPIX;
    const float* qb = br ? qb2 : qb1;
    const float* rb = br ? rb2 : rb1;
    const float* ksE = g_ksumE + ((size_t)br * NB + b) * 64;
    const float* rvp = g_rv + ((size_t)br * NB + b) * 64;

    for (int i = tid; i < 2048; i += 256) {
        int c = i >> 5, chunk = i & 31;
        float4 xv = *(const float4*)&xb[(size_t)c * NPIX + p0 + chunk * 4];
        uint32_t h0, l0, h1, l1;
        splitbf(xv.x, xv.y, h0, l0);
        splitbf(xv.z, xv.w, h1, l1);
        *(uint2*)(dsmc2 + c * 272 + chunk * 8) = make_uint2(h0, h1);
        *(uint2*)(dsmc2 + 17408 + c * 272 + chunk * 8) = make_uint2(l0, l1);
    }
    __syncthreads();

    const uint32_t aHa = sbase + ((((lane >> 4) & 1) * 8 + (lane & 7)) * 272)
                               + ((wt * 16 + ((lane >> 3) & 1) * 8) * 2);
    const uint32_t aLa = aHa + 17408;

    float acc[8][4];
#pragma unroll
    for (int nt = 0; nt < 8; nt++)
#pragma unroll
        for (int k = 0; k < 4; k++) acc[nt][k] = 0.f;

#pragma unroll
    for (int kc = 0; kc < 4; kc++) {
        const uint4* WH = (const uint4*)&g_QKVfrag[((br * 2 + 0) * 4 + kc) * 512 + lane * 16];
        const uint4* WL = (const uint4*)&g_QKVfrag[((br * 2 + 1) * 4 + kc) * 512 + lane * 16];
        uint4 bh[4], bl[4];
#pragma unroll
        for (int q = 0; q < 4; q++) { bh[q] = __ldg(&WH[q]); bl[q] = __ldg(&WL[q]); }
        uint32_t ah0, ah1, ah2, ah3, al0, al1, al2, al3;
        ldsm_x4_trans(ah0, ah1, ah2, ah3, aHa + kc * 4352);
        ldsm_x4_trans(al0, al1, al2, al3, aLa + kc * 4352);
#pragma unroll
        for (int nt = 0; nt < 8; nt++) {
            uint32_t b0h = (nt & 1) ? bh[nt >> 1].z : bh[nt >> 1].x;
            uint32_t b1h = (nt & 1) ? bh[nt >> 1].w : bh[nt >> 1].y;
            uint32_t b0l = (nt & 1) ? bl[nt >> 1].z : bl[nt >> 1].x;
            uint32_t b1l = (nt & 1) ? bl[nt >> 1].w : bl[nt >> 1].y;
            mma_bf16(acc[nt], ah0, ah1, ah2, ah3, b0h, b1h);
            mma_bf16(acc[nt], ah0, ah1, ah2, ah3, b0l, b1l);
            mma_bf16(acc[nt], al0, al1, al2, al3, b0h, b1h);
        }
    }
    __syncthreads();

    float kse[16];
#pragma unroll
    for (int nt = 0; nt < 8; nt++) {
        float q0 = __ldg(&qb[nt * 8 + tg * 2 + 0]);
        float q1 = __ldg(&qb[nt * 8 + tg * 2 + 1]);
        kse[nt * 2 + 0] = __ldg(&ksE[nt * 8 + tg * 2 + 0]);
        kse[nt * 2 + 1] = __ldg(&ksE[nt * 8 + tg * 2 + 1]);
        acc[nt][0] += q0; acc[nt][1] += q1;
        acc[nt][2] += q0; acc[nt][3] += q1;
    }

    float invv[2], denn[2];
#pragma unroll
    for (int h = 0; h < 2; h++) {
        float s = 0.f, d = 0.f;
#pragma unroll
        for (int nt = 0; nt < 8; nt++) {
            float a = acc[nt][h * 2], c = acc[nt][h * 2 + 1];
            s = fmaf(a, a, s); s = fmaf(c, c, s);
            d = fmaf(a, kse[nt * 2], d); d = fmaf(c, kse[nt * 2 + 1], d);
        }
        s += __shfl_xor_sync(0xffffffffu, s, 1);
        s += __shfl_xor_sync(0xffffffffu, s, 2);
        d += __shfl_xor_sync(0xffffffffu, d, 1);
        d += __shfl_xor_sync(0xffffffffu, d, 2);
        float inv = rsqrtf(s);
        invv[h] = inv;
        denn[h] = 1.f / (65536.f + inv * d);
    }

    float acc2[8][4];
#pragma unroll
    for (int nt = 0; nt < 8; nt++)
#pragma unroll
        for (int k = 0; k < 4; k++) acc2[nt][k] = 0.f;

    const uint32_t* rmbase = g_RMfrag + (size_t)(br * 8 + b) * 4096;
#pragma unroll
    for (int kc = 0; kc < 4; kc++) {
        const uint4* RH = (const uint4*)&rmbase[(0 * 4 + kc) * 512 + lane * 16];
        const uint4* RL = (const uint4*)&rmbase[(1 * 4 + kc) * 512 + lane * 16];
        uint4 bh[4], bl[4];
#pragma unroll
        for (int q = 0; q < 4; q++) { bh[q] = __ldg(&RH[q]); bl[q] = __ldg(&RL[q]); }
        float i0 = invv[0], i1 = invv[1];
        uint32_t ah0, ah1, ah2, ah3, al0, al1, al2, al3;
        splitbf(acc[2 * kc][0] * i0, acc[2 * kc][1] * i0, ah0, al0);
        splitbf(acc[2 * kc][2] * i1, acc[2 * kc][3] * i1, ah1, al1);
        splitbf(acc[2 * kc + 1][0] * i0, acc[2 * kc + 1][1] * i0, ah2, al2);
        splitbf(acc[2 * kc + 1][2] * i1, acc[2 * kc + 1][3] * i1, ah3, al3);
#pragma unroll
        for (int nt = 0; nt < 8; nt++) {
            uint32_t b0h = (nt & 1) ? bh[nt >> 1].z : bh[nt >> 1].x;
            uint32_t b1h = (nt & 1) ? bh[nt >> 1].w : bh[nt >> 1].y;
            uint32_t b0l = (nt & 1) ? bl[nt >> 1].z : bl[nt >> 1].x;
            uint32_t b1l = (nt & 1) ? bl[nt >> 1].w : bl[nt >> 1].y;
            mma_bf16(acc2[nt], ah0, ah1, ah2, ah3, b0h, b1h);
            mma_bf16(acc2[nt], ah0, ah1, ah2, ah3, b0l, b1l);
            mma_bf16(acc2[nt], al0, al1, al2, al3, b0h, b1h);
        }
    }

#pragma unroll
    for (int nt = 0; nt < 8; nt++) {
        int o = nt * 8 + tg * 2;
        float rv0 = __ldg(&rvp[o]), rv1 = __ldg(&rvp[o + 1]);
        float rb0 = __ldg(&rb[o]),  rb1 = __ldg(&rb[o + 1]);
#pragma unroll
        for (int h = 0; h < 2; h++) {
            int r = wt * 16 + g + h * 8;
            float den = denn[h];
            float v0 = den * (rv0 + acc2[nt][h * 2 + 0]) + rb0;
            float v1 = den * (rv1 + acc2[nt][h * 2 + 1]) + rb1;
            uint32_t ph, pl;
            splitbf(v0, v1, ph, pl);
            *(uint32_t*)(dsmc2 + r * 144 + o * 2) = ph;
            *(uint32_t*)(dsmc2 + 18432 + r * 144 + o * 2) = pl;
        }
    }
    __syncthreads();

    for (int u = tid; u < 2048; u += 256) {
        int plane = u >> 10;
        int rest = u & 1023;
        int px = rest >> 3, q = rest & 7;
        uint4 val = *(const uint4*)(dsmc2 + plane * 18432 + px * 144 + q * 16);
        __nv_bfloat16* dst = plane ? g_lo : g_hi;
        *(uint4*)&dst[((size_t)(b * NPIX + p0 + px)) * 128 + br * 64 + q * 8] = val;
    }
}

// -------------------- conv: ldmatrix implicit GEMM + smem B-fragment cache --------
// smem: sHi [0,35360) | sLo [35360,70720) | sB [70720,103488)  (32KB per (ky,kx))
// sB layout (uint4 units): [(cc8*2+half)][q(0..3)][lane(0..31)]  -> conflict-free LDS.128
#define STRIP_STRIDE 272
#define STRIP_BYTES (130 * STRIP_STRIDE)
#define CONV_SMEM (2 * STRIP_BYTES + 32768)

__global__ void __launch_bounds__(256, 2) conv_kernel(const float* __restrict__ cbias,
                                                      float* __restrict__ out)
{
    extern __shared__ __align__(16) char dsmc[];
    char* sHi = dsmc;
    char* sLo = dsmc + STRIP_BYTES;
    uint4* sB4 = (uint4*)(dsmc + 2 * STRIP_BYTES);
    float* sOut = (float*)dsmc;
    const uint32_t sHiB = smem_u32(dsmc);

    const int tid = threadIdx.x;
    const int lane = tid & 31, wt = tid >> 5;
    const int x0 = blockIdx.x * 128, y = blockIdx.y, b = blockIdx.z;

    float acc[8][4];
#pragma unroll
    for (int nt = 0; nt < 8; nt++)
#pragma unroll
        for (int j = 0; j < 4; j++) acc[nt][j] = 0.f;

    const int g = lane >> 2, tg = lane & 3;
    const uint32_t aBase = (uint32_t)((wt * 16 + ((lane >> 3) & 1) * 8 + (lane & 7)) * STRIP_STRIDE
                                      + ((lane >> 4) & 1) * 16);
    const uint4* gB = (const uint4*)g_Bfrag;

    for (int ky = 0; ky < 3; ky++) {
        int yy = y + ky - 1;
        bool yok = (yy >= 0 && yy < IMG_H);
        __syncthreads();   // strips (and sB) free to overwrite
        if (yok) {
            size_t rowbase = ((size_t)b * NPIX + (size_t)yy * IMG_W) * 128;
            for (int i = tid; i < 130 * 16; i += 256) {
                int row = i >> 4, ch = i & 15;
                int px = x0 + row - 1;
                uint4 vh = make_uint4(0u, 0u, 0u, 0u);
                uint4 vl = make_uint4(0u, 0u, 0u, 0u);
                if (px >= 0 && px < IMG_W) {
                    size_t gi = rowbase + (size_t)px * 128 + ch * 8;
                    vh = *(const uint4*)&g_hi[gi];
                    vl = *(const uint4*)&g_lo[gi];
                }
                *(uint4*)(sHi + row * STRIP_STRIDE + ch * 16) = vh;
                *(uint4*)(sLo + row * STRIP_STRIDE + ch * 16) = vl;
            }
        }
        if (!yok) continue;   // block-uniform

#pragma unroll 1
        for (int kx = 0; kx < 3; kx++) {
            __syncthreads();   // prior sB reads done; (kx==0) also fences strip writes
            {
                int gbase = (ky * 24 + kx * 8) * 2 * 128;
                for (int i = tid; i < 2048; i += 256) {
                    int q = i & 3, ln = (i >> 2) & 31, ch = i >> 7;
                    sB4[(ch * 4 + q) * 32 + ln] = __ldg(&gB[gbase + i]);
                }
            }
            __syncthreads();
#pragma unroll
            for (int cc8 = 0; cc8 < 8; cc8++) {
                uint4 bh[4], bl[4];
#pragma unroll
                for (int q = 0; q < 4; q++) {
                    bh[q] = sB4[((cc8 * 2 + 0) * 4 + q) * 32 + lane];
                    bl[q] = sB4[((cc8 * 2 + 1) * 4 + q) * 32 + lane];
                }
                uint32_t ad = sHiB + aBase + kx * STRIP_STRIDE + cc8 * 32;
                uint32_t ah0, ah1, ah2, ah3, al0, al1, al2, al3;
                ldsm_x4(ah0, ah1, ah2, ah3, ad);
                ldsm_x4(al0, al1, al2, al3, ad + STRIP_BYTES);

#pragma unroll
                for (int nt = 0; nt < 8; nt++) {
                    uint32_t bh0 = (nt & 1) ? bh[nt >> 1].z : bh[nt >> 1].x;
                    uint32_t bh1 = (nt & 1) ? bh[nt >> 1].w : bh[nt >> 1].y;
                    uint32_t bl0 = (nt & 1) ? bl[nt >> 1].z : bl[nt >> 1].x;
                    uint32_t bl1 = (nt & 1) ? bl[nt >> 1].w : bl[nt >> 1].y;
                    mma_bf16(acc[nt], ah0, ah1, ah2, ah3, bh0, bh1);
                    mma_bf16(acc[nt], ah0, ah1, ah2, ah3, bl0, bl1);
                    mma_bf16(acc[nt], al0, al1, al2, al3, bh0, bh1);
                }
            }
        }
    }

    __syncthreads();
#pragma unroll
    for (int nt = 0; nt < 8; nt++)
#pragma unroll
        for (int h = 0; h < 2; h++)
#pragma unroll
            for (int j = 0; j < 2; j++) {
                int o = nt * 8 + tg * 2 + j;
                int px = wt * 16 + g + h * 8;
                sOut[o * 132 + px] = acc[nt][h * 2 + j];
            }
    __syncthreads();
    for (int i = tid; i < 64 * 32; i += 256) {
        int o = i >> 5, ch = i & 31;
        float4 v = *(const float4*)&sOut[o * 132 + ch * 4];
        float bias = __ldg(&cbias[o]);
        v.x += bias; v.y += bias; v.z += bias; v.w += bias;
        *(float4*)&out[((size_t)(b * 64 + o)) * NPIX + (size_t)y * IMG_W + x0 + ch * 4] = v;
    }
}

// -------------------- launch --------------------
extern "C" void kernel_launch(void* const* d_in, const int* in_sizes, int n_in,
                              void* d_out, int out_size)
{
    (void)in_sizes; (void)n_in; (void)out_size;
    const float* t1  = (const float*)d_in[0];
    const float* t2  = (const float*)d_in[1];
    const float* q1w = (const float*)d_in[2];  const float* q1b = (const float*)d_in[3];
    const float* k1w = (const float*)d_in[4];  const float* k1b = (const float*)d_in[5];
    const float* v1w = (const float*)d_in[6];  const float* v1b = (const float*)d_in[7];
    const float* r1w = (const float*)d_in[8];  const float* r1b = (const float*)d_in[9];
    const float* q2w = (const float*)d_in[10]; const float* q2b = (const float*)d_in[11];
    const float* k2w = (const float*)d_in[12]; const float* k2b = (const float*)d_in[13];
    const float* v2w = (const float*)d_in[14]; const float* v2b = (const float*)d_in[15];
    const float* r2w = (const float*)d_in[16]; const float* r2b = (const float*)d_in[17];
    const float* cw  = (const float*)d_in[18]; const float* cb  = (const float*)d_in[19];

    cudaFuncSetAttribute(pass1_kernel, cudaFuncAttributeMaxDynamicSharedMemorySize, P1_SMEM);
    cudaFuncSetAttribute(pass2_kernel, cudaFuncAttributeMaxDynamicSharedMemorySize, P2_SMEM);
    cudaFuncSetAttribute(conv_kernel, cudaFuncAttributeMaxDynamicSharedMemorySize, CONV_SMEM);

    prep_zero_kernel<<<256, 256>>>();                                 // launch 0
    prep_conv_kernel<<<288, 256>>>(cw);                               // launch 1
    prep_qkv_kernel<<<96, 256>>>(q1w, k1w, v1w, q2w, k2w, v2w);       // launch 2
    dim3 g1(512, 8, 2);
    pass1_kernel<<<g1, 256, P1_SMEM>>>(t1, t2, k1b, v1b, k2b, v2b);   // launch 3 (ncu)
    dim3 gm(8, 2);
    mid_kernel<<<gm, 256>>>(r1w, r2w);                                // launch 4
    pass2_kernel<<<g1, 256, P2_SMEM>>>(t1, t2, q1b, r1b, q2b, r2b);   // launch 5
    dim3 gc(2, 256, 8);
    conv_kernel<<<gc, 256, CONV_SMEM>>>(cb, (float*)d_out);           // launch 6
}

// round 16
// speedup vs baseline: 1.5791x; 1.1581x over previous
#include <cuda_runtime.h>
#include <cuda_bf16.h>
#include <cstdint>

#define NPIX 65536
#define IMG_H 256
#define IMG_W 256
#define NB 8

// ---- device scratch ----
__device__ __nv_bfloat16 g_hi[NB * NPIX * 128];   // NHWC [b][y][x][ci], hi plane
__device__ __nv_bfloat16 g_lo[NB * NPIX * 128];   // lo plane
__device__ uint32_t g_Bfrag[3 * 24 * 2 * 32 * 16];  // conv weight mma frags
__device__ uint32_t g_QKVfrag[3 * 2 * 2 * 4 * 32 * 16]; // [kind q/k/v][br][half][kc][lane][ntj]
__device__ uint32_t g_RMfrag[16 * 2 * 4 * 32 * 16]; // [(br*8+b)][half][kc][lane][ntj]
__device__ float g_mat[2 * NB * 64 * 64];
__device__ float g_ksum[2 * NB * 64];
__device__ float g_vsum[2 * NB * 64];
__device__ float g_rv[2 * NB * 64];
__device__ float g_ksumE[2 * NB * 64];

// ---- mma.sync bf16 helper (m16n8k16, f32 accum) ----
__device__ __forceinline__ void mma_bf16(float* d,
                                         uint32_t a0, uint32_t a1, uint32_t a2, uint32_t a3,
                                         uint32_t b0, uint32_t b1) {
    asm volatile(
        "mma.sync.aligned.m16n8k16.row.col.f32.bf16.bf16.f32 "
        "{%0,%1,%2,%3}, {%4,%5,%6,%7}, {%8,%9}, {%0,%1,%2,%3};"
        : "+f"(d[0]), "+f"(d[1]), "+f"(d[2]), "+f"(d[3])
        : "r"(a0), "r"(a1), "r"(a2), "r"(a3), "r"(b0), "r"(b1));
}

__device__ __forceinline__ void ldsm_x4(uint32_t& r0, uint32_t& r1, uint32_t& r2, uint32_t& r3,
                                        uint32_t addr) {
    asm volatile("ldmatrix.sync.aligned.m8n8.x4.shared.b16 {%0,%1,%2,%3}, [%4];"
                 : "=r"(r0), "=r"(r1), "=r"(r2), "=r"(r3) : "r"(addr));
}
__device__ __forceinline__ void ldsm_x4_trans(uint32_t& r0, uint32_t& r1, uint32_t& r2, uint32_t& r3,
                                              uint32_t addr) {
    asm volatile("ldmatrix.sync.aligned.m8n8.x4.trans.shared.b16 {%0,%1,%2,%3}, [%4];"
                 : "=r"(r0), "=r"(r1), "=r"(r2), "=r"(r3) : "r"(addr));
}

__device__ __forceinline__ uint32_t smem_u32(const void* p) {
    uint32_t a;
    asm("{ .reg .u64 t; cvta.to.shared.u64 t, %1; cvt.u32.u64 %0, t; }" : "=r"(a) : "l"(p));
    return a;
}

__device__ __forceinline__ void splitbf(float a, float b, uint32_t& h, uint32_t& l) {
    __nv_bfloat16 ha = __float2bfloat16(a), hb = __float2bfloat16(b);
    __nv_bfloat162 hh; hh.x = ha; hh.y = hb;
    h = *(uint32_t*)&hh;
    __nv_bfloat162 ll = __floats2bfloat162_rn(a - __bfloat162float(ha),
                                              b - __bfloat162float(hb));
    l = *(uint32_t*)&ll;
}
__device__ __forceinline__ uint32_t packbf_hi_lo(float a, float b, int half) {
    if (half == 0) {
        __nv_bfloat162 hh; hh.x = __float2bfloat16(a); hh.y = __float2bfloat16(b);
        return *(uint32_t*)&hh;
    }
    __nv_bfloat16 ha = __float2bfloat16(a), hb = __float2bfloat16(b);
    __nv_bfloat162 ll = __floats2bfloat162_rn(a - __bfloat162float(ha),
                                              b - __bfloat162float(hb));
    return *(uint32_t*)&ll;
}

// stage 1024 uint4 of weight frags into permuted smem cache:
// dst[((kc*2+half)*4 + q)*32 + ln] = src[(half*4+kc)*128 + ln*4 + q]
__device__ __forceinline__ void stage_wcache(uint4* sW, const uint4* src, int tid) {
    for (int i = tid; i < 1024; i += 256) {
        int q = i & 3, ln = (i >> 2) & 31, hk = i >> 7;   // hk = half*4+kc
        int half = hk >> 2, kc = hk & 3;
        sW[((kc * 2 + half) * 4 + q) * 32 + ln] = __ldg(&src[i]);
    }
}

// -------------------- prep, split into 3 launches (pass1 at capture idx 3) ----
__global__ void __launch_bounds__(256) prep_zero_kernel() {
    int idx = blockIdx.x * 256 + threadIdx.x;   // grid 256 -> 65536
    g_mat[idx] = 0.f;
    if (idx < 2 * NB * 64) { g_ksum[idx] = 0.f; g_vsum[idx] = 0.f; }
}

__global__ void __launch_bounds__(256) prep_conv_kernel(const float* __restrict__ cw) {
    int i = blockIdx.x * 256 + threadIdx.x;     // grid 288 -> 73728
    if (i >= 73728) return;
    int ky = i / 24576;
    int rem = i % 24576;
    int kc = rem / 1024;
    int rem2 = rem % 1024;
    int half = rem2 / 512;
    int rem3 = rem2 % 512;
    int lane = rem3 / 16;
    int r4 = rem3 % 16;
    int nt = r4 >> 1, j = r4 & 1;
    int kx = kc >> 3, cc8 = kc & 7;
    int n = nt * 8 + (lane >> 2);
    int ci0 = cc8 * 16 + (lane & 3) * 2 + j * 8;
    float w0 = cw[((n * 128 + ci0) * 3 + ky) * 3 + kx];
    float w1 = cw[((n * 128 + ci0 + 1) * 3 + ky) * 3 + kx];
    g_Bfrag[i] = packbf_hi_lo(w0, w1, half);
}

__global__ void __launch_bounds__(256) prep_qkv_kernel(
    const float* __restrict__ q1w, const float* __restrict__ k1w, const float* __restrict__ v1w,
    const float* __restrict__ q2w, const float* __restrict__ k2w, const float* __restrict__ v2w)
{
    int t = blockIdx.x;                          // grid 96
    int kind = t / 32;                           // 0=q, 1=k, 2=v
    int i = (t % 32) * 256 + threadIdx.x;        // 0..8191
    int br = i >> 12;
    int r = i & 4095;
    int half = r >> 11;
    int kc = (r >> 9) & 3;
    int lane = (r >> 4) & 31;
    int ntj = r & 15;
    int nt = ntj >> 1, j = ntj & 1;
    int o = nt * 8 + (lane >> 2);
    int c0 = kc * 16 + (lane & 3) * 2 + j * 8;
    const float* w;
    if (kind == 0) w = br ? q2w : q1w;
    else if (kind == 1) w = br ? k2w : k1w;
    else w = br ? v2w : v1w;
    float w0 = w[o * 64 + c0];
    float w1 = w[o * 64 + c0 + 1];
    g_QKVfrag[kind * 8192 + i] = packbf_hi_lo(w0, w1, half);
}

// -------------------- pass 1: ldmatrix K,V proj + mma stats + smem W-cache -------
// grid (512, 8, 2), 256 thr = 8 warps, 2 CTAs/SM. Tile: 128 px.
// smem: sXh [0,17408) | sXl [17408,34816) | Kp fp32 [34816,68608) | Vp [68608,102400)
// W-cache (16KB) lives at start of Vp region during projections.
#define P1_SMEM 102400

__global__ void __launch_bounds__(256, 2) pass1_kernel(
    const float* __restrict__ x1, const float* __restrict__ x2,
    const float* __restrict__ kb1, const float* __restrict__ vb1,
    const float* __restrict__ kb2, const float* __restrict__ vb2)
{
    extern __shared__ __align__(16) char dsm1c[];
    float* Kp = (float*)(dsm1c + 34816);
    float* Vp = (float*)(dsm1c + 68608);
    uint4* sW = (uint4*)(dsm1c + 68608);   // 16KB cache, overlaps Vp start
    const uint32_t sbase = smem_u32(dsm1c);

    const int tid = threadIdx.x;
    const int lane = tid & 31, wt = tid >> 5;
    const int g = lane >> 2, tg = lane & 3;
    const int b = blockIdx.y, br = blockIdx.z;
    const int p0 = blockIdx.x * 128;
    const float* xb = (br ? x2 : x1) + (size_t)b * 64 * NPIX;
    const float* kb = br ? kb2 : kb1;
    const float* vb = br ? vb2 : vb1;

    // stage X as pre-split bf16 planes [c][px], stride 272B
    for (int i = tid; i < 2048; i += 256) {
        int c = i >> 5, chunk = i & 31;
        float4 xv = *(const float4*)&xb[(size_t)c * NPIX + p0 + chunk * 4];
        uint32_t h0, l0, h1, l1;
        splitbf(xv.x, xv.y, h0, l0);
        splitbf(xv.z, xv.w, h1, l1);
        *(uint2*)(dsm1c + c * 272 + chunk * 8) = make_uint2(h0, h1);
        *(uint2*)(dsm1c + 17408 + c * 272 + chunk * 8) = make_uint2(l0, l1);
    }

    const uint32_t aH = sbase + ((((lane >> 4) & 1) * 8 + (lane & 7)) * 272)
                              + ((wt * 16 + ((lane >> 3) & 1) * 8) * 2);
    const uint32_t aL = aH + 17408;

    // ---- projections: kv=0 -> K (normalized at park), kv=1 -> V ----
#pragma unroll 1
    for (int kv = 0; kv < 2; kv++) {
        const float* bias = kv ? vb : kb;
        float* park = kv ? Vp : Kp;

        __syncthreads();   // prior readers of cache region done (kv=0: X staging fence)
        stage_wcache(sW, (const uint4*)(g_QKVfrag + (kv + 1) * 8192 + br * 4096), tid);
        __syncthreads();

        float acc[8][4];
#pragma unroll
        for (int nt = 0; nt < 8; nt++)
#pragma unroll
            for (int k = 0; k < 4; k++) acc[nt][k] = 0.f;

#pragma unroll
        for (int kc = 0; kc < 4; kc++) {
            uint4 bh[4], bl[4];
#pragma unroll
            for (int q = 0; q < 4; q++) {
                bh[q] = sW[((kc * 2 + 0) * 4 + q) * 32 + lane];
                bl[q] = sW[((kc * 2 + 1) * 4 + q) * 32 + lane];
            }
            uint32_t ah0, ah1, ah2, ah3, al0, al1, al2, al3;
            ldsm_x4_trans(ah0, ah1, ah2, ah3, aH + kc * 4352);
            ldsm_x4_trans(al0, al1, al2, al3, aL + kc * 4352);
#pragma unroll
            for (int nt = 0; nt < 8; nt++) {
                uint32_t b0h = (nt & 1) ? bh[nt >> 1].z : bh[nt >> 1].x;
                uint32_t b1h = (nt & 1) ? bh[nt >> 1].w : bh[nt >> 1].y;
                uint32_t b0l = (nt & 1) ? bl[nt >> 1].z : bl[nt >> 1].x;
                uint32_t b1l = (nt & 1) ? bl[nt >> 1].w : bl[nt >> 1].y;
                mma_bf16(acc[nt], ah0, ah1, ah2, ah3, b0h, b1h);
                mma_bf16(acc[nt], ah0, ah1, ah2, ah3, b0l, b1l);
                mma_bf16(acc[nt], al0, al1, al2, al3, b0h, b1h);
            }
        }

        // add bias
#pragma unroll
        for (int nt = 0; nt < 8; nt++) {
            float b0 = __ldg(&bias[nt * 8 + tg * 2 + 0]);
            float b1 = __ldg(&bias[nt * 8 + tg * 2 + 1]);
            acc[nt][0] += b0; acc[nt][1] += b1;
            acc[nt][2] += b0; acc[nt][3] += b1;
        }

        __syncthreads();   // all warps done reading cache before park may overwrite it

        if (kv == 0) {
#pragma unroll
            for (int h = 0; h < 2; h++) {
                float s = 0.f;
#pragma unroll
                for (int nt = 0; nt < 8; nt++) {
                    float a = acc[nt][h * 2], c = acc[nt][h * 2 + 1];
                    s = fmaf(a, a, s); s = fmaf(c, c, s);
                }
                s += __shfl_xor_sync(0xffffffffu, s, 1);
                s += __shfl_xor_sync(0xffffffffu, s, 2);
                float inv = rsqrtf(s);
                int px = wt * 16 + g + h * 8;
#pragma unroll
                for (int nt = 0; nt < 8; nt++)
#pragma unroll
                    for (int j = 0; j < 2; j++)
                        park[(nt * 8 + tg * 2 + j) * 132 + px] = acc[nt][h * 2 + j] * inv;
            }
        } else {
#pragma unroll
            for (int h = 0; h < 2; h++) {
                int px = wt * 16 + g + h * 8;
#pragma unroll
                for (int nt = 0; nt < 8; nt++)
#pragma unroll
                    for (int j = 0; j < 2; j++)
                        park[(nt * 8 + tg * 2 + j) * 132 + px] = acc[nt][h * 2 + j];
            }
        }
    }
    __syncthreads();

    // ---- stats GEMM: matrix += Kn * V^T  (M=64 kch, N=64 vch, K=128 px) ----
    const int mt4 = wt >> 1;
    const int nh = wt & 1;
    float acc2[4][4];
#pragma unroll
    for (int nt = 0; nt < 4; nt++)
#pragma unroll
        for (int k = 0; k < 4; k++) acc2[nt][k] = 0.f;
    float ksg = 0.f, ksg8 = 0.f;
    float vs[4] = {0.f, 0.f, 0.f, 0.f};

#pragma unroll 4
    for (int kc = 0; kc < 8; kc++) {
        int px0 = kc * 16 + tg * 2;
        int m0 = mt4 * 16 + g;
        float2 k0 = *(const float2*)&Kp[m0 * 132 + px0];
        float2 k8 = *(const float2*)&Kp[m0 * 132 + px0 + 8];
        float2 k10 = *(const float2*)&Kp[(m0 + 8) * 132 + px0];
        float2 k18 = *(const float2*)&Kp[(m0 + 8) * 132 + px0 + 8];
        uint32_t a0h, a0l, a1h, a1l, a2h, a2l, a3h, a3l;
        splitbf(k0.x, k0.y, a0h, a0l);
        splitbf(k10.x, k10.y, a1h, a1l);
        splitbf(k8.x, k8.y, a2h, a2l);
        splitbf(k18.x, k18.y, a3h, a3l);
        if (nh == 0) {
            ksg += k0.x + k0.y + k8.x + k8.y;
            ksg8 += k10.x + k10.y + k18.x + k18.y;
        }
#pragma unroll
        for (int nt = 0; nt < 4; nt++) {
            int n = (nh * 4 + nt) * 8 + g;
            float2 b0 = *(const float2*)&Vp[n * 132 + px0];
            float2 b8 = *(const float2*)&Vp[n * 132 + px0 + 8];
            if (mt4 == 0) vs[nt] += b0.x + b0.y + b8.x + b8.y;
            uint32_t bh0, bl0, bh1, bl1;
            splitbf(b0.x, b0.y, bh0, bl0);
            splitbf(b8.x, b8.y, bh1, bl1);
            mma_bf16(acc2[nt], a0h, a1h, a2h, a3h, bh0, bh1);
            mma_bf16(acc2[nt], a0h, a1h, a2h, a3h, bl0, bl1);
            mma_bf16(acc2[nt], a0l, a1l, a2l, a3l, bh0, bh1);
        }
    }

    float* mat = g_mat + ((size_t)br * NB + b) * 4096;
#pragma unroll
    for (int nt = 0; nt < 4; nt++) {
#pragma unroll
        for (int k = 0; k < 4; k++) {
            int m = mt4 * 16 + g + ((k >= 2) ? 8 : 0);
            int n = (nh * 4 + nt) * 8 + tg * 2 + (k & 1);
            atomicAdd(&mat[m * 64 + n], acc2[nt][k]);
        }
    }
    if (nh == 0) {
        ksg += __shfl_xor_sync(0xffffffffu, ksg, 1);
        ksg += __shfl_xor_sync(0xffffffffu, ksg, 2);
        ksg8 += __shfl_xor_sync(0xffffffffu, ksg8, 1);
        ksg8 += __shfl_xor_sync(0xffffffffu, ksg8, 2);
        if (tg == 0) {
            float* kp = g_ksum + ((size_t)br * NB + b) * 64;
            atomicAdd(&kp[mt4 * 16 + g], ksg);
            atomicAdd(&kp[mt4 * 16 + g + 8], ksg8);
        }
    }
    if (mt4 == 0) {
#pragma unroll
        for (int nt = 0; nt < 4; nt++) {
            float v = vs[nt];
            v += __shfl_xor_sync(0xffffffffu, v, 1);
            v += __shfl_xor_sync(0xffffffffu, v, 2);
            if (tg == 0)
                atomicAdd(&g_vsum[((size_t)br * NB + b) * 64 + (nh * 4 + nt) * 8 + g], v);
        }
    }
}

// -------------------- mid: RM frags, rv, ksumE --------------------
__global__ void __launch_bounds__(256) mid_kernel(const float* __restrict__ rw1,
                                                  const float* __restrict__ rw2)
{
    __shared__ float sMat[4096];
    __shared__ float sRw[4096];
    const int tid = threadIdx.x;
    const int b = blockIdx.x, br = blockIdx.y;
    const float* rw = br ? rw2 : rw1;
    const float* mat = g_mat + ((size_t)br * NB + b) * 4096;
#pragma unroll
    for (int r = 0; r < 16; r++) {
        int i = tid + r * 256;
        sMat[i] = mat[i];
        sRw[i] = rw[i];
    }
    __syncthreads();
    const int ty = tid >> 4, tx = tid & 15;
    float acc[4][4];
#pragma unroll
    for (int i = 0; i < 4; i++)
#pragma unroll
        for (int j = 0; j < 4; j++) acc[i][j] = 0.f;
#pragma unroll 4
    for (int c = 0; c < 64; c++) {
        float a[4], w[4];
#pragma unroll
        for (int i = 0; i < 4; i++) a[i] = sMat[(ty * 4 + i) * 64 + c];
#pragma unroll
        for (int j = 0; j < 4; j++) w[j] = sRw[(tx * 4 + j) * 64 + c];
#pragma unroll
        for (int i = 0; i < 4; i++)
#pragma unroll
            for (int j = 0; j < 4; j++) acc[i][j] += a[i] * w[j];
    }
    if (tid < 64) {
        const float* vsump = g_vsum + ((size_t)br * NB + b) * 64;
        float s = 0.f;
        for (int c = 0; c < 64; c++) s += sRw[tid * 64 + c] * vsump[c];
        g_rv[((size_t)br * NB + b) * 64 + tid] = s;
        g_ksumE[((size_t)br * NB + b) * 64 + tid] =
            g_ksum[((size_t)br * NB + b) * 64 + tid] + 1e-6f;
    }
    __syncthreads();
#pragma unroll
    for (int i = 0; i < 4; i++)
#pragma unroll
        for (int j = 0; j < 4; j++)
            sMat[(tx * 4 + j) * 64 + (ty * 4 + i)] = acc[i][j];
    __syncthreads();
    uint32_t* dst = g_RMfrag + (size_t)(br * 8 + b) * 4096;
    for (int t = tid; t < 4096; t += 256) {
        int half = t >> 11;
        int lane = (t >> 4) & 31;
        int ntj = t & 15;
        int nt = ntj >> 1, j = ntj & 1;
        int kc = (t >> 9) & 3;
        int o = nt * 8 + (lane >> 2);
        int m0 = kc * 16 + (lane & 3) * 2 + j * 8;
        float w0 = sMat[o * 64 + m0];
        float w1 = sMat[o * 64 + m0 + 1];
        dst[t] = packbf_hi_lo(w0, w1, half);
    }
}

// -------------------- pass 2: ldmatrix Q proj + register RM*Qn + smem W-cache ----
// smem: sXh [0,17408) sXl [17408,34816) | W-cache [34816,51200)
// epilogue planes reuse [0,36864). P2_SMEM = 51200, 2 CTAs/SM.
#define P2_SMEM 51200

__global__ void __launch_bounds__(256, 2) pass2_kernel(
    const float* __restrict__ x1, const float* __restrict__ x2,
    const float* __restrict__ qb1, const float* __restrict__ rb1,
    const float* __restrict__ qb2, const float* __restrict__ rb2)
{
    extern __shared__ __align__(16) char dsmc2[];
    uint4* sW = (uint4*)(dsmc2 + 34816);
    const uint32_t sbase = smem_u32(dsmc2);

    const int tid = threadIdx.x;
    const int lane = tid & 31, wt = tid >> 5;
    const int g = lane >> 2, tg = lane & 3;
    const int b = blockIdx.y, br = blockIdx.z;
    const int p0 = blockIdx.x * 128;
    const float* xb = (br ? x2 : x1) + (size_t)b * 64 * NPIX;
    const float* qb = br ? qb2 : qb1;
    const float* rb = br ? rb2 : rb1;
    const float* ksE = g_ksumE + ((size_t)br * NB + b) * 64;
    const float* rvp = g_rv + ((size_t)br * NB + b) * 64;

    for (int i = tid; i < 2048; i += 256) {
        int c = i >> 5, chunk = i & 31;
        float4 xv = *(const float4*)&xb[(size_t)c * NPIX + p0 + chunk * 4];
        uint32_t h0, l0, h1, l1;
        splitbf(xv.x, xv.y, h0, l0);
        splitbf(xv.z, xv.w, h1, l1);
        *(uint2*)(dsmc2 + c * 272 + chunk * 8) = make_uint2(h0, h1);
        *(uint2*)(dsmc2 + 17408 + c * 272 + chunk * 8) = make_uint2(l0, l1);
    }
    // stage Wq cache (distinct smem region; no sync needed between these writes)
    stage_wcache(sW, (const uint4*)(g_QKVfrag + br * 4096), tid);
    __syncthreads();

    const uint32_t aHa = sbase + ((((lane >> 4) & 1) * 8 + (lane & 7)) * 272)
                               + ((wt * 16 + ((lane >> 3) & 1) * 8) * 2);
    const uint32_t aLa = aHa + 17408;

    // ---- phase A: Q = Wq*x + qb ----
    float acc[8][4];
#pragma unroll
    for (int nt = 0; nt < 8; nt++)
#pragma unroll
        for (int k = 0; k < 4; k++) acc[nt][k] = 0.f;

#pragma unroll
    for (int kc = 0; kc < 4; kc++) {
        uint4 bh[4], bl[4];
#pragma unroll
        for (int q = 0; q < 4; q++) {
            bh[q] = sW[((kc * 2 + 0) * 4 + q) * 32 + lane];
            bl[q] = sW[((kc * 2 + 1) * 4 + q) * 32 + lane];
        }
        uint32_t ah0, ah1, ah2, ah3, al0, al1, al2, al3;
        ldsm_x4_trans(ah0, ah1, ah2, ah3, aHa + kc * 4352);
        ldsm_x4_trans(al0, al1, al2, al3, aLa + kc * 4352);
#pragma unroll
        for (int nt = 0; nt < 8; nt++) {
            uint32_t b0h = (nt & 1) ? bh[nt >> 1].z : bh[nt >> 1].x;
            uint32_t b1h = (nt & 1) ? bh[nt >> 1].w : bh[nt >> 1].y;
            uint32_t b0l = (nt & 1) ? bl[nt >> 1].z : bl[nt >> 1].x;
            uint32_t b1l = (nt & 1) ? bl[nt >> 1].w : bl[nt >> 1].y;
            mma_bf16(acc[nt], ah0, ah1, ah2, ah3, b0h, b1h);
            mma_bf16(acc[nt], ah0, ah1, ah2, ah3, b0l, b1l);
            mma_bf16(acc[nt], al0, al1, al2, al3, b0h, b1h);
        }
    }
    __syncthreads();   // X dead; all warps done with Wq cache

    // stage RM cache into same region
    stage_wcache(sW, (const uint4*)(g_RMfrag + (size_t)(br * 8 + b) * 4096), tid);

    // add qb (register work overlaps staging)
    float kse[16];
#pragma unroll
    for (int nt = 0; nt < 8; nt++) {
        float q0 = __ldg(&qb[nt * 8 + tg * 2 + 0]);
        float q1 = __ldg(&qb[nt * 8 + tg * 2 + 1]);
        kse[nt * 2 + 0] = __ldg(&ksE[nt * 8 + tg * 2 + 0]);
        kse[nt * 2 + 1] = __ldg(&ksE[nt * 8 + tg * 2 + 1]);
        acc[nt][0] += q0; acc[nt][1] += q1;
        acc[nt][2] += q0; acc[nt][3] += q1;
    }

    // per-px inv + den via quad shfl
    float invv[2], denn[2];
#pragma unroll
    for (int h = 0; h < 2; h++) {
        float s = 0.f, d = 0.f;
#pragma unroll
        for (int nt = 0; nt < 8; nt++) {
            float a = acc[nt][h * 2], c = acc[nt][h * 2 + 1];
            s = fmaf(a, a, s); s = fmaf(c, c, s);
            d = fmaf(a, kse[nt * 2], d); d = fmaf(c, kse[nt * 2 + 1], d);
        }
        s += __shfl_xor_sync(0xffffffffu, s, 1);
        s += __shfl_xor_sync(0xffffffffu, s, 2);
        d += __shfl_xor_sync(0xffffffffu, d, 1);
        d += __shfl_xor_sync(0xffffffffu, d, 2);
        float inv = rsqrtf(s);
        invv[h] = inv;
        denn[h] = 1.f / (65536.f + inv * d);
    }
    __syncthreads();   // RM cache ready

    // ---- phase B from registers: out = RM * (Q * inv) ----
    float acc2[8][4];
#pragma unroll
    for (int nt = 0; nt < 8; nt++)
#pragma unroll
        for (int k = 0; k < 4; k++) acc2[nt][k] = 0.f;

#pragma unroll
    for (int kc = 0; kc < 4; kc++) {
        uint4 bh[4], bl[4];
#pragma unroll
        for (int q = 0; q < 4; q++) {
            bh[q] = sW[((kc * 2 + 0) * 4 + q) * 32 + lane];
            bl[q] = sW[((kc * 2 + 1) * 4 + q) * 32 + lane];
        }
        float i0 = invv[0], i1 = invv[1];
        uint32_t ah0, ah1, ah2, ah3, al0, al1, al2, al3;
        splitbf(acc[2 * kc][0] * i0, acc[2 * kc][1] * i0, ah0, al0);
        splitbf(acc[2 * kc][2] * i1, acc[2 * kc][3] * i1, ah1, al1);
        splitbf(acc[2 * kc + 1][0] * i0, acc[2 * kc + 1][1] * i0, ah2, al2);
        splitbf(acc[2 * kc + 1][2] * i1, acc[2 * kc + 1][3] * i1, ah3, al3);
#pragma unroll
        for (int nt = 0; nt < 8; nt++) {
            uint32_t b0h = (nt & 1) ? bh[nt >> 1].z : bh[nt >> 1].x;
            uint32_t b1h = (nt & 1) ? bh[nt >> 1].w : bh[nt >> 1].y;
            uint32_t b0l = (nt & 1) ? bl[nt >> 1].z : bl[nt >> 1].x;
            uint32_t b1l = (nt & 1) ? bl[nt >> 1].w : bl[nt >> 1].y;
            mma_bf16(acc2[nt], ah0, ah1, ah2, ah3, b0h, b1h);
            mma_bf16(acc2[nt], ah0, ah1, ah2, ah3, b0l, b1l);
            mma_bf16(acc2[nt], al0, al1, al2, al3, b0h, b1h);
        }
    }
    __syncthreads();   // all warps done with RM cache before epilogue overwrites [0,36864)

    // epilogue -> bf16 hi/lo planes [px][72 bf16 stride] in smem, packed STS.32
#pragma unroll
    for (int nt = 0; nt < 8; nt++) {
        int o = nt * 8 + tg * 2;
        float rv0 = __ldg(&rvp[o]), rv1 = __ldg(&rvp[o + 1]);
        float rb0 = __ldg(&rb[o]),  rb1 = __ldg(&rb[o + 1]);
#pragma unroll
        for (int h = 0; h < 2; h++) {
            int r = wt * 16 + g + h * 8;
            float den = denn[h];
            float v0 = den * (rv0 + acc2[nt][h * 2 + 0]) + rb0;
            float v1 = den * (rv1 + acc2[nt][h * 2 + 1]) + rb1;
            uint32_t ph, pl;
            splitbf(v0, v1, ph, pl);
            *(uint32_t*)(dsmc2 + r * 144 + o * 2) = ph;
            *(uint32_t*)(dsmc2 + 18432 + r * 144 + o * 2) = pl;
        }
    }
    __syncthreads();

    for (int u = tid; u < 2048; u += 256) {
        int plane = u >> 10;
        int rest = u & 1023;
        int px = rest >> 3, q = rest & 7;
        uint4 val = *(const uint4*)(dsmc2 + plane * 18432 + px * 144 + q * 16);
        __nv_bfloat16* dst = plane ? g_lo : g_hi;
        *(uint4*)&dst[((size_t)(b * NPIX + p0 + px)) * 128 + br * 64 + q * 8] = val;
    }
}

// -------------------- conv: ldmatrix implicit GEMM + smem B-fragment cache --------
#define STRIP_STRIDE 272
#define STRIP_BYTES (130 * STRIP_STRIDE)
#define CONV_SMEM (2 * STRIP_BYTES + 32768)

__global__ void __launch_bounds__(256, 2) conv_kernel(const float* __restrict__ cbias,
                                                      float* __restrict__ out)
{
    extern __shared__ __align__(16) char dsmc[];
    char* sHi = dsmc;
    char* sLo = dsmc + STRIP_BYTES;
    uint4* sB4 = (uint4*)(dsmc + 2 * STRIP_BYTES);
    float* sOut = (float*)dsmc;
    const uint32_t sHiB = smem_u32(dsmc);

    const int tid = threadIdx.x;
    const int lane = tid & 31, wt = tid >> 5;
    const int x0 = blockIdx.x * 128, y = blockIdx.y, b = blockIdx.z;

    float acc[8][4];
#pragma unroll
    for (int nt = 0; nt < 8; nt++)
#pragma unroll
        for (int j = 0; j < 4; j++) acc[nt][j] = 0.f;

    const int g = lane >> 2, tg = lane & 3;
    const uint32_t aBase = (uint32_t)((wt * 16 + ((lane >> 3) & 1) * 8 + (lane & 7)) * STRIP_STRIDE
                                      + ((lane >> 4) & 1) * 16);
    const uint4* gB = (const uint4*)g_Bfrag;

    for (int ky = 0; ky < 3; ky++) {
        int yy = y + ky - 1;
        bool yok = (yy >= 0 && yy < IMG_H);
        __syncthreads();
        if (yok) {
            size_t rowbase = ((size_t)b * NPIX + (size_t)yy * IMG_W) * 128;
            for (int i = tid; i < 130 * 16; i += 256) {
                int row = i >> 4, ch = i & 15;
                int px = x0 + row - 1;
                uint4 vh = make_uint4(0u, 0u, 0u, 0u);
                uint4 vl = make_uint4(0u, 0u, 0u, 0u);
                if (px >= 0 && px < IMG_W) {
                    size_t gi = rowbase + (size_t)px * 128 + ch * 8;
                    vh = *(const uint4*)&g_hi[gi];
                    vl = *(const uint4*)&g_lo[gi];
                }
                *(uint4*)(sHi + row * STRIP_STRIDE + ch * 16) = vh;
                *(uint4*)(sLo + row * STRIP_STRIDE + ch * 16) = vl;
            }
        }
        if (!yok) continue;

#pragma unroll 1
        for (int kx = 0; kx < 3; kx++) {
            __syncthreads();
            {
                int gbase = (ky * 24 + kx * 8) * 2 * 128;
                for (int i = tid; i < 2048; i += 256) {
                    int q = i & 3, ln = (i >> 2) & 31, ch = i >> 7;
                    sB4[(ch * 4 + q) * 32 + ln] = __ldg(&gB[gbase + i]);
                }
            }
            __syncthreads();
#pragma unroll
            for (int cc8 = 0; cc8 < 8; cc8++) {
                uint4 bh[4], bl[4];
#pragma unroll
                for (int q = 0; q < 4; q++) {
                    bh[q] = sB4[((cc8 * 2 + 0) * 4 + q) * 32 + lane];
                    bl[q] = sB4[((cc8 * 2 + 1) * 4 + q) * 32 + lane];
                }
                uint32_t ad = sHiB + aBase + kx * STRIP_STRIDE + cc8 * 32;
                uint32_t ah0, ah1, ah2, ah3, al0, al1, al2, al3;
                ldsm_x4(ah0, ah1, ah2, ah3, ad);
                ldsm_x4(al0, al1, al2, al3, ad + STRIP_BYTES);

#pragma unroll
                for (int nt = 0; nt < 8; nt++) {
                    uint32_t bh0 = (nt & 1) ? bh[nt >> 1].z : bh[nt >> 1].x;
                    uint32_t bh1 = (nt & 1) ? bh[nt >> 1].w : bh[nt >> 1].y;
                    uint32_t bl0 = (nt & 1) ? bl[nt >> 1].z : bl[nt >> 1].x;
                    uint32_t bl1 = (nt & 1) ? bl[nt >> 1].w : bl[nt >> 1].y;
                    mma_bf16(acc[nt], ah0, ah1, ah2, ah3, bh0, bh1);
                    mma_bf16(acc[nt], ah0, ah1, ah2, ah3, bl0, bl1);
                    mma_bf16(acc[nt], al0, al1, al2, al3, bh0, bh1);
                }
            }
        }
    }

    __syncthreads();
#pragma unroll
    for (int nt = 0; nt < 8; nt++)
#pragma unroll
        for (int h = 0; h < 2; h++)
#pragma unroll
            for (int j = 0; j < 2; j++) {
                int o = nt * 8 + tg * 2 + j;
                int px = wt * 16 + g + h * 8;
                sOut[o * 132 + px] = acc[nt][h * 2 + j];
            }
    __syncthreads();
    for (int i = tid; i < 64 * 32; i += 256) {
        int o = i >> 5, ch = i & 31;
        float4 v = *(const float4*)&sOut[o * 132 + ch * 4];
        float bias = __ldg(&cbias[o]);
        v.x += bias; v.y += bias; v.z += bias; v.w += bias;
        *(float4*)&out[((size_t)(b * 64 + o)) * NPIX + (size_t)y * IMG_W + x0 + ch * 4] = v;
    }
}

// -------------------- launch --------------------
extern "C" void kernel_launch(void* const* d_in, const int* in_sizes, int n_in,
                              void* d_out, int out_size)
{
    (void)in_sizes; (void)n_in; (void)out_size;
    const float* t1  = (const float*)d_in[0];
    const float* t2  = (const float*)d_in[1];
    const float* q1w = (const float*)d_in[2];  const float* q1b = (const float*)d_in[3];
    const float* k1w = (const float*)d_in[4];  const float* k1b = (const float*)d_in[5];
    const float* v1w = (const float*)d_in[6];  const float* v1b = (const float*)d_in[7];
    const float* r1w = (const float*)d_in[8];  const float* r1b = (const float*)d_in[9];
    const float* q2w = (const float*)d_in[10]; const float* q2b = (const float*)d_in[11];
    const float* k2w = (const float*)d_in[12]; const float* k2b = (const float*)d_in[13];
    const float* v2w = (const float*)d_in[14]; const float* v2b = (const float*)d_in[15];
    const float* r2w = (const float*)d_in[16]; const float* r2b = (const float*)d_in[17];
    const float* cw  = (const float*)d_in[18]; const float* cb  = (const float*)d_in[19];

    cudaFuncSetAttribute(pass1_kernel, cudaFuncAttributeMaxDynamicSharedMemorySize, P1_SMEM);
    cudaFuncSetAttribute(pass2_kernel, cudaFuncAttributeMaxDynamicSharedMemorySize, P2_SMEM);
    cudaFuncSetAttribute(conv_kernel, cudaFuncAttributeMaxDynamicSharedMemorySize, CONV_SMEM);

    prep_zero_kernel<<<256, 256>>>();                                 // launch 0
    prep_conv_kernel<<<288, 256>>>(cw);                               // launch 1
    prep_qkv_kernel<<<96, 256>>>(q1w, k1w, v1w, q2w, k2w, v2w);       // launch 2
    dim3 g1(512, 8, 2);
    pass1_kernel<<<g1, 256, P1_SMEM>>>(t1, t2, k1b, v1b, k2b, v2b);   // launch 3 (ncu)
    dim3 gm(8, 2);
    mid_kernel<<<gm, 256>>>(r1w, r2w);                                // launch 4
    pass2_kernel<<<g1, 256, P2_SMEM>>>(t1, t2, q1b, r1b, q2b, r2b);   // launch 5
    dim3 gc(2, 256, 8);
    conv_kernel<<<gc, 256, CONV_SMEM>>>(cb, (float*)d_out);           // launch 6
}

// round 17
// speedup vs baseline: 1.5807x; 1.0010x over previous
#include <cuda_runtime.h>
#include <cuda_bf16.h>
#include <cstdint>

#define NPIX 65536
#define IMG_H 256
#define IMG_W 256
#define NB 8

// ---- device scratch ----
__device__ __nv_bfloat16 g_hi[NB * NPIX * 128];   // NHWC [b][y][x][ci], hi plane
__device__ __nv_bfloat16 g_lo[NB * NPIX * 128];   // lo plane
__device__ uint32_t g_Bfrag[3 * 24 * 2 * 32 * 16];  // conv weight mma frags
__device__ uint32_t g_QKVfrag[3 * 2 * 2 * 4 * 32 * 16]; // [kind q/k/v][br][half][kc][lane][ntj]
__device__ uint32_t g_RMfrag[16 * 2 * 4 * 32 * 16]; // [(br*8+b)][half][kc][lane][ntj]
__device__ float g_mat[2 * NB * 64 * 64];
__device__ float g_ksum[2 * NB * 64];
__device__ float g_vsum[2 * NB * 64];
__device__ float g_rv[2 * NB * 64];
__device__ float g_ksumE[2 * NB * 64];

// ---- mma.sync bf16 helper (m16n8k16, f32 accum) ----
__device__ __forceinline__ void mma_bf16(float* d,
                                         uint32_t a0, uint32_t a1, uint32_t a2, uint32_t a3,
                                         uint32_t b0, uint32_t b1) {
    asm volatile(
        "mma.sync.aligned.m16n8k16.row.col.f32.bf16.bf16.f32 "
        "{%0,%1,%2,%3}, {%4,%5,%6,%7}, {%8,%9}, {%0,%1,%2,%3};"
        : "+f"(d[0]), "+f"(d[1]), "+f"(d[2]), "+f"(d[3])
        : "r"(a0), "r"(a1), "r"(a2), "r"(a3), "r"(b0), "r"(b1));
}

__device__ __forceinline__ void ldsm_x4(uint32_t& r0, uint32_t& r1, uint32_t& r2, uint32_t& r3,
                                        uint32_t addr) {
    asm volatile("ldmatrix.sync.aligned.m8n8.x4.shared.b16 {%0,%1,%2,%3}, [%4];"
                 : "=r"(r0), "=r"(r1), "=r"(r2), "=r"(r3) : "r"(addr));
}
__device__ __forceinline__ void ldsm_x4_trans(uint32_t& r0, uint32_t& r1, uint32_t& r2, uint32_t& r3,
                                              uint32_t addr) {
    asm volatile("ldmatrix.sync.aligned.m8n8.x4.trans.shared.b16 {%0,%1,%2,%3}, [%4];"
                 : "=r"(r0), "=r"(r1), "=r"(r2), "=r"(r3) : "r"(addr));
}

__device__ __forceinline__ uint32_t smem_u32(const void* p) {
    uint32_t a;
    asm("{ .reg .u64 t; cvta.to.shared.u64 t, %1; cvt.u32.u64 %0, t; }" : "=r"(a) : "l"(p));
    return a;
}

__device__ __forceinline__ void splitbf(float a, float b, uint32_t& h, uint32_t& l) {
    __nv_bfloat16 ha = __float2bfloat16(a), hb = __float2bfloat16(b);
    __nv_bfloat162 hh; hh.x = ha; hh.y = hb;
    h = *(uint32_t*)&hh;
    __nv_bfloat162 ll = __floats2bfloat162_rn(a - __bfloat162float(ha),
                                              b - __bfloat162float(hb));
    l = *(uint32_t*)&ll;
}
__device__ __forceinline__ uint32_t packbf_hi_lo(float a, float b, int half) {
    if (half == 0) {
        __nv_bfloat162 hh; hh.x = __float2bfloat16(a); hh.y = __float2bfloat16(b);
        return *(uint32_t*)&hh;
    }
    __nv_bfloat16 ha = __float2bfloat16(a), hb = __float2bfloat16(b);
    __nv_bfloat162 ll = __floats2bfloat162_rn(a - __bfloat162float(ha),
                                              b - __bfloat162float(hb));
    return *(uint32_t*)&ll;
}

// stage 1024 uint4 of weight frags into permuted smem cache:
// dst[((kc*2+half)*4 + q)*32 + ln] = src[(half*4+kc)*128 + ln*4 + q]
__device__ __forceinline__ void stage_wcache(uint4* sW, const uint4* src, int tid) {
    for (int i = tid; i < 1024; i += 256) {
        int q = i & 3, ln = (i >> 2) & 31, hk = i >> 7;   // hk = half*4+kc
        int half = hk >> 2, kc = hk & 3;
        sW[((kc * 2 + half) * 4 + q) * 32 + ln] = __ldg(&src[i]);
    }
}

// -------------------- prep, split into 3 launches (pass1 at capture idx 3) ----
__global__ void __launch_bounds__(256) prep_zero_kernel() {
    int idx = blockIdx.x * 256 + threadIdx.x;   // grid 256 -> 65536
    g_mat[idx] = 0.f;
    if (idx < 2 * NB * 64) { g_ksum[idx] = 0.f; g_vsum[idx] = 0.f; }
}

__global__ void __launch_bounds__(256) prep_conv_kernel(const float* __restrict__ cw) {
    int i = blockIdx.x * 256 + threadIdx.x;     // grid 288 -> 73728
    if (i >= 73728) return;
    int ky = i / 24576;
    int rem = i % 24576;
    int kc = rem / 1024;
    int rem2 = rem % 1024;
    int half = rem2 / 512;
    int rem3 = rem2 % 512;
    int lane = rem3 / 16;
    int r4 = rem3 % 16;
    int nt = r4 >> 1, j = r4 & 1;
    int kx = kc >> 3, cc8 = kc & 7;
    int n = nt * 8 + (lane >> 2);
    int ci0 = cc8 * 16 + (lane & 3) * 2 + j * 8;
    float w0 = cw[((n * 128 + ci0) * 3 + ky) * 3 + kx];
    float w1 = cw[((n * 128 + ci0 + 1) * 3 + ky) * 3 + kx];
    g_Bfrag[i] = packbf_hi_lo(w0, w1, half);
}

__global__ void __launch_bounds__(256) prep_qkv_kernel(
    const float* __restrict__ q1w, const float* __restrict__ k1w, const float* __restrict__ v1w,
    const float* __restrict__ q2w, const float* __restrict__ k2w, const float* __restrict__ v2w)
{
    int t = blockIdx.x;                          // grid 96
    int kind = t / 32;                           // 0=q, 1=k, 2=v
    int i = (t % 32) * 256 + threadIdx.x;        // 0..8191
    int br = i >> 12;
    int r = i & 4095;
    int half = r >> 11;
    int kc = (r >> 9) & 3;
    int lane = (r >> 4) & 31;
    int ntj = r & 15;
    int nt = ntj >> 1, j = ntj & 1;
    int o = nt * 8 + (lane >> 2);
    int c0 = kc * 16 + (lane & 3) * 2 + j * 8;
    const float* w;
    if (kind == 0) w = br ? q2w : q1w;
    else if (kind == 1) w = br ? k2w : k1w;
    else w = br ? v2w : v1w;
    float w0 = w[o * 64 + c0];
    float w1 = w[o * 64 + c0 + 1];
    g_QKVfrag[kind * 8192 + i] = packbf_hi_lo(w0, w1, half);
}

// -------------------- pass 1: merged K+V projection + mma stats --------------------
// grid (512, 8, 2), 256 thr = 8 warps, 2 CTAs/SM. Tile: 128 px.
// smem: sXh [0,17408) | sXl [17408,34816) | Kp fp32 [34816,68608) | Vp [68608,102400)
// W caches (2x16KB) live at start of Vp region during projections.
#define P1_SMEM 102400

__global__ void __launch_bounds__(256, 2) pass1_kernel(
    const float* __restrict__ x1, const float* __restrict__ x2,
    const float* __restrict__ kb1, const float* __restrict__ vb1,
    const float* __restrict__ kb2, const float* __restrict__ vb2)
{
    extern __shared__ __align__(16) char dsm1c[];
    float* Kp = (float*)(dsm1c + 34816);
    float* Vp = (float*)(dsm1c + 68608);
    uint4* sWk = (uint4*)(dsm1c + 68608);
    uint4* sWv = (uint4*)(dsm1c + 68608 + 16384);
    const uint32_t sbase = smem_u32(dsm1c);

    const int tid = threadIdx.x;
    const int lane = tid & 31, wt = tid >> 5;
    const int g = lane >> 2, tg = lane & 3;
    const int b = blockIdx.y, br = blockIdx.z;
    const int p0 = blockIdx.x * 128;
    const float* xb = (br ? x2 : x1) + (size_t)b * 64 * NPIX;
    const float* kb = br ? kb2 : kb1;
    const float* vb = br ? vb2 : vb1;

    // stage X as pre-split bf16 planes [c][px], stride 272B
    for (int i = tid; i < 2048; i += 256) {
        int c = i >> 5, chunk = i & 31;
        float4 xv = *(const float4*)&xb[(size_t)c * NPIX + p0 + chunk * 4];
        uint32_t h0, l0, h1, l1;
        splitbf(xv.x, xv.y, h0, l0);
        splitbf(xv.z, xv.w, h1, l1);
        *(uint2*)(dsm1c + c * 272 + chunk * 8) = make_uint2(h0, h1);
        *(uint2*)(dsm1c + 17408 + c * 272 + chunk * 8) = make_uint2(l0, l1);
    }
    // stage both K and V weight caches (distinct smem region)
    stage_wcache(sWk, (const uint4*)(g_QKVfrag + 1 * 8192 + br * 4096), tid);
    stage_wcache(sWv, (const uint4*)(g_QKVfrag + 2 * 8192 + br * 4096), tid);
    __syncthreads();

    const uint32_t aH = sbase + ((((lane >> 4) & 1) * 8 + (lane & 7)) * 272)
                              + ((wt * 16 + ((lane >> 3) & 1) * 8) * 2);
    const uint32_t aL = aH + 17408;

    // ---- merged projections: shared A-fragments, K then V mma per kc ----
    float accK[8][4], accV[8][4];
#pragma unroll
    for (int nt = 0; nt < 8; nt++)
#pragma unroll
        for (int k = 0; k < 4; k++) { accK[nt][k] = 0.f; accV[nt][k] = 0.f; }

#pragma unroll
    for (int kc = 0; kc < 4; kc++) {
        uint32_t ah0, ah1, ah2, ah3, al0, al1, al2, al3;
        ldsm_x4_trans(ah0, ah1, ah2, ah3, aH + kc * 4352);
        ldsm_x4_trans(al0, al1, al2, al3, aL + kc * 4352);
        {
            uint4 bh[4], bl[4];
#pragma unroll
            for (int q = 0; q < 4; q++) {
                bh[q] = sWk[((kc * 2 + 0) * 4 + q) * 32 + lane];
                bl[q] = sWk[((kc * 2 + 1) * 4 + q) * 32 + lane];
            }
#pragma unroll
            for (int nt = 0; nt < 8; nt++) {
                uint32_t b0h = (nt & 1) ? bh[nt >> 1].z : bh[nt >> 1].x;
                uint32_t b1h = (nt & 1) ? bh[nt >> 1].w : bh[nt >> 1].y;
                uint32_t b0l = (nt & 1) ? bl[nt >> 1].z : bl[nt >> 1].x;
                uint32_t b1l = (nt & 1) ? bl[nt >> 1].w : bl[nt >> 1].y;
                mma_bf16(accK[nt], ah0, ah1, ah2, ah3, b0h, b1h);
                mma_bf16(accK[nt], ah0, ah1, ah2, ah3, b0l, b1l);
                mma_bf16(accK[nt], al0, al1, al2, al3, b0h, b1h);
            }
        }
        {
            uint4 bh[4], bl[4];
#pragma unroll
            for (int q = 0; q < 4; q++) {
                bh[q] = sWv[((kc * 2 + 0) * 4 + q) * 32 + lane];
                bl[q] = sWv[((kc * 2 + 1) * 4 + q) * 32 + lane];
            }
#pragma unroll
            for (int nt = 0; nt < 8; nt++) {
                uint32_t b0h = (nt & 1) ? bh[nt >> 1].z : bh[nt >> 1].x;
                uint32_t b1h = (nt & 1) ? bh[nt >> 1].w : bh[nt >> 1].y;
                uint32_t b0l = (nt & 1) ? bl[nt >> 1].z : bl[nt >> 1].x;
                uint32_t b1l = (nt & 1) ? bl[nt >> 1].w : bl[nt >> 1].y;
                mma_bf16(accV[nt], ah0, ah1, ah2, ah3, b0h, b1h);
                mma_bf16(accV[nt], ah0, ah1, ah2, ah3, b0l, b1l);
                mma_bf16(accV[nt], al0, al1, al2, al3, b0h, b1h);
            }
        }
    }

    // bias
#pragma unroll
    for (int nt = 0; nt < 8; nt++) {
        float kb0 = __ldg(&kb[nt * 8 + tg * 2 + 0]);
        float kb1v = __ldg(&kb[nt * 8 + tg * 2 + 1]);
        float vb0 = __ldg(&vb[nt * 8 + tg * 2 + 0]);
        float vb1v = __ldg(&vb[nt * 8 + tg * 2 + 1]);
        accK[nt][0] += kb0; accK[nt][1] += kb1v;
        accK[nt][2] += kb0; accK[nt][3] += kb1v;
        accV[nt][0] += vb0; accV[nt][1] += vb1v;
        accV[nt][2] += vb0; accV[nt][3] += vb1v;
    }

    __syncthreads();   // all warps done reading W caches before V park overwrites

    // norm K via quad shfl; park Kn and V
#pragma unroll
    for (int h = 0; h < 2; h++) {
        float s = 0.f;
#pragma unroll
        for (int nt = 0; nt < 8; nt++) {
            float a = accK[nt][h * 2], c = accK[nt][h * 2 + 1];
            s = fmaf(a, a, s); s = fmaf(c, c, s);
        }
        s += __shfl_xor_sync(0xffffffffu, s, 1);
        s += __shfl_xor_sync(0xffffffffu, s, 2);
        float inv = rsqrtf(s);
        int px = wt * 16 + g + h * 8;
#pragma unroll
        for (int nt = 0; nt < 8; nt++)
#pragma unroll
            for (int j = 0; j < 2; j++) {
                Kp[(nt * 8 + tg * 2 + j) * 132 + px] = accK[nt][h * 2 + j] * inv;
                Vp[(nt * 8 + tg * 2 + j) * 132 + px] = accV[nt][h * 2 + j];
            }
    }
    __syncthreads();

    // ---- stats GEMM: matrix += Kn * V^T  (M=64 kch, N=64 vch, K=128 px) ----
    const int mt4 = wt >> 1;
    const int nh = wt & 1;
    float acc2[4][4];
#pragma unroll
    for (int nt = 0; nt < 4; nt++)
#pragma unroll
        for (int k = 0; k < 4; k++) acc2[nt][k] = 0.f;
    float ksg = 0.f, ksg8 = 0.f;
    float vs[4] = {0.f, 0.f, 0.f, 0.f};

#pragma unroll 4
    for (int kc = 0; kc < 8; kc++) {
        int px0 = kc * 16 + tg * 2;
        int m0 = mt4 * 16 + g;
        float2 k0 = *(const float2*)&Kp[m0 * 132 + px0];
        float2 k8 = *(const float2*)&Kp[m0 * 132 + px0 + 8];
        float2 k10 = *(const float2*)&Kp[(m0 + 8) * 132 + px0];
        float2 k18 = *(const float2*)&Kp[(m0 + 8) * 132 + px0 + 8];
        uint32_t a0h, a0l, a1h, a1l, a2h, a2l, a3h, a3l;
        splitbf(k0.x, k0.y, a0h, a0l);
        splitbf(k10.x, k10.y, a1h, a1l);
        splitbf(k8.x, k8.y, a2h, a2l);
        splitbf(k18.x, k18.y, a3h, a3l);
        if (nh == 0) {
            ksg += k0.x + k0.y + k8.x + k8.y;
            ksg8 += k10.x + k10.y + k18.x + k18.y;
        }
#pragma unroll
        for (int nt = 0; nt < 4; nt++) {
            int n = (nh * 4 + nt) * 8 + g;
            float2 b0 = *(const float2*)&Vp[n * 132 + px0];
            float2 b8 = *(const float2*)&Vp[n * 132 + px0 + 8];
            if (mt4 == 0) vs[nt] += b0.x + b0.y + b8.x + b8.y;
            uint32_t bh0, bl0, bh1, bl1;
            splitbf(b0.x, b0.y, bh0, bl0);
            splitbf(b8.x, b8.y, bh1, bl1);
            mma_bf16(acc2[nt], a0h, a1h, a2h, a3h, bh0, bh1);
            mma_bf16(acc2[nt], a0h, a1h, a2h, a3h, bl0, bl1);
            mma_bf16(acc2[nt], a0l, a1l, a2l, a3l, bh0, bh1);
        }
    }

    float* mat = g_mat + ((size_t)br * NB + b) * 4096;
#pragma unroll
    for (int nt = 0; nt < 4; nt++) {
#pragma unroll
        for (int k = 0; k < 4; k++) {
            int m = mt4 * 16 + g + ((k >= 2) ? 8 : 0);
            int n = (nh * 4 + nt) * 8 + tg * 2 + (k & 1);
            atomicAdd(&mat[m * 64 + n], acc2[nt][k]);
        }
    }
    if (nh == 0) {
        ksg += __shfl_xor_sync(0xffffffffu, ksg, 1);
        ksg += __shfl_xor_sync(0xffffffffu, ksg, 2);
        ksg8 += __shfl_xor_sync(0xffffffffu, ksg8, 1);
        ksg8 += __shfl_xor_sync(0xffffffffu, ksg8, 2);
        if (tg == 0) {
            float* kp = g_ksum + ((size_t)br * NB + b) * 64;
            atomicAdd(&kp[mt4 * 16 + g], ksg);
            atomicAdd(&kp[mt4 * 16 + g + 8], ksg8);
        }
    }
    if (mt4 == 0) {
#pragma unroll
        for (int nt = 0; nt < 4; nt++) {
            float v = vs[nt];
            v += __shfl_xor_sync(0xffffffffu, v, 1);
            v += __shfl_xor_sync(0xffffffffu, v, 2);
            if (tg == 0)
                atomicAdd(&g_vsum[((size_t)br * NB + b) * 64 + (nh * 4 + nt) * 8 + g], v);
        }
    }
}

// -------------------- mid: RM frags, rv, ksumE --------------------
__global__ void __launch_bounds__(256) mid_kernel(const float* __restrict__ rw1,
                                                  const float* __restrict__ rw2)
{
    __shared__ float sMat[4096];
    __shared__ float sRw[4096];
    const int tid = threadIdx.x;
    const int b = blockIdx.x, br = blockIdx.y;
    const float* rw = br ? rw2 : rw1;
    const float* mat = g_mat + ((size_t)br * NB + b) * 4096;
#pragma unroll
    for (int r = 0; r < 16; r++) {
        int i = tid + r * 256;
        sMat[i] = mat[i];
        sRw[i] = rw[i];
    }
    __syncthreads();
    const int ty = tid >> 4, tx = tid & 15;
    float acc[4][4];
#pragma unroll
    for (int i = 0; i < 4; i++)
#pragma unroll
        for (int j = 0; j < 4; j++) acc[i][j] = 0.f;
#pragma unroll 4
    for (int c = 0; c < 64; c++) {
        float a[4], w[4];
#pragma unroll
        for (int i = 0; i < 4; i++) a[i] = sMat[(ty * 4 + i) * 64 + c];
#pragma unroll
        for (int j = 0; j < 4; j++) w[j] = sRw[(tx * 4 + j) * 64 + c];
#pragma unroll
        for (int i = 0; i < 4; i++)
#pragma unroll
            for (int j = 0; j < 4; j++) acc[i][j] += a[i] * w[j];
    }
    if (tid < 64) {
        const float* vsump = g_vsum + ((size_t)br * NB + b) * 64;
        float s = 0.f;
        for (int c = 0; c < 64; c++) s += sRw[tid * 64 + c] * vsump[c];
        g_rv[((size_t)br * NB + b) * 64 + tid] = s;
        g_ksumE[((size_t)br * NB + b) * 64 + tid] =
            g_ksum[((size_t)br * NB + b) * 64 + tid] + 1e-6f;
    }
    __syncthreads();
#pragma unroll
    for (int i = 0; i < 4; i++)
#pragma unroll
        for (int j = 0; j < 4; j++)
            sMat[(tx * 4 + j) * 64 + (ty * 4 + i)] = acc[i][j];
    __syncthreads();
    uint32_t* dst = g_RMfrag + (size_t)(br * 8 + b) * 4096;
    for (int t = tid; t < 4096; t += 256) {
        int half = t >> 11;
        int lane = (t >> 4) & 31;
        int ntj = t & 15;
        int nt = ntj >> 1, j = ntj & 1;
        int kc = (t >> 9) & 3;
        int o = nt * 8 + (lane >> 2);
        int m0 = kc * 16 + (lane & 3) * 2 + j * 8;
        float w0 = sMat[o * 64 + m0];
        float w1 = sMat[o * 64 + m0 + 1];
        dst[t] = packbf_hi_lo(w0, w1, half);
    }
}

// -------------------- pass 2: ldmatrix Q proj + register RM*Qn + smem W-cache ----
#define P2_SMEM 51200

__global__ void __launch_bounds__(256, 2) pass2_kernel(
    const float* __restrict__ x1, const float* __restrict__ x2,
    const float* __restrict__ qb1, const float* __restrict__ rb1,
    const float* __restrict__ qb2, const float* __restrict__ rb2)
{
    extern __shared__ __align__(16) char dsmc2[];
    uint4* sW = (uint4*)(dsmc2 + 34816);
    const uint32_t sbase = smem_u32(dsmc2);

    const int tid = threadIdx.x;
    const int lane = tid & 31, wt = tid >> 5;
    const int g = lane >> 2, tg = lane & 3;
    const int b = blockIdx.y, br = blockIdx.z;
    const int p0 = blockIdx.x * 128;
    const float* xb = (br ? x2 : x1) + (size_t)b * 64 * NPIX;
    const float* qb = br ? qb2 : qb1;
    const float* rb = br ? rb2 : rb1;
    const float* ksE = g_ksumE + ((size_t)br * NB + b) * 64;
    const float* rvp = g_rv + ((size_t)br * NB + b) * 64;

    for (int i = tid; i < 2048; i += 256) {
        int c = i >> 5, chunk = i & 31;
        float4 xv = *(const float4*)&xb[(size_t)c * NPIX + p0 + chunk * 4];
        uint32_t h0, l0, h1, l1;
        splitbf(xv.x, xv.y, h0, l0);
        splitbf(xv.z, xv.w, h1, l1);
        *(uint2*)(dsmc2 + c * 272 + chunk * 8) = make_uint2(h0, h1);
        *(uint2*)(dsmc2 + 17408 + c * 272 + chunk * 8) = make_uint2(l0, l1);
    }
    stage_wcache(sW, (const uint4*)(g_QKVfrag + br * 4096), tid);
    __syncthreads();

    const uint32_t aHa = sbase + ((((lane >> 4) & 1) * 8 + (lane & 7)) * 272)
                               + ((wt * 16 + ((lane >> 3) & 1) * 8) * 2);
    const uint32_t aLa = aHa + 17408;

    // ---- phase A: Q = Wq*x + qb ----
    float acc[8][4];
#pragma unroll
    for (int nt = 0; nt < 8; nt++)
#pragma unroll
        for (int k = 0; k < 4; k++) acc[nt][k] = 0.f;

#pragma unroll
    for (int kc = 0; kc < 4; kc++) {
        uint4 bh[4], bl[4];
#pragma unroll
        for (int q = 0; q < 4; q++) {
            bh[q] = sW[((kc * 2 + 0) * 4 + q) * 32 + lane];
            bl[q] = sW[((kc * 2 + 1) * 4 + q) * 32 + lane];
        }
        uint32_t ah0, ah1, ah2, ah3, al0, al1, al2, al3;
        ldsm_x4_trans(ah0, ah1, ah2, ah3, aHa + kc * 4352);
        ldsm_x4_trans(al0, al1, al2, al3, aLa + kc * 4352);
#pragma unroll
        for (int nt = 0; nt < 8; nt++) {
            uint32_t b0h = (nt & 1) ? bh[nt >> 1].z : bh[nt >> 1].x;
            uint32_t b1h = (nt & 1) ? bh[nt >> 1].w : bh[nt >> 1].y;
            uint32_t b0l = (nt & 1) ? bl[nt >> 1].z : bl[nt >> 1].x;
            uint32_t b1l = (nt & 1) ? bl[nt >> 1].w : bl[nt >> 1].y;
            mma_bf16(acc[nt], ah0, ah1, ah2, ah3, b0h, b1h);
            mma_bf16(acc[nt], ah0, ah1, ah2, ah3, b0l, b1l);
            mma_bf16(acc[nt], al0, al1, al2, al3, b0h, b1h);
        }
    }
    __syncthreads();   // X dead; all warps done with Wq cache

    stage_wcache(sW, (const uint4*)(g_RMfrag + (size_t)(br * 8 + b) * 4096), tid);

    float kse[16];
#pragma unroll
    for (int nt = 0; nt < 8; nt++) {
        float q0 = __ldg(&qb[nt * 8 + tg * 2 + 0]);
        float q1 = __ldg(&qb[nt * 8 + tg * 2 + 1]);
        kse[nt * 2 + 0] = __ldg(&ksE[nt * 8 + tg * 2 + 0]);
        kse[nt * 2 + 1] = __ldg(&ksE[nt * 8 + tg * 2 + 1]);
        acc[nt][0] += q0; acc[nt][1] += q1;
        acc[nt][2] += q0; acc[nt][3] += q1;
    }

    float invv[2], denn[2];
#pragma unroll
    for (int h = 0; h < 2; h++) {
        float s = 0.f, d = 0.f;
#pragma unroll
        for (int nt = 0; nt < 8; nt++) {
            float a = acc[nt][h * 2], c = acc[nt][h * 2 + 1];
            s = fmaf(a, a, s); s = fmaf(c, c, s);
            d = fmaf(a, kse[nt * 2], d); d = fmaf(c, kse[nt * 2 + 1], d);
        }
        s += __shfl_xor_sync(0xffffffffu, s, 1);
        s += __shfl_xor_sync(0xffffffffu, s, 2);
        d += __shfl_xor_sync(0xffffffffu, d, 1);
        d += __shfl_xor_sync(0xffffffffu, d, 2);
        float inv = rsqrtf(s);
        invv[h] = inv;
        denn[h] = 1.f / (65536.f + inv * d);
    }
    __syncthreads();   // RM cache ready

    float acc2[8][4];
#pragma unroll
    for (int nt = 0; nt < 8; nt++)
#pragma unroll
        for (int k = 0; k < 4; k++) acc2[nt][k] = 0.f;

#pragma unroll
    for (int kc = 0; kc < 4; kc++) {
        uint4 bh[4], bl[4];
#pragma unroll
        for (int q = 0; q < 4; q++) {
            bh[q] = sW[((kc * 2 + 0) * 4 + q) * 32 + lane];
            bl[q] = sW[((kc * 2 + 1) * 4 + q) * 32 + lane];
        }
        float i0 = invv[0], i1 = invv[1];
        uint32_t ah0, ah1, ah2, ah3, al0, al1, al2, al3;
        splitbf(acc[2 * kc][0] * i0, acc[2 * kc][1] * i0, ah0, al0);
        splitbf(acc[2 * kc][2] * i1, acc[2 * kc][3] * i1, ah1, al1);
        splitbf(acc[2 * kc + 1][0] * i0, acc[2 * kc + 1][1] * i0, ah2, al2);
        splitbf(acc[2 * kc + 1][2] * i1, acc[2 * kc + 1][3] * i1, ah3, al3);
#pragma unroll
        for (int nt = 0; nt < 8; nt++) {
            uint32_t b0h = (nt & 1) ? bh[nt >> 1].z : bh[nt >> 1].x;
            uint32_t b1h = (nt & 1) ? bh[nt >> 1].w : bh[nt >> 1].y;
            uint32_t b0l = (nt & 1) ? bl[nt >> 1].z : bl[nt >> 1].x;
            uint32_t b1l = (nt & 1) ? bl[nt >> 1].w : bl[nt >> 1].y;
            mma_bf16(acc2[nt], ah0, ah1, ah2, ah3, b0h, b1h);
            mma_bf16(acc2[nt], ah0, ah1, ah2, ah3, b0l, b1l);
            mma_bf16(acc2[nt], al0, al1, al2, al3, b0h, b1h);
        }
    }
    __syncthreads();   // all warps done with RM cache before epilogue overwrites

#pragma unroll
    for (int nt = 0; nt < 8; nt++) {
        int o = nt * 8 + tg * 2;
        float rv0 = __ldg(&rvp[o]), rv1 = __ldg(&rvp[o + 1]);
        float rb0 = __ldg(&rb[o]),  rb1 = __ldg(&rb[o + 1]);
#pragma unroll
        for (int h = 0; h < 2; h++) {
            int r = wt * 16 + g + h * 8;
            float den = denn[h];
            float v0 = den * (rv0 + acc2[nt][h * 2 + 0]) + rb0;
            float v1 = den * (rv1 + acc2[nt][h * 2 + 1]) + rb1;
            uint32_t ph, pl;
            splitbf(v0, v1, ph, pl);
            *(uint32_t*)(dsmc2 + r * 144 + o * 2) = ph;
            *(uint32_t*)(dsmc2 + 18432 + r * 144 + o * 2) = pl;
        }
    }
    __syncthreads();

    for (int u = tid; u < 2048; u += 256) {
        int plane = u >> 10;
        int rest = u & 1023;
        int px = rest >> 3, q = rest & 7;
        uint4 val = *(const uint4*)(dsmc2 + plane * 18432 + px * 144 + q * 16);
        __nv_bfloat16* dst = plane ? g_lo : g_hi;
        *(uint4*)&dst[((size_t)(b * NPIX + p0 + px)) * 128 + br * 64 + q * 8] = val;
    }
}

// -------------------- conv: n-split warps (m32 x n32) + smem B cache --------------
#define STRIP_STRIDE 272
#define STRIP_BYTES (130 * STRIP_STRIDE)
#define CONV_SMEM (2 * STRIP_BYTES + 32768)

__global__ void __launch_bounds__(256, 2) conv_kernel(const float* __restrict__ cbias,
                                                      float* __restrict__ out)
{
    extern __shared__ __align__(16) char dsmc[];
    char* sHi = dsmc;
    char* sLo = dsmc + STRIP_BYTES;
    uint4* sB4 = (uint4*)(dsmc + 2 * STRIP_BYTES);
    float* sOut = (float*)dsmc;
    const uint32_t sHiB = smem_u32(dsmc);

    const int tid = threadIdx.x;
    const int lane = tid & 31, wt = tid >> 5;
    const int x0 = blockIdx.x * 128, y = blockIdx.y, b = blockIdx.z;

    const int mg = wt >> 1, ng = wt & 1;    // 4 px-groups x 2 oc-halves
    float acc[2][4][4];                      // [mt][ntl][k]
#pragma unroll
    for (int mt = 0; mt < 2; mt++)
#pragma unroll
        for (int l = 0; l < 4; l++)
#pragma unroll
            for (int j = 0; j < 4; j++) acc[mt][l][j] = 0.f;

    const int g = lane >> 2, tg = lane & 3;
    const uint32_t aRow = (uint32_t)(((lane >> 3) & 1) * 8 + (lane & 7));
    const uint32_t aCol = (uint32_t)(((lane >> 4) & 1) * 16);
    const uint4* gB = (const uint4*)g_Bfrag;

    for (int ky = 0; ky < 3; ky++) {
        int yy = y + ky - 1;
        bool yok = (yy >= 0 && yy < IMG_H);
        __syncthreads();
        if (yok) {
            size_t rowbase = ((size_t)b * NPIX + (size_t)yy * IMG_W) * 128;
            for (int i = tid; i < 130 * 16; i += 256) {
                int row = i >> 4, ch = i & 15;
                int px = x0 + row - 1;
                uint4 vh = make_uint4(0u, 0u, 0u, 0u);
                uint4 vl = make_uint4(0u, 0u, 0u, 0u);
                if (px >= 0 && px < IMG_W) {
                    size_t gi = rowbase + (size_t)px * 128 + ch * 8;
                    vh = *(const uint4*)&g_hi[gi];
                    vl = *(const uint4*)&g_lo[gi];
                }
                *(uint4*)(sHi + row * STRIP_STRIDE + ch * 16) = vh;
                *(uint4*)(sLo + row * STRIP_STRIDE + ch * 16) = vl;
            }
        }
        if (!yok) continue;

#pragma unroll 1
        for (int kx = 0; kx < 3; kx++) {
            __syncthreads();
            {
                int gbase = (ky * 24 + kx * 8) * 2 * 128;
                for (int i = tid; i < 2048; i += 256) {
                    int q = i & 3, ln = (i >> 2) & 31, ch = i >> 7;
                    sB4[(ch * 4 + q) * 32 + ln] = __ldg(&gB[gbase + i]);
                }
            }
            __syncthreads();
#pragma unroll
            for (int cc8 = 0; cc8 < 8; cc8++) {
                uint4 bh[2], bl[2];
#pragma unroll
                for (int qq = 0; qq < 2; qq++) {
                    bh[qq] = sB4[((cc8 * 2 + 0) * 4 + ng * 2 + qq) * 32 + lane];
                    bl[qq] = sB4[((cc8 * 2 + 1) * 4 + ng * 2 + qq) * 32 + lane];
                }
#pragma unroll
                for (int mt = 0; mt < 2; mt++) {
                    uint32_t ad = sHiB + (mg * 32 + mt * 16 + aRow) * STRIP_STRIDE + aCol
                                 + kx * STRIP_STRIDE + cc8 * 32;
                    uint32_t ah0, ah1, ah2, ah3, al0, al1, al2, al3;
                    ldsm_x4(ah0, ah1, ah2, ah3, ad);
                    ldsm_x4(al0, al1, al2, al3, ad + STRIP_BYTES);
#pragma unroll
                    for (int l = 0; l < 4; l++) {
                        uint32_t bh0 = (l & 1) ? bh[l >> 1].z : bh[l >> 1].x;
                        uint32_t bh1 = (l & 1) ? bh[l >> 1].w : bh[l >> 1].y;
                        uint32_t bl0 = (l & 1) ? bl[l >> 1].z : bl[l >> 1].x;
                        uint32_t bl1 = (l & 1) ? bl[l >> 1].w : bl[l >> 1].y;
                        mma_bf16(acc[mt][l], ah0, ah1, ah2, ah3, bh0, bh1);
                        mma_bf16(acc[mt][l], ah0, ah1, ah2, ah3, bl0, bl1);
                        mma_bf16(acc[mt][l], al0, al1, al2, al3, bh0, bh1);
                    }
                }
            }
        }
    }

    __syncthreads();
#pragma unroll
    for (int mt = 0; mt < 2; mt++)
#pragma unroll
        for (int l = 0; l < 4; l++)
#pragma unroll
            for (int h = 0; h < 2; h++)
#pragma unroll
                for (int j = 0; j < 2; j++) {
                    int o = (ng * 4 + l) * 8 + tg * 2 + j;
                    int px = mg * 32 + mt * 16 + g + h * 8;
                    sOut[o * 132 + px] = acc[mt][l][h * 2 + j];
                }
    __syncthreads();
    for (int i = tid; i < 64 * 32; i += 256) {
        int o = i >> 5, ch = i & 31;
        float4 v = *(const float4*)&sOut[o * 132 + ch * 4];
        float bias = __ldg(&cbias[o]);
        v.x += bias; v.y += bias; v.z += bias; v.w += bias;
        *(float4*)&out[((size_t)(b * 64 + o)) * NPIX + (size_t)y * IMG_W + x0 + ch * 4] = v;
    }
}

// -------------------- launch --------------------
extern "C" void kernel_launch(void* const* d_in, const int* in_sizes, int n_in,
                              void* d_out, int out_size)
{
    (void)in_sizes; (void)n_in; (void)out_size;
    const float* t1  = (const float*)d_in[0];
    const float* t2  = (const float*)d_in[1];
    const float* q1w = (const float*)d_in[2];  const float* q1b = (const float*)d_in[3];
    const float* k1w = (const float*)d_in[4];  const float* k1b = (const float*)d_in[5];
    const float* v1w = (const float*)d_in[6];  const float* v1b = (const float*)d_in[7];
    const float* r1w = (const float*)d_in[8];  const float* r1b = (const float*)d_in[9];
    const float* q2w = (const float*)d_in[10]; const float* q2b = (const float*)d_in[11];
    const float* k2w = (const float*)d_in[12]; const float* k2b = (const float*)d_in[13];
    const float* v2w = (const float*)d_in[14]; const float* v2b = (const float*)d_in[15];
    const float* r2w = (const float*)d_in[16]; const float* r2b = (const float*)d_in[17];
    const float* cw  = (const float*)d_in[18]; const float* cb  = (const float*)d_in[19];

    cudaFuncSetAttribute(pass1_kernel, cudaFuncAttributeMaxDynamicSharedMemorySize, P1_SMEM);
    cudaFuncSetAttribute(pass2_kernel, cudaFuncAttributeMaxDynamicSharedMemorySize, P2_SMEM);
    cudaFuncSetAttribute(conv_kernel, cudaFuncAttributeMaxDynamicSharedMemorySize, CONV_SMEM);

    prep_zero_kernel<<<256, 256>>>();                                 // launch 0
    prep_conv_kernel<<<288, 256>>>(cw);                               // launch 1
    prep_qkv_kernel<<<96, 256>>>(q1w, k1w, v1w, q2w, k2w, v2w);       // launch 2
    dim3 g1(512, 8, 2);
    pass1_kernel<<<g1, 256, P1_SMEM>>>(t1, t2, k1b, v1b, k2b, v2b);   // launch 3 (ncu)
    dim3 gm(8, 2);
    mid_kernel<<<gm, 256>>>(r1w, r2w);                                // launch 4
    pass2_kernel<<<g1, 256, P2_SMEM>>>(t1, t2, q1b, r1b, q2b, r2b);   // launch 5
    dim3 gc(2, 256, 8);
    conv_kernel<<<gc, 256, CONV_SMEM>>>(cb, (float*)d_out);           // launch 6
}